// round 7
// baseline (speedup 1.0000x reference)
#include <cuda_runtime.h>
#include <cuda_bf16.h>
#include <math.h>
#include <stdint.h>

#define NN 50000
#define EE 500000
#define NB_SCAN ((NN + 255) / 256)   // 196

// ---------------- scratch ----------------
__device__ float    g_nf[(size_t)NN * 256];
__device__ float    g_node_out[(size_t)NN * 512];  // [f_ni(128) | f_nj(128) | h_src(256)]
__device__ float    g_efbuf[(size_t)EE * 128];
__device__ float    g_elog[(size_t)EE * 4];
__device__ float    g_bcat[512];
__device__ __nv_bfloat16 g_btn_hi[512 * 256];
__device__ __nv_bfloat16 g_btn_lo[512 * 256];
__device__ __nv_bfloat16 g_bte_hi[128 * 128];
__device__ __nv_bfloat16 g_bte_lo[128 * 128];
// CSR by dst
__device__ int g_deg[NN];
__device__ int g_offs[NN + 1];
__device__ int g_cursor[NN];
__device__ int g_eidx[EE];
__device__ int g_bsum[256];

// ---------------- helpers ----------------
__device__ __forceinline__ uint32_t smem_u32(const void* p) {
    uint32_t a;
    asm("{ .reg .u64 t; cvta.to.shared.u64 t, %1; cvt.u32.u64 %0, t; }" : "=r"(a) : "l"(p));
    return a;
}
__device__ __forceinline__ unsigned lds32(uint32_t a) {
    unsigned v;
    asm volatile("ld.shared.b32 %0, [%1];" : "=r"(v) : "r"(a));
    return v;
}
__device__ __forceinline__ void sts128(uint32_t a, uint4 v) {
    asm volatile("st.shared.v4.b32 [%0], {%1, %2, %3, %4};"
                 :: "r"(a), "r"(v.x), "r"(v.y), "r"(v.z), "r"(v.w) : "memory");
}
#define CP_ASYNC16(dst, src) \
    asm volatile("cp.async.ca.shared.global [%0], [%1], 16;" :: "r"(dst), "l"(src) : "memory")
#define CP_COMMIT() asm volatile("cp.async.commit_group;" ::: "memory")
#define CP_WAIT0()  asm volatile("cp.async.wait_group 0;" ::: "memory")

__device__ __forceinline__ void mma_bf16(float& d0, float& d1, float& d2, float& d3,
                                         unsigned a0, unsigned a1, unsigned a2, unsigned a3,
                                         unsigned b0, unsigned b1) {
    asm volatile(
        "mma.sync.aligned.m16n8k16.row.col.f32.bf16.bf16.f32 "
        "{%0,%1,%2,%3}, {%4,%5,%6,%7}, {%8,%9}, {%0,%1,%2,%3};"
        : "+f"(d0), "+f"(d1), "+f"(d2), "+f"(d3)
        : "r"(a0), "r"(a1), "r"(a2), "r"(a3), "r"(b0), "r"(b1));
}
__device__ __forceinline__ void split2(float a, float b, unsigned& hi, unsigned& lo) {
    __nv_bfloat16 ah = __float2bfloat16_rn(a), bh = __float2bfloat16_rn(b);
    __nv_bfloat16 al = __float2bfloat16_rn(a - __bfloat162float(ah));
    __nv_bfloat16 bl = __float2bfloat16_rn(b - __bfloat162float(bh));
    hi = (unsigned)__bfloat16_as_ushort(ah) | ((unsigned)__bfloat16_as_ushort(bh) << 16);
    lo = (unsigned)__bfloat16_as_ushort(al) | ((unsigned)__bfloat16_as_ushort(bl) << 16);
}
__device__ __forceinline__ float elu_f(float v)   { return v > 0.f ? v : expm1f(v); }
__device__ __forceinline__ float lrelu_f(float v) { return v > 0.f ? v : 0.01f * v; }

// ---------------- node GEMM smem layout (R5) ----------------
#define AHI    0
#define ALO    10240
#define BHI    20480
#define BLO    30720
#define BUFSZ  40960
#define NODE_BIAS 81920
#define NODE_SMEM (81920 + 2048)
// ---------------- edge GEMM smem layout: resident B ----------------
// A bufs: 2 x (hi 10240 + lo 10240) = 40960
#define EA_STRIDE 20480
#define EB_HI  40960     // 32768 (up to 4 chunks x 8192)
#define EB_LO  73728     // 32768
#define ESRC   106496
#define EDST   107008
#define EBIAS  107520
#define EATTN  108032
#define ELSH   108544    // 2048
#define EDGE_SMEM 110592
#define EST    0         // stage 128x132 fp32 = 67584, overlaps tiles post-mainloop

// ---------------- small kernels ----------------
__global__ void k_embed(const int* __restrict__ node_types,
                        const float* __restrict__ embed, float* __restrict__ nf) {
    int i = blockIdx.x * 256 + threadIdx.x;
    if (i < NN * 128) {
        int n = i >> 7, c = i & 127;
        nf[(size_t)n * 128 + c] = embed[node_types[n] * 128 + c];
    }
}

__global__ void k_prep(const float* __restrict__ Wni, const float* __restrict__ Wnj,
                       const float* __restrict__ Wsrc, const float* __restrict__ bsrc,
                       const float* __restrict__ Wfij,
                       float* __restrict__ bcat,
                       __nv_bfloat16* __restrict__ btn_hi, __nv_bfloat16* __restrict__ btn_lo,
                       __nv_bfloat16* __restrict__ bte_hi, __nv_bfloat16* __restrict__ bte_lo,
                       int in_n, int in_e) {
    int i = blockIdx.x * 256 + threadIdx.x;
    int nn = 512 * in_n;
    if (i < nn) {
        int n = i / in_n, k = i - n * in_n;
        float v;
        if (n < 128)      v = Wni[k * 128 + n];
        else if (n < 256) v = Wnj[k * 128 + (n - 128)];
        else              v = Wsrc[k * 256 + (n - 256)];
        __nv_bfloat16 h = __float2bfloat16_rn(v);
        __nv_bfloat16 l = __float2bfloat16_rn(v - __bfloat162float(h));
        btn_hi[(size_t)n * in_n + k] = h;
        btn_lo[(size_t)n * in_n + k] = l;
    } else if (i < nn + 128 * in_e) {
        int j = i - nn;
        int n = j / in_e, k = j - n * in_e;
        float v = Wfij[k * 128 + n];
        __nv_bfloat16 h = __float2bfloat16_rn(v);
        __nv_bfloat16 l = __float2bfloat16_rn(v - __bfloat162float(h));
        bte_hi[(size_t)n * in_e + k] = h;
        bte_lo[(size_t)n * in_e + k] = l;
    }
    if (i < 512) bcat[i] = (i < 256) ? 0.f : bsrc[i - 256];
}

// ---------------- CSR build ----------------
__global__ void k_zero_deg(int* __restrict__ deg) {
    int i = blockIdx.x * 256 + threadIdx.x;
    if (i < NN) deg[i] = 0;
}
__global__ void k_hist(const int* __restrict__ dst, int* __restrict__ deg) {
    int e = blockIdx.x * 256 + threadIdx.x;
    if (e < EE) atomicAdd(&deg[dst[e]], 1);
}
__global__ void k_scanA(const int* __restrict__ deg, int* __restrict__ bsum) {
    __shared__ int sh[256];
    int i = blockIdx.x * 256 + threadIdx.x;
    sh[threadIdx.x] = (i < NN) ? deg[i] : 0;
    __syncthreads();
    for (int o = 128; o > 0; o >>= 1) {
        if (threadIdx.x < o) sh[threadIdx.x] += sh[threadIdx.x + o];
        __syncthreads();
    }
    if (threadIdx.x == 0) bsum[blockIdx.x] = sh[0];
}
__global__ void k_scanB(int* __restrict__ bsum) {
    __shared__ int sh[256];
    int t = threadIdx.x;
    int v = (t < NB_SCAN) ? bsum[t] : 0;
    sh[t] = v;
    __syncthreads();
    for (int o = 1; o < 256; o <<= 1) {
        int add = (t >= o) ? sh[t - o] : 0;
        __syncthreads();
        sh[t] += add;
        __syncthreads();
    }
    if (t < NB_SCAN) bsum[t] = sh[t] - v;
}
__global__ void k_scanC(const int* __restrict__ deg, const int* __restrict__ bsum,
                        int* __restrict__ offs, int* __restrict__ cursor) {
    __shared__ int sh[256];
    int i = blockIdx.x * 256 + threadIdx.x;
    int t = threadIdx.x;
    int v = (i < NN) ? deg[i] : 0;
    sh[t] = v;
    __syncthreads();
    for (int o = 1; o < 256; o <<= 1) {
        int add = (t >= o) ? sh[t - o] : 0;
        __syncthreads();
        sh[t] += add;
        __syncthreads();
    }
    if (i < NN) {
        int ex = bsum[blockIdx.x] + sh[t] - v;
        offs[i] = ex;
        cursor[i] = ex;
    }
    if (i == 0) offs[NN] = EE;
}
__global__ void k_scatter(const int* __restrict__ dst, int* __restrict__ cursor,
                          int* __restrict__ eidx) {
    int e = blockIdx.x * 256 + threadIdx.x;
    if (e < EE) {
        int pos = atomicAdd(&cursor[dst[e]], 1);
        eidx[pos] = e;
    }
}

// ---------------- node GEMM mainloop (R5, unchanged) ----------------
__device__ __forceinline__ void b_cpasync(uint32_t sb, int buf,
                                          const __nv_bfloat16* __restrict__ Bth,
                                          const __nv_bfloat16* __restrict__ Btl,
                                          int n0, int K, int k0) {
    int tid = threadIdx.x;
#pragma unroll
    for (int i = 0; i < 2; i++) {
        int c = tid + i * 256;
        int n = c >> 2, k16 = c & 3;
        size_t go = (size_t)(n0 + n) * K + k0 + k16 * 8;
        uint32_t da = sb + buf * BUFSZ + BHI + n * 80 + k16 * 16;
        CP_ASYNC16(da, Bth + go);
        CP_ASYNC16(da + (BLO - BHI), Btl + go);
    }
}

__device__ __forceinline__ void a_convert_sts(uint32_t sb, uint32_t abase_off, int r, int hk,
                                              const float4 pa[4]) {
    uint32_t ah = sb + abase_off + r * 80 + hk * 32;
    uint32_t al = ah + 10240;
#pragma unroll
    for (int q = 0; q < 2; q++) {
        unsigned h0, l0, h1, l1, h2, l2, h3, l3;
        split2(pa[2 * q].x,     pa[2 * q].y,     h0, l0);
        split2(pa[2 * q].z,     pa[2 * q].w,     h1, l1);
        split2(pa[2 * q + 1].x, pa[2 * q + 1].y, h2, l2);
        split2(pa[2 * q + 1].z, pa[2 * q + 1].w, h3, l3);
        sts128(ah + q * 16, make_uint4(h0, h1, h2, h3));
        sts128(al + q * 16, make_uint4(l0, l1, l2, l3));
    }
}

__device__ __forceinline__ void load_a_frags(uint32_t abase, unsigned ahr[2][4], unsigned alr[2][4]) {
#pragma unroll
    for (int mt = 0; mt < 2; mt++) {
        uint32_t a0 = abase + mt * (16 * 80);
        ahr[mt][0] = lds32(a0);
        ahr[mt][1] = lds32(a0 + 8 * 80);
        ahr[mt][2] = lds32(a0 + 16);
        ahr[mt][3] = lds32(a0 + 8 * 80 + 16);
        uint32_t a0l = a0 + 10240;
        alr[mt][0] = lds32(a0l);
        alr[mt][1] = lds32(a0l + 8 * 80);
        alr[mt][2] = lds32(a0l + 16);
        alr[mt][3] = lds32(a0l + 8 * 80 + 16);
    }
}

__device__ __forceinline__ void mma_compute_node(uint32_t sb, int buf, float acc[2][8][4]) {
    int tid = threadIdx.x, lane = tid & 31, wid = tid >> 5;
    int g = lane >> 2, tig = lane & 3;
    int wm = wid & 3, wn = wid >> 2;
    uint32_t bo = sb + buf * BUFSZ;
#pragma unroll
    for (int ks = 0; ks < 2; ks++) {
        unsigned ahr[2][4], alr[2][4];
        load_a_frags(bo + AHI + (wm * 32 + g) * 80 + ks * 32 + tig * 4, ahr, alr);
        uint32_t bbase = bo + BHI + (wn * 64 + g) * 80 + ks * 32 + tig * 4;
#pragma unroll
        for (int nt = 0; nt < 8; nt++) {
            uint32_t b0a = bbase + nt * (8 * 80);
            unsigned bh0 = lds32(b0a), bh1 = lds32(b0a + 16);
            unsigned bl0 = lds32(b0a + (BLO - BHI)), bl1 = lds32(b0a + (BLO - BHI) + 16);
#pragma unroll
            for (int mt = 0; mt < 2; mt++) {
                float* d = acc[mt][nt];
                mma_bf16(d[0], d[1], d[2], d[3],
                         ahr[mt][0], ahr[mt][1], ahr[mt][2], ahr[mt][3], bh0, bh1);
                mma_bf16(d[0], d[1], d[2], d[3],
                         ahr[mt][0], ahr[mt][1], ahr[mt][2], ahr[mt][3], bl0, bl1);
                mma_bf16(d[0], d[1], d[2], d[3],
                         alr[mt][0], alr[mt][1], alr[mt][2], alr[mt][3], bh0, bh1);
            }
        }
    }
}

__global__ __launch_bounds__(256, 2) void gemm_node_mma(
    const float* __restrict__ A,
    const __nv_bfloat16* __restrict__ Bth, const __nv_bfloat16* __restrict__ Btl,
    const float* __restrict__ bias, float* __restrict__ Cout, int M, int K) {
    extern __shared__ __align__(16) char smem[];
    uint32_t sb = smem_u32(smem);
    float* bsm = (float*)(smem + NODE_BIAS);
    int tid = threadIdx.x;
    ((float2*)bsm)[tid] = ((const float2*)bias)[tid];

    int row0 = blockIdx.x * 128, n0 = blockIdx.y * 128;
    float acc[2][8][4];
#pragma unroll
    for (int mt = 0; mt < 2; mt++)
#pragma unroll
        for (int nt = 0; nt < 8; nt++)
#pragma unroll
            for (int q = 0; q < 4; q++) acc[mt][nt][q] = 0.f;

    int r = tid >> 1, hk = tid & 1;
    int arow = row0 + r;
    bool aval = arow < M;
    const float* abase = A + (size_t)arow * K + hk * 16;
    int nst = K >> 5;
    float4 pa[4];
    const float4 z4 = make_float4(0.f, 0.f, 0.f, 0.f);
#pragma unroll
    for (int q = 0; q < 4; q++) pa[q] = aval ? *(const float4*)(abase + q * 4) : z4;
    b_cpasync(sb, 0, Bth, Btl, n0, K, 0);
    CP_COMMIT();
    a_convert_sts(sb, 0 * BUFSZ + AHI, r, hk, pa);
    CP_WAIT0();
    __syncthreads();
    for (int s = 0; s < nst; s++) {
        int buf = s & 1;
        bool more = (s + 1) < nst;
        if (more) {
            b_cpasync(sb, buf ^ 1, Bth, Btl, n0, K, (s + 1) * 32);
            CP_COMMIT();
            const float* ap = abase + (s + 1) * 32;
#pragma unroll
            for (int q = 0; q < 4; q++) pa[q] = aval ? *(const float4*)(ap + q * 4) : z4;
        }
        mma_compute_node(sb, buf, acc);
        if (more) {
            a_convert_sts(sb, (buf ^ 1) * BUFSZ + AHI, r, hk, pa);
            CP_WAIT0();
        }
        __syncthreads();
    }

    int lane = tid & 31, wid = tid >> 5;
    int g = lane >> 2, tig = lane & 3;
    int wm = wid & 3, wn = wid >> 2;
#pragma unroll
    for (int mt = 0; mt < 2; mt++) {
        int r0 = row0 + wm * 32 + mt * 16 + g;
#pragma unroll
        for (int nt = 0; nt < 8; nt++) {
            int cc = n0 + wn * 64 + nt * 8 + 2 * tig;
            float b0 = bsm[cc], b1 = bsm[cc + 1];
            float* d = acc[mt][nt];
            if (r0 < M)
                *(float2*)(Cout + (size_t)r0 * 512 + cc) = make_float2(d[0] + b0, d[1] + b1);
            if (r0 + 8 < M)
                *(float2*)(Cout + (size_t)(r0 + 8) * 512 + cc) = make_float2(d[2] + b0, d[3] + b1);
        }
    }
}

// ---------------- edge GEMM: resident-B mainloop + fused epilogue ----------------
__device__ __forceinline__ void mma_compute_edge(uint32_t sb, int abuf, int chunk,
                                                 float acc[2][8][4]) {
    int tid = threadIdx.x, lane = tid & 31, wid = tid >> 5;
    int g = lane >> 2, tig = lane & 3;
    int wm = wid & 3, wn = wid >> 2;
    uint32_t ao = sb + abuf * EA_STRIDE;
    uint32_t sw = (g >> 1) & 3;
    uint32_t bb = sb + EB_HI + chunk * 8192 + (wn * 64 + g) * 64 + tig * 4;
#pragma unroll
    for (int ks = 0; ks < 2; ks++) {
        unsigned ahr[2][4], alr[2][4];
        load_a_frags(ao + (wm * 32 + g) * 80 + ks * 32 + tig * 4, ahr, alr);
        uint32_t o0 = ((unsigned)(ks * 2)     ^ sw) * 16;
        uint32_t o1 = ((unsigned)(ks * 2 + 1) ^ sw) * 16;
#pragma unroll
        for (int nt = 0; nt < 8; nt++) {
            uint32_t ba = bb + nt * 512;
            unsigned bh0 = lds32(ba + o0), bh1 = lds32(ba + o1);
            unsigned bl0 = lds32(ba + o0 + 32768), bl1 = lds32(ba + o1 + 32768);
#pragma unroll
            for (int mt = 0; mt < 2; mt++) {
                float* d = acc[mt][nt];
                mma_bf16(d[0], d[1], d[2], d[3],
                         ahr[mt][0], ahr[mt][1], ahr[mt][2], ahr[mt][3], bh0, bh1);
                mma_bf16(d[0], d[1], d[2], d[3],
                         ahr[mt][0], ahr[mt][1], ahr[mt][2], ahr[mt][3], bl0, bl1);
                mma_bf16(d[0], d[1], d[2], d[3],
                         alr[mt][0], alr[mt][1], alr[mt][2], alr[mt][3], bh0, bh1);
            }
        }
    }
}

__global__ __launch_bounds__(256, 2) void gemm_edge_mma(
    const float* __restrict__ A,
    const __nv_bfloat16* __restrict__ Bth, const __nv_bfloat16* __restrict__ Btl,
    const float* __restrict__ node_out,
    const int* __restrict__ src, const int* __restrict__ dst,
    const float* __restrict__ bias, const float* __restrict__ attn,
    float* __restrict__ ef_out, float* __restrict__ elog, int M, int K) {
    extern __shared__ __align__(16) char smem[];
    uint32_t sb = smem_u32(smem);
    float* stage = (float*)(smem + EST);
    int*   ssh = (int*)(smem + ESRC);
    int*   dsh = (int*)(smem + EDST);
    float* bsh = (float*)(smem + EBIAS);
    float* ash = (float*)(smem + EATTN);
    float* lsh = (float*)(smem + ELSH);

    int tid = threadIdx.x;
    int e0 = blockIdx.x * 128;
    if (tid < 128) {
        int e = e0 + tid;
        ssh[tid] = (e < M) ? src[e] : 0;
        dsh[tid] = (e < M) ? dst[e] : 0;
        bsh[tid] = bias[tid];
        ash[tid] = attn[tid];
    }

    float acc[2][8][4];
#pragma unroll
    for (int mt = 0; mt < 2; mt++)
#pragma unroll
        for (int nt = 0; nt < 8; nt++)
#pragma unroll
            for (int q = 0; q < 4; q++) acc[mt][nt][q] = 0.f;

    int nst = K >> 5;
    // resident B load (all chunks) — swizzled 64B rows
    for (int it = 0; it < nst * 2; it++) {
        int c = tid + it * 256;
        int chunk = c >> 9;
        int rem = c & 511;
        int n = rem >> 2, k16 = rem & 3;
        size_t go = (size_t)n * K + chunk * 32 + k16 * 8;
        uint32_t d = sb + EB_HI + chunk * 8192 + n * 64 +
                     ((unsigned)(k16 ^ ((n >> 1) & 3)) * 16);
        CP_ASYNC16(d, Bth + go);
        CP_ASYNC16(d + 32768, Btl + go);
    }
    CP_COMMIT();

    int r = tid >> 1, hk = tid & 1;
    int arow = e0 + r;
    bool aval = arow < M;
    const float* abase = A + (size_t)arow * K + hk * 16;
    float4 pa[4];
    const float4 z4 = make_float4(0.f, 0.f, 0.f, 0.f);
#pragma unroll
    for (int q = 0; q < 4; q++) pa[q] = aval ? *(const float4*)(abase + q * 4) : z4;
    a_convert_sts(sb, 0 * EA_STRIDE, r, hk, pa);
    CP_WAIT0();
    __syncthreads();

    for (int s = 0; s < nst; s++) {
        int buf = s & 1;
        bool more = (s + 1) < nst;
        if (more) {
            const float* ap = abase + (s + 1) * 32;
#pragma unroll
            for (int q = 0; q < 4; q++) pa[q] = aval ? *(const float4*)(ap + q * 4) : z4;
        }
        mma_compute_edge(sb, buf, s, acc);
        if (more) a_convert_sts(sb, (buf ^ 1) * EA_STRIDE, r, hk, pa);
        __syncthreads();
    }

    int lane = tid & 31, wid = tid >> 5;
    int g = lane >> 2, tig = lane & 3;
    int wm = wid & 3, wn = wid >> 2;
#pragma unroll
    for (int mt = 0; mt < 2; mt++) {
        int rr = wm * 32 + mt * 16 + g;
#pragma unroll
        for (int nt = 0; nt < 8; nt++) {
            int cc = wn * 64 + nt * 8 + 2 * tig;
            float* d = acc[mt][nt];
            *(float2*)&stage[rr * 132 + cc] = make_float2(d[0], d[1]);
            *(float2*)&stage[(rr + 8) * 132 + cc] = make_float2(d[2], d[3]);
        }
    }
    __syncthreads();

    {
        int rr = tid & 127, hc = tid >> 7;
        int e = e0 + rr;
        if (e < M) {
            int si = ssh[rr], dj = dsh[rr];
            const float* pni = node_out + (size_t)si * 512 + hc * 64;
            const float* pnj = node_out + (size_t)dj * 512 + 128 + hc * 64;
            const float* sp = stage + rr * 132 + hc * 64;
            float* op = ef_out + (size_t)e * 128 + hc * 64;
            float part[2] = {0.f, 0.f};
#pragma unroll
            for (int q = 0; q < 16; q++) {
                int c = hc * 64 + q * 4;
                float4 sv = *(const float4*)(sp + q * 4);
                float4 a = *(const float4*)(pni + q * 4);
                float4 b = *(const float4*)(pnj + q * 4);
                float4 o;
                float v;
                v = sv.x + a.x + b.x + bsh[c + 0];
                v = lrelu_f(v); part[q >> 3] += v * ash[c + 0]; o.x = elu_f(v);
                v = sv.y + a.y + b.y + bsh[c + 1];
                v = lrelu_f(v); part[q >> 3] += v * ash[c + 1]; o.y = elu_f(v);
                v = sv.z + a.z + b.z + bsh[c + 2];
                v = lrelu_f(v); part[q >> 3] += v * ash[c + 2]; o.z = elu_f(v);
                v = sv.w + a.w + b.w + bsh[c + 3];
                v = lrelu_f(v); part[q >> 3] += v * ash[c + 3]; o.w = elu_f(v);
                *(float4*)(op + q * 4) = o;
            }
            lsh[rr * 4 + hc * 2 + 0] = part[0];
            lsh[rr * 4 + hc * 2 + 1] = part[1];
        }
    }
    __syncthreads();

    for (int t = tid; t < 512; t += 256) {
        int r2 = t >> 2, h = t & 3;
        int e2 = e0 + r2;
        if (e2 < M) elog[(size_t)e2 * 4 + h] = lsh[r2 * 4 + h];
    }
}

// ---------------- CSR aggregation (2-way unrolled) ----------------
__global__ __launch_bounds__(256) void k_aggr(
    const int* __restrict__ srcs, const int* __restrict__ eidx,
    const int* __restrict__ offs, const float* __restrict__ elog,
    const float* __restrict__ node_out, float* __restrict__ outp) {
    int node = (blockIdx.x * 256 + threadIdx.x) >> 5;
    int lane = threadIdx.x & 31;
    if (node >= NN) return;
    int beg = offs[node], end = offs[node + 1];

    float4 mx = make_float4(-1e30f, -1e30f, -1e30f, -1e30f);
    for (int j = beg + lane; j < end; j += 32) {
        int e = eidx[j];
        float4 l = *(const float4*)(elog + (size_t)e * 4);
        mx.x = fmaxf(mx.x, l.x); mx.y = fmaxf(mx.y, l.y);
        mx.z = fmaxf(mx.z, l.z); mx.w = fmaxf(mx.w, l.w);
    }
#pragma unroll
    for (int o = 16; o > 0; o >>= 1) {
        mx.x = fmaxf(mx.x, __shfl_xor_sync(0xFFFFFFFFu, mx.x, o));
        mx.y = fmaxf(mx.y, __shfl_xor_sync(0xFFFFFFFFu, mx.y, o));
        mx.z = fmaxf(mx.z, __shfl_xor_sync(0xFFFFFFFFu, mx.z, o));
        mx.w = fmaxf(mx.w, __shfl_xor_sync(0xFFFFFFFFu, mx.w, o));
    }
    int h = lane >> 3;
    float mh = (h == 0) ? mx.x : (h == 1) ? mx.y : (h == 2) ? mx.z : mx.w;

    float acc[8] = {0.f, 0.f, 0.f, 0.f, 0.f, 0.f, 0.f, 0.f};
    float ssum = 0.f;
    int j = beg;
    for (; j + 1 < end; j += 2) {
        int ea = eidx[j], eb = eidx[j + 1];
        int sa = srcs[ea], sbn = srcs[eb];
        float la = elog[(size_t)ea * 4 + h], lb = elog[(size_t)eb * 4 + h];
        const float4* pa = (const float4*)(node_out + (size_t)sa * 512 + 256) + lane * 2;
        const float4* pb = (const float4*)(node_out + (size_t)sbn * 512 + 256) + lane * 2;
        float4 a0 = pa[0], a1 = pa[1];
        float4 b0 = pb[0], b1 = pb[1];
        float wa = expf(la - mh), wb = expf(lb - mh);
        ssum += wa + wb;
        acc[0] += wa * a0.x + wb * b0.x; acc[1] += wa * a0.y + wb * b0.y;
        acc[2] += wa * a0.z + wb * b0.z; acc[3] += wa * a0.w + wb * b0.w;
        acc[4] += wa * a1.x + wb * b1.x; acc[5] += wa * a1.y + wb * b1.y;
        acc[6] += wa * a1.z + wb * b1.z; acc[7] += wa * a1.w + wb * b1.w;
    }
    if (j < end) {
        int e = eidx[j];
        float w = expf(elog[(size_t)e * 4 + h] - mh);
        ssum += w;
        const float4* hp = (const float4*)(node_out + (size_t)srcs[e] * 512 + 256) + lane * 2;
        float4 v0 = hp[0], v1 = hp[1];
        acc[0] += w * v0.x; acc[1] += w * v0.y; acc[2] += w * v0.z; acc[3] += w * v0.w;
        acc[4] += w * v1.x; acc[5] += w * v1.y; acc[6] += w * v1.z; acc[7] += w * v1.w;
    }
    float inv = (end > beg) ? 1.f / ssum : 0.f;
    float* op = outp + (size_t)node * 256 + lane * 8;
    float4 o0, o1;
    o0.x = elu_f(acc[0] * inv); o0.y = elu_f(acc[1] * inv);
    o0.z = elu_f(acc[2] * inv); o0.w = elu_f(acc[3] * inv);
    o1.x = elu_f(acc[4] * inv); o1.y = elu_f(acc[5] * inv);
    o1.z = elu_f(acc[6] * inv); o1.w = elu_f(acc[7] * inv);
    *(float4*)op = o0;
    *(float4*)(op + 4) = o1;
}

// ---------------- host ----------------
extern "C" void kernel_launch(void* const* d_in, const int* in_sizes, int n_in,
                              void* d_out, int out_size) {
    const int*   node_types = (const int*)d_in[0];
    const int*   src        = (const int*)d_in[1];
    const int*   dst        = (const int*)d_in[2];
    const float* efeats     = (const float*)d_in[3];
    const float* embed      = (const float*)d_in[4];
    const float* W_src[2] = {(const float*)d_in[5],  (const float*)d_in[12]};
    const float* b_src[2] = {(const float*)d_in[6],  (const float*)d_in[13]};
    const float* W_ni[2]  = {(const float*)d_in[7],  (const float*)d_in[14]};
    const float* W_nj[2]  = {(const float*)d_in[8],  (const float*)d_in[15]};
    const float* W_fij[2] = {(const float*)d_in[9],  (const float*)d_in[16]};
    const float* attn[2]  = {(const float*)d_in[10], (const float*)d_in[17]};
    const float* bias[2]  = {(const float*)d_in[11], (const float*)d_in[18]};

    float *nf, *node_out, *efbuf, *elog, *bcat;
    int *deg, *offs, *cursor, *eidx, *bsum;
    __nv_bfloat16 *btnh, *btnl, *bteh, *btel;
    cudaGetSymbolAddress((void**)&nf, g_nf);
    cudaGetSymbolAddress((void**)&node_out, g_node_out);
    cudaGetSymbolAddress((void**)&efbuf, g_efbuf);
    cudaGetSymbolAddress((void**)&elog, g_elog);
    cudaGetSymbolAddress((void**)&bcat, g_bcat);
    cudaGetSymbolAddress((void**)&btnh, g_btn_hi);
    cudaGetSymbolAddress((void**)&btnl, g_btn_lo);
    cudaGetSymbolAddress((void**)&bteh, g_bte_hi);
    cudaGetSymbolAddress((void**)&btel, g_bte_lo);
    cudaGetSymbolAddress((void**)&deg, g_deg);
    cudaGetSymbolAddress((void**)&offs, g_offs);
    cudaGetSymbolAddress((void**)&cursor, g_cursor);
    cudaGetSymbolAddress((void**)&eidx, g_eidx);
    cudaGetSymbolAddress((void**)&bsum, g_bsum);

    cudaFuncSetAttribute(gemm_node_mma, cudaFuncAttributeMaxDynamicSharedMemorySize, NODE_SMEM);
    cudaFuncSetAttribute(gemm_edge_mma, cudaFuncAttributeMaxDynamicSharedMemorySize, EDGE_SMEM);

    float* out_nf = (float*)d_out;
    float* out_ef = out_nf + (size_t)NN * 256;

    k_embed<<<(NN * 128 + 255) / 256, 256>>>(node_types, embed, nf);

    // CSR by dst (edges identical across layers)
    k_zero_deg<<<NB_SCAN, 256>>>(deg);
    k_hist<<<(EE + 255) / 256, 256>>>(dst, deg);
    k_scanA<<<NB_SCAN, 256>>>(deg, bsum);
    k_scanB<<<1, 256>>>(bsum);
    k_scanC<<<NB_SCAN, 256>>>(deg, bsum, offs, cursor);
    k_scatter<<<(EE + 255) / 256, 256>>>(dst, cursor, eidx);

    const float* ef_in = efeats;
    for (int L = 0; L < 2; L++) {
        int in_n = L ? 256 : 128;
        int in_e = L ? 128 : 64;
        int prep_items = 512 * in_n + 128 * in_e;
        k_prep<<<(prep_items + 255) / 256, 256>>>(W_ni[L], W_nj[L], W_src[L], b_src[L],
                                                  W_fij[L], bcat, btnh, btnl, bteh, btel,
                                                  in_n, in_e);

        dim3 gn((NN + 127) / 128, 4);
        gemm_node_mma<<<gn, 256, NODE_SMEM>>>(nf, btnh, btnl, bcat, node_out, NN, in_n);

        float* ef_out = L ? out_ef : efbuf;
        gemm_edge_mma<<<(EE + 127) / 128, 256, EDGE_SMEM>>>(ef_in, bteh, btel, node_out,
                                                            src, dst, bias[L], attn[L],
                                                            ef_out, elog, EE, in_e);

        float* nf_out = L ? out_nf : nf;
        k_aggr<<<(NN * 32 + 255) / 256, 256>>>(src, eidx, offs, elog, node_out, nf_out);
        ef_in = ef_out;
    }
}

// round 8
// speedup vs baseline: 1.1900x; 1.1900x over previous
#include <cuda_runtime.h>
#include <cuda_bf16.h>
#include <math.h>
#include <stdint.h>

#define NN 50000
#define EE 500000
#define NB_SCAN ((NN + 255) / 256)   // 196

// ---------------- scratch ----------------
__device__ float    g_nf[(size_t)NN * 256];
__device__ float    g_node_out[(size_t)NN * 512];  // [f_ni(128) | f_nj(128) | h_src(256)]
__device__ float    g_efbuf[(size_t)EE * 128];
__device__ float    g_elog[(size_t)EE * 4];        // raw attention logits
__device__ float    g_bcat[512];
__device__ __nv_bfloat16 g_btn_hi[512 * 256];
__device__ __nv_bfloat16 g_btn_lo[512 * 256];
__device__ __nv_bfloat16 g_bte_hi[128 * 128];
__device__ __nv_bfloat16 g_bte_lo[128 * 128];
// CSR by dst
__device__ int g_deg[NN];
__device__ int g_offs[NN + 1];
__device__ int g_cursor[NN];
__device__ int g_eidx[EE];
__device__ int g_bsum[256];

// ---------------- helpers ----------------
__device__ __forceinline__ uint32_t smem_u32(const void* p) {
    uint32_t a;
    asm("{ .reg .u64 t; cvta.to.shared.u64 t, %1; cvt.u32.u64 %0, t; }" : "=r"(a) : "l"(p));
    return a;
}
__device__ __forceinline__ unsigned lds32(uint32_t a) {
    unsigned v;
    asm volatile("ld.shared.b32 %0, [%1];" : "=r"(v) : "r"(a));
    return v;
}
__device__ __forceinline__ void sts64(uint32_t a, unsigned x, unsigned y) {
    asm volatile("st.shared.v2.b32 [%0], {%1, %2};" :: "r"(a), "r"(x), "r"(y) : "memory");
}
__device__ __forceinline__ void sts128(uint32_t a, uint4 v) {
    asm volatile("st.shared.v4.b32 [%0], {%1, %2, %3, %4};"
                 :: "r"(a), "r"(v.x), "r"(v.y), "r"(v.z), "r"(v.w) : "memory");
}
#define CP_ASYNC16(dst, src) \
    asm volatile("cp.async.ca.shared.global [%0], [%1], 16;" :: "r"(dst), "l"(src) : "memory")
#define CP_COMMIT() asm volatile("cp.async.commit_group;" ::: "memory")
#define CP_WAIT0()  asm volatile("cp.async.wait_group 0;" ::: "memory")

__device__ __forceinline__ void mma_bf16(float& d0, float& d1, float& d2, float& d3,
                                         unsigned a0, unsigned a1, unsigned a2, unsigned a3,
                                         unsigned b0, unsigned b1) {
    asm volatile(
        "mma.sync.aligned.m16n8k16.row.col.f32.bf16.bf16.f32 "
        "{%0,%1,%2,%3}, {%4,%5,%6,%7}, {%8,%9}, {%0,%1,%2,%3};"
        : "+f"(d0), "+f"(d1), "+f"(d2), "+f"(d3)
        : "r"(a0), "r"(a1), "r"(a2), "r"(a3), "r"(b0), "r"(b1));
}
__device__ __forceinline__ void split2(float a, float b, unsigned& hi, unsigned& lo) {
    __nv_bfloat16 ah = __float2bfloat16_rn(a), bh = __float2bfloat16_rn(b);
    __nv_bfloat16 al = __float2bfloat16_rn(a - __bfloat162float(ah));
    __nv_bfloat16 bl = __float2bfloat16_rn(b - __bfloat162float(bh));
    hi = (unsigned)__bfloat16_as_ushort(ah) | ((unsigned)__bfloat16_as_ushort(bh) << 16);
    lo = (unsigned)__bfloat16_as_ushort(al) | ((unsigned)__bfloat16_as_ushort(bl) << 16);
}
__device__ __forceinline__ float elu_f(float v)   { return v > 0.f ? v : expm1f(v); }
__device__ __forceinline__ float lrelu_f(float v) { return v > 0.f ? v : 0.01f * v; }

// ---------------- smem layout (bytes) ----------------
#define AHI    0
#define ALO    10240
#define BHI    20480
#define BLO    30720
#define BUFSZ  40960
#define NODE_BIAS 81920
#define NODE_SMEM (81920 + 2048)
#define EST      0
#define ESRC     81920
#define EDST     82432
#define EBIAS    82944
#define EATTN    83456
#define ELSH     83968
#define EDGE_SMEM 86016

// ---------------- small kernels ----------------
__global__ void k_embed(const int* __restrict__ node_types,
                        const float* __restrict__ embed, float* __restrict__ nf) {
    int i = blockIdx.x * 256 + threadIdx.x;
    if (i < NN * 128) {
        int n = i >> 7, c = i & 127;
        nf[(size_t)n * 128 + c] = embed[node_types[n] * 128 + c];
    }
}

__global__ void k_prep(const float* __restrict__ Wni, const float* __restrict__ Wnj,
                       const float* __restrict__ Wsrc, const float* __restrict__ bsrc,
                       const float* __restrict__ Wfij,
                       float* __restrict__ bcat,
                       __nv_bfloat16* __restrict__ btn_hi, __nv_bfloat16* __restrict__ btn_lo,
                       __nv_bfloat16* __restrict__ bte_hi, __nv_bfloat16* __restrict__ bte_lo,
                       int in_n, int in_e) {
    int i = blockIdx.x * 256 + threadIdx.x;
    int nn = 512 * in_n;
    if (i < nn) {
        int n = i / in_n, k = i - n * in_n;
        float v;
        if (n < 128)      v = Wni[k * 128 + n];
        else if (n < 256) v = Wnj[k * 128 + (n - 128)];
        else              v = Wsrc[k * 256 + (n - 256)];
        __nv_bfloat16 h = __float2bfloat16_rn(v);
        __nv_bfloat16 l = __float2bfloat16_rn(v - __bfloat162float(h));
        btn_hi[(size_t)n * in_n + k] = h;
        btn_lo[(size_t)n * in_n + k] = l;
    } else if (i < nn + 128 * in_e) {
        int j = i - nn;
        int n = j / in_e, k = j - n * in_e;
        float v = Wfij[k * 128 + n];
        __nv_bfloat16 h = __float2bfloat16_rn(v);
        __nv_bfloat16 l = __float2bfloat16_rn(v - __bfloat162float(h));
        bte_hi[(size_t)n * in_e + k] = h;
        bte_lo[(size_t)n * in_e + k] = l;
    }
    if (i < 512) bcat[i] = (i < 256) ? 0.f : bsrc[i - 256];
}

// ---------------- CSR build ----------------
__global__ void k_zero_deg(int* __restrict__ deg) {
    int i = blockIdx.x * 256 + threadIdx.x;
    if (i < NN) deg[i] = 0;
}
__global__ void k_hist(const int* __restrict__ dst, int* __restrict__ deg) {
    int e = blockIdx.x * 256 + threadIdx.x;
    if (e < EE) atomicAdd(&deg[dst[e]], 1);
}
__global__ void k_scanA(const int* __restrict__ deg, int* __restrict__ bsum) {
    __shared__ int sh[256];
    int i = blockIdx.x * 256 + threadIdx.x;
    sh[threadIdx.x] = (i < NN) ? deg[i] : 0;
    __syncthreads();
    for (int o = 128; o > 0; o >>= 1) {
        if (threadIdx.x < o) sh[threadIdx.x] += sh[threadIdx.x + o];
        __syncthreads();
    }
    if (threadIdx.x == 0) bsum[blockIdx.x] = sh[0];
}
__global__ void k_scanB(int* __restrict__ bsum) {
    __shared__ int sh[256];
    int t = threadIdx.x;
    int v = (t < NB_SCAN) ? bsum[t] : 0;
    sh[t] = v;
    __syncthreads();
    for (int o = 1; o < 256; o <<= 1) {
        int add = (t >= o) ? sh[t - o] : 0;
        __syncthreads();
        sh[t] += add;
        __syncthreads();
    }
    if (t < NB_SCAN) bsum[t] = sh[t] - v;
}
__global__ void k_scanC(const int* __restrict__ deg, const int* __restrict__ bsum,
                        int* __restrict__ offs, int* __restrict__ cursor) {
    __shared__ int sh[256];
    int i = blockIdx.x * 256 + threadIdx.x;
    int t = threadIdx.x;
    int v = (i < NN) ? deg[i] : 0;
    sh[t] = v;
    __syncthreads();
    for (int o = 1; o < 256; o <<= 1) {
        int add = (t >= o) ? sh[t - o] : 0;
        __syncthreads();
        sh[t] += add;
        __syncthreads();
    }
    if (i < NN) {
        int ex = bsum[blockIdx.x] + sh[t] - v;
        offs[i] = ex;
        cursor[i] = ex;
    }
    if (i == 0) offs[NN] = EE;
}
__global__ void k_scatter(const int* __restrict__ dst, int* __restrict__ cursor,
                          int* __restrict__ eidx) {
    int e = blockIdx.x * 256 + threadIdx.x;
    if (e < EE) {
        int pos = atomicAdd(&cursor[dst[e]], 1);
        eidx[pos] = e;
    }
}

// ---------------- pipelined GEMM mainloop (R5) ----------------
__device__ __forceinline__ void b_cpasync(uint32_t sb, int buf,
                                          const __nv_bfloat16* __restrict__ Bth,
                                          const __nv_bfloat16* __restrict__ Btl,
                                          int n0, int K, int k0) {
    int tid = threadIdx.x;
#pragma unroll
    for (int i = 0; i < 2; i++) {
        int c = tid + i * 256;
        int n = c >> 2, k16 = c & 3;
        size_t go = (size_t)(n0 + n) * K + k0 + k16 * 8;
        uint32_t da = sb + buf * BUFSZ + BHI + n * 80 + k16 * 16;
        CP_ASYNC16(da, Bth + go);
        CP_ASYNC16(da + (BLO - BHI), Btl + go);
    }
}

__device__ __forceinline__ void a_convert_sts(uint32_t sb, int buf, int r, int hk,
                                              const float4 pa[4]) {
    uint32_t ah = sb + buf * BUFSZ + AHI + r * 80 + hk * 32;
    uint32_t al = ah + (ALO - AHI);
#pragma unroll
    for (int q = 0; q < 2; q++) {
        unsigned h0, l0, h1, l1, h2, l2, h3, l3;
        split2(pa[2 * q].x,     pa[2 * q].y,     h0, l0);
        split2(pa[2 * q].z,     pa[2 * q].w,     h1, l1);
        split2(pa[2 * q + 1].x, pa[2 * q + 1].y, h2, l2);
        split2(pa[2 * q + 1].z, pa[2 * q + 1].w, h3, l3);
        sts128(ah + q * 16, make_uint4(h0, h1, h2, h3));
        sts128(al + q * 16, make_uint4(l0, l1, l2, l3));
    }
}

__device__ __forceinline__ void mma_compute(uint32_t sb, int buf, float acc[2][8][4]) {
    int tid = threadIdx.x, lane = tid & 31, wid = tid >> 5;
    int g = lane >> 2, tig = lane & 3;
    int wm = wid & 3, wn = wid >> 2;
    uint32_t bo = sb + buf * BUFSZ;
#pragma unroll
    for (int ks = 0; ks < 2; ks++) {
        unsigned ahr[2][4], alr[2][4];
        uint32_t abase = bo + AHI + (wm * 32 + g) * 80 + ks * 32 + tig * 4;
#pragma unroll
        for (int mt = 0; mt < 2; mt++) {
            uint32_t a0 = abase + mt * (16 * 80);
            ahr[mt][0] = lds32(a0);
            ahr[mt][1] = lds32(a0 + 8 * 80);
            ahr[mt][2] = lds32(a0 + 16);
            ahr[mt][3] = lds32(a0 + 8 * 80 + 16);
            uint32_t a0l = a0 + (ALO - AHI);
            alr[mt][0] = lds32(a0l);
            alr[mt][1] = lds32(a0l + 8 * 80);
            alr[mt][2] = lds32(a0l + 16);
            alr[mt][3] = lds32(a0l + 8 * 80 + 16);
        }
        uint32_t bbase = bo + BHI + (wn * 64 + g) * 80 + ks * 32 + tig * 4;
#pragma unroll
        for (int nt = 0; nt < 8; nt++) {
            uint32_t b0a = bbase + nt * (8 * 80);
            unsigned bh0 = lds32(b0a), bh1 = lds32(b0a + 16);
            unsigned bl0 = lds32(b0a + (BLO - BHI)), bl1 = lds32(b0a + (BLO - BHI) + 16);
#pragma unroll
            for (int mt = 0; mt < 2; mt++) {
                float* d = acc[mt][nt];
                mma_bf16(d[0], d[1], d[2], d[3],
                         ahr[mt][0], ahr[mt][1], ahr[mt][2], ahr[mt][3], bh0, bh1);
                mma_bf16(d[0], d[1], d[2], d[3],
                         ahr[mt][0], ahr[mt][1], ahr[mt][2], ahr[mt][3], bl0, bl1);
                mma_bf16(d[0], d[1], d[2], d[3],
                         alr[mt][0], alr[mt][1], alr[mt][2], alr[mt][3], bh0, bh1);
            }
        }
    }
}

__device__ __forceinline__ void mma_mainloop(
    uint32_t sb, const float* __restrict__ A,
    const __nv_bfloat16* __restrict__ Bth, const __nv_bfloat16* __restrict__ Btl,
    int row0, int n0, int M, int K, float acc[2][8][4]) {
    int tid = threadIdx.x;
    int r = tid >> 1, hk = tid & 1;
    int arow = row0 + r;
    bool aval = arow < M;
    const float* abase = A + (size_t)arow * K + hk * 16;
    int nst = K >> 5;

    float4 pa[4];
    const float4 z4 = make_float4(0.f, 0.f, 0.f, 0.f);
#pragma unroll
    for (int q = 0; q < 4; q++) pa[q] = aval ? *(const float4*)(abase + q * 4) : z4;
    b_cpasync(sb, 0, Bth, Btl, n0, K, 0);
    CP_COMMIT();
    a_convert_sts(sb, 0, r, hk, pa);
    CP_WAIT0();
    __syncthreads();

    for (int s = 0; s < nst; s++) {
        int buf = s & 1, nb = buf ^ 1;
        bool more = (s + 1) < nst;
        if (more) {
            b_cpasync(sb, nb, Bth, Btl, n0, K, (s + 1) * 32);
            CP_COMMIT();
            const float* ap = abase + (s + 1) * 32;
#pragma unroll
            for (int q = 0; q < 4; q++) pa[q] = aval ? *(const float4*)(ap + q * 4) : z4;
        }
        mma_compute(sb, buf, acc);
        if (more) {
            a_convert_sts(sb, nb, r, hk, pa);
            CP_WAIT0();
        }
        __syncthreads();
    }
}

// ---------------- node GEMM ----------------
__global__ __launch_bounds__(256, 2) void gemm_node_mma(
    const float* __restrict__ A,
    const __nv_bfloat16* __restrict__ Bth, const __nv_bfloat16* __restrict__ Btl,
    const float* __restrict__ bias, float* __restrict__ Cout, int M, int K) {
    extern __shared__ __align__(16) char smem[];
    uint32_t sb = smem_u32(smem);
    float* bsm = (float*)(smem + NODE_BIAS);
    int tid = threadIdx.x;
    ((float2*)bsm)[tid] = ((const float2*)bias)[tid];

    int row0 = blockIdx.x * 128, n0 = blockIdx.y * 128;
    float acc[2][8][4];
#pragma unroll
    for (int mt = 0; mt < 2; mt++)
#pragma unroll
        for (int nt = 0; nt < 8; nt++)
#pragma unroll
            for (int q = 0; q < 4; q++) acc[mt][nt][q] = 0.f;

    mma_mainloop(sb, A, Bth, Btl, row0, n0, M, K, acc);

    int lane = tid & 31, wid = tid >> 5;
    int g = lane >> 2, tig = lane & 3;
    int wm = wid & 3, wn = wid >> 2;
#pragma unroll
    for (int mt = 0; mt < 2; mt++) {
        int r0 = row0 + wm * 32 + mt * 16 + g;
#pragma unroll
        for (int nt = 0; nt < 8; nt++) {
            int cc = n0 + wn * 64 + nt * 8 + 2 * tig;
            float b0 = bsm[cc], b1 = bsm[cc + 1];
            float* d = acc[mt][nt];
            if (r0 < M)
                *(float2*)(Cout + (size_t)r0 * 512 + cc) = make_float2(d[0] + b0, d[1] + b1);
            if (r0 + 8 < M)
                *(float2*)(Cout + (size_t)(r0 + 8) * 512 + cc) = make_float2(d[2] + b0, d[3] + b1);
        }
    }
}

// ---------------- edge GEMM fused epilogue (R5) ----------------
__global__ __launch_bounds__(256, 2) void gemm_edge_mma(
    const float* __restrict__ A,
    const __nv_bfloat16* __restrict__ Bth, const __nv_bfloat16* __restrict__ Btl,
    const float* __restrict__ node_out,
    const int* __restrict__ src, const int* __restrict__ dst,
    const float* __restrict__ bias, const float* __restrict__ attn,
    float* __restrict__ ef_out, float* __restrict__ elog, int M, int K) {
    extern __shared__ __align__(16) char smem[];
    uint32_t sb = smem_u32(smem);
    float* stage = (float*)(smem + EST);
    int*   ssh = (int*)(smem + ESRC);
    int*   dsh = (int*)(smem + EDST);
    float* bsh = (float*)(smem + EBIAS);
    float* ash = (float*)(smem + EATTN);
    float* lsh = (float*)(smem + ELSH);

    int tid = threadIdx.x;
    int e0 = blockIdx.x * 128;
    if (tid < 128) {
        int e = e0 + tid;
        ssh[tid] = (e < M) ? src[e] : 0;
        dsh[tid] = (e < M) ? dst[e] : 0;
        bsh[tid] = bias[tid];
        ash[tid] = attn[tid];
    }

    float acc[2][8][4];
#pragma unroll
    for (int mt = 0; mt < 2; mt++)
#pragma unroll
        for (int nt = 0; nt < 8; nt++)
#pragma unroll
            for (int q = 0; q < 4; q++) acc[mt][nt][q] = 0.f;

    mma_mainloop(sb, A, Bth, Btl, e0, 0, M, K, acc);

    int lane = tid & 31, wid = tid >> 5;
    int g = lane >> 2, tig = lane & 3;
    int wm = wid & 3, wn = wid >> 2;
#pragma unroll
    for (int mt = 0; mt < 2; mt++) {
        int r = wm * 32 + mt * 16 + g;
#pragma unroll
        for (int nt = 0; nt < 8; nt++) {
            int cc = wn * 64 + nt * 8 + 2 * tig;
            float* d = acc[mt][nt];
            *(float2*)&stage[r * 132 + cc] = make_float2(d[0], d[1]);
            *(float2*)&stage[(r + 8) * 132 + cc] = make_float2(d[2], d[3]);
        }
    }
    __syncthreads();

    {
        int r = tid & 127, hc = tid >> 7;
        int e = e0 + r;
        if (e < M) {
            int si = ssh[r], dj = dsh[r];
            const float* pni = node_out + (size_t)si * 512 + hc * 64;
            const float* pnj = node_out + (size_t)dj * 512 + 128 + hc * 64;
            const float* sp = stage + r * 132 + hc * 64;
            float* op = ef_out + (size_t)e * 128 + hc * 64;
            float part[2] = {0.f, 0.f};
#pragma unroll
            for (int q = 0; q < 16; q++) {
                int c = hc * 64 + q * 4;
                float4 sv = *(const float4*)(sp + q * 4);
                float4 a = *(const float4*)(pni + q * 4);
                float4 b = *(const float4*)(pnj + q * 4);
                float4 o;
                float v;
                v = sv.x + a.x + b.x + bsh[c + 0];
                v = lrelu_f(v); part[q >> 3] += v * ash[c + 0]; o.x = elu_f(v);
                v = sv.y + a.y + b.y + bsh[c + 1];
                v = lrelu_f(v); part[q >> 3] += v * ash[c + 1]; o.y = elu_f(v);
                v = sv.z + a.z + b.z + bsh[c + 2];
                v = lrelu_f(v); part[q >> 3] += v * ash[c + 2]; o.z = elu_f(v);
                v = sv.w + a.w + b.w + bsh[c + 3];
                v = lrelu_f(v); part[q >> 3] += v * ash[c + 3]; o.w = elu_f(v);
                *(float4*)(op + q * 4) = o;
            }
            lsh[r * 4 + hc * 2 + 0] = part[0];
            lsh[r * 4 + hc * 2 + 1] = part[1];
        }
    }
    __syncthreads();

    for (int t = tid; t < 512; t += 256) {
        int r2 = t >> 2, h = t & 3;
        int e2 = e0 + r2;
        if (e2 < M) elog[(size_t)e2 * 4 + h] = lsh[r2 * 4 + h];
    }
}

// ---------------- CSR aggregation (2-way unrolled accumulation) ----------------
__global__ __launch_bounds__(256) void k_aggr(
    const int* __restrict__ srcs, const int* __restrict__ eidx,
    const int* __restrict__ offs, const float* __restrict__ elog,
    const float* __restrict__ node_out, float* __restrict__ outp) {
    int node = (blockIdx.x * 256 + threadIdx.x) >> 5;
    int lane = threadIdx.x & 31;
    if (node >= NN) return;
    int beg = offs[node], end = offs[node + 1];

    float4 mx = make_float4(-1e30f, -1e30f, -1e30f, -1e30f);
    for (int j = beg + lane; j < end; j += 32) {
        int e = eidx[j];
        float4 l = *(const float4*)(elog + (size_t)e * 4);
        mx.x = fmaxf(mx.x, l.x); mx.y = fmaxf(mx.y, l.y);
        mx.z = fmaxf(mx.z, l.z); mx.w = fmaxf(mx.w, l.w);
    }
#pragma unroll
    for (int o = 16; o > 0; o >>= 1) {
        mx.x = fmaxf(mx.x, __shfl_xor_sync(0xFFFFFFFFu, mx.x, o));
        mx.y = fmaxf(mx.y, __shfl_xor_sync(0xFFFFFFFFu, mx.y, o));
        mx.z = fmaxf(mx.z, __shfl_xor_sync(0xFFFFFFFFu, mx.z, o));
        mx.w = fmaxf(mx.w, __shfl_xor_sync(0xFFFFFFFFu, mx.w, o));
    }
    int h = lane >> 3;
    float mh = (h == 0) ? mx.x : (h == 1) ? mx.y : (h == 2) ? mx.z : mx.w;

    float acc[8] = {0.f, 0.f, 0.f, 0.f, 0.f, 0.f, 0.f, 0.f};
    float ssum = 0.f;
    int j = beg;
    for (; j + 1 < end; j += 2) {
        int ea = eidx[j], eb = eidx[j + 1];
        int sa = srcs[ea], sbn = srcs[eb];
        float la = elog[(size_t)ea * 4 + h], lb = elog[(size_t)eb * 4 + h];
        const float4* pa = (const float4*)(node_out + (size_t)sa * 512 + 256) + lane * 2;
        const float4* pb = (const float4*)(node_out + (size_t)sbn * 512 + 256) + lane * 2;
        float4 a0 = pa[0], a1 = pa[1];
        float4 b0 = pb[0], b1 = pb[1];
        float wa = expf(la - mh), wb = expf(lb - mh);
        ssum += wa + wb;
        acc[0] += wa * a0.x + wb * b0.x; acc[1] += wa * a0.y + wb * b0.y;
        acc[2] += wa * a0.z + wb * b0.z; acc[3] += wa * a0.w + wb * b0.w;
        acc[4] += wa * a1.x + wb * b1.x; acc[5] += wa * a1.y + wb * b1.y;
        acc[6] += wa * a1.z + wb * b1.z; acc[7] += wa * a1.w + wb * b1.w;
    }
    if (j < end) {
        int e = eidx[j];
        float w = expf(elog[(size_t)e * 4 + h] - mh);
        ssum += w;
        const float4* hp = (const float4*)(node_out + (size_t)srcs[e] * 512 + 256) + lane * 2;
        float4 v0 = hp[0], v1 = hp[1];
        acc[0] += w * v0.x; acc[1] += w * v0.y; acc[2] += w * v0.z; acc[3] += w * v0.w;
        acc[4] += w * v1.x; acc[5] += w * v1.y; acc[6] += w * v1.z; acc[7] += w * v1.w;
    }
    float inv = (end > beg) ? 1.f / ssum : 0.f;
    float* op = outp + (size_t)node * 256 + lane * 8;
    float4 o0, o1;
    o0.x = elu_f(acc[0] * inv); o0.y = elu_f(acc[1] * inv);
    o0.z = elu_f(acc[2] * inv); o0.w = elu_f(acc[3] * inv);
    o1.x = elu_f(acc[4] * inv); o1.y = elu_f(acc[5] * inv);
    o1.z = elu_f(acc[6] * inv); o1.w = elu_f(acc[7] * inv);
    *(float4*)op = o0;
    *(float4*)(op + 4) = o1;
}

// ---------------- host ----------------
extern "C" void kernel_launch(void* const* d_in, const int* in_sizes, int n_in,
                              void* d_out, int out_size) {
    const int*   node_types = (const int*)d_in[0];
    const int*   src        = (const int*)d_in[1];
    const int*   dst        = (const int*)d_in[2];
    const float* efeats     = (const float*)d_in[3];
    const float* embed      = (const float*)d_in[4];
    const float* W_src[2] = {(const float*)d_in[5],  (const float*)d_in[12]};
    const float* b_src[2] = {(const float*)d_in[6],  (const float*)d_in[13]};
    const float* W_ni[2]  = {(const float*)d_in[7],  (const float*)d_in[14]};
    const float* W_nj[2]  = {(const float*)d_in[8],  (const float*)d_in[15]};
    const float* W_fij[2] = {(const float*)d_in[9],  (const float*)d_in[16]};
    const float* attn[2]  = {(const float*)d_in[10], (const float*)d_in[17]};
    const float* bias[2]  = {(const float*)d_in[11], (const float*)d_in[18]};

    float *nf, *node_out, *efbuf, *elog, *bcat;
    int *deg, *offs, *cursor, *eidx, *bsum;
    __nv_bfloat16 *btnh, *btnl, *bteh, *btel;
    cudaGetSymbolAddress((void**)&nf, g_nf);
    cudaGetSymbolAddress((void**)&node_out, g_node_out);
    cudaGetSymbolAddress((void**)&efbuf, g_efbuf);
    cudaGetSymbolAddress((void**)&elog, g_elog);
    cudaGetSymbolAddress((void**)&bcat, g_bcat);
    cudaGetSymbolAddress((void**)&btnh, g_btn_hi);
    cudaGetSymbolAddress((void**)&btnl, g_btn_lo);
    cudaGetSymbolAddress((void**)&bteh, g_bte_hi);
    cudaGetSymbolAddress((void**)&btel, g_bte_lo);
    cudaGetSymbolAddress((void**)&deg, g_deg);
    cudaGetSymbolAddress((void**)&offs, g_offs);
    cudaGetSymbolAddress((void**)&cursor, g_cursor);
    cudaGetSymbolAddress((void**)&eidx, g_eidx);
    cudaGetSymbolAddress((void**)&bsum, g_bsum);

    cudaFuncSetAttribute(gemm_node_mma, cudaFuncAttributeMaxDynamicSharedMemorySize, NODE_SMEM);
    cudaFuncSetAttribute(gemm_edge_mma, cudaFuncAttributeMaxDynamicSharedMemorySize, EDGE_SMEM);

    float* out_nf = (float*)d_out;
    float* out_ef = out_nf + (size_t)NN * 256;

    k_embed<<<(NN * 128 + 255) / 256, 256>>>(node_types, embed, nf);

    // CSR by dst (edges identical across layers)
    k_zero_deg<<<NB_SCAN, 256>>>(deg);
    k_hist<<<(EE + 255) / 256, 256>>>(dst, deg);
    k_scanA<<<NB_SCAN, 256>>>(deg, bsum);
    k_scanB<<<1, 256>>>(bsum);
    k_scanC<<<NB_SCAN, 256>>>(deg, bsum, offs, cursor);
    k_scatter<<<(EE + 255) / 256, 256>>>(dst, cursor, eidx);

    const float* ef_in = efeats;
    for (int L = 0; L < 2; L++) {
        int in_n = L ? 256 : 128;
        int in_e = L ? 128 : 64;
        int prep_items = 512 * in_n + 128 * in_e;
        k_prep<<<(prep_items + 255) / 256, 256>>>(W_ni[L], W_nj[L], W_src[L], b_src[L],
                                                  W_fij[L], bcat, btnh, btnl, bteh, btel,
                                                  in_n, in_e);

        dim3 gn((NN + 127) / 128, 4);
        gemm_node_mma<<<gn, 256, NODE_SMEM>>>(nf, btnh, btnl, bcat, node_out, NN, in_n);

        float* ef_out = L ? out_ef : efbuf;
        gemm_edge_mma<<<(EE + 127) / 128, 256, EDGE_SMEM>>>(ef_in, bteh, btel, node_out,
                                                            src, dst, bias[L], attn[L],
                                                            ef_out, elog, EE, in_e);

        float* nf_out = L ? out_nf : nf;
        k_aggr<<<(NN * 32 + 255) / 256, 256>>>(src, eidx, offs, elog, node_out, nf_out);
        ef_in = ef_out;
    }
}

// round 9
// speedup vs baseline: 1.4085x; 1.1836x over previous
#include <cuda_runtime.h>
#include <cuda_bf16.h>
#include <math.h>
#include <stdint.h>

#define NN 50000
#define EE 500000
#define NB_SCAN ((NN + 255) / 256)   // 196

// ---------------- scratch ----------------
__device__ float    g_nf[(size_t)NN * 256];
__device__ float    g_node_out[(size_t)NN * 512];  // [f_ni(128) | f_nj(128) | h_src(256)]
__device__ float    g_efbuf[(size_t)EE * 128];
__device__ float    g_elog[(size_t)EE * 4];        // raw attention logits
__device__ float    g_bcat[512];
__device__ __nv_bfloat16 g_btn_hi[512 * 256];
__device__ __nv_bfloat16 g_btn_lo[512 * 256];
__device__ __nv_bfloat16 g_bte_hi[128 * 128];
__device__ __nv_bfloat16 g_bte_lo[128 * 128];
// CSR by dst
__device__ int g_deg[NN];
__device__ int g_offs[NN + 1];
__device__ int g_cursor[NN];
__device__ int g_eidx[EE];
__device__ int g_bsum[256];

// ---------------- helpers ----------------
__device__ __forceinline__ uint32_t smem_u32(const void* p) {
    uint32_t a;
    asm("{ .reg .u64 t; cvta.to.shared.u64 t, %1; cvt.u32.u64 %0, t; }" : "=r"(a) : "l"(p));
    return a;
}
__device__ __forceinline__ unsigned lds32(uint32_t a) {
    unsigned v;
    asm volatile("ld.shared.b32 %0, [%1];" : "=r"(v) : "r"(a));
    return v;
}
__device__ __forceinline__ void sts128(uint32_t a, uint4 v) {
    asm volatile("st.shared.v4.b32 [%0], {%1, %2, %3, %4};"
                 :: "r"(a), "r"(v.x), "r"(v.y), "r"(v.z), "r"(v.w) : "memory");
}
#define CP_ASYNC16(dst, src) \
    asm volatile("cp.async.ca.shared.global [%0], [%1], 16;" :: "r"(dst), "l"(src) : "memory")
#define CP_COMMIT() asm volatile("cp.async.commit_group;" ::: "memory")
#define CP_WAIT0()  asm volatile("cp.async.wait_group 0;" ::: "memory")

__device__ __forceinline__ void mma_bf16(float& d0, float& d1, float& d2, float& d3,
                                         unsigned a0, unsigned a1, unsigned a2, unsigned a3,
                                         unsigned b0, unsigned b1) {
    asm volatile(
        "mma.sync.aligned.m16n8k16.row.col.f32.bf16.bf16.f32 "
        "{%0,%1,%2,%3}, {%4,%5,%6,%7}, {%8,%9}, {%0,%1,%2,%3};"
        : "+f"(d0), "+f"(d1), "+f"(d2), "+f"(d3)
        : "r"(a0), "r"(a1), "r"(a2), "r"(a3), "r"(b0), "r"(b1));
}
__device__ __forceinline__ void split2(float a, float b, unsigned& hi, unsigned& lo) {
    __nv_bfloat16 ah = __float2bfloat16_rn(a), bh = __float2bfloat16_rn(b);
    __nv_bfloat16 al = __float2bfloat16_rn(a - __bfloat162float(ah));
    __nv_bfloat16 bl = __float2bfloat16_rn(b - __bfloat162float(bh));
    hi = (unsigned)__bfloat16_as_ushort(ah) | ((unsigned)__bfloat16_as_ushort(bh) << 16);
    lo = (unsigned)__bfloat16_as_ushort(al) | ((unsigned)__bfloat16_as_ushort(bl) << 16);
}
__device__ __forceinline__ float elu_f(float v)   { return v > 0.f ? v : expm1f(v); }
__device__ __forceinline__ float lrelu_f(float v) { return v > 0.f ? v : 0.01f * v; }

// ---------------- smem layout (bytes) ----------------
#define AHI    0
#define ALO    10240
#define BHI    20480
#define BLO    30720
#define BUFSZ  40960
#define NODE_BIAS 81920
#define NODE_SMEM (81920 + 2048)
// edge: no stage buffer anymore
#define ESRC     81920
#define EDST     82432
#define EBIAS    82944
#define EATTN    83456
#define EDGE_SMEM 83968

// ---------------- small kernels ----------------
__global__ void k_embed(const int* __restrict__ node_types,
                        const float* __restrict__ embed, float* __restrict__ nf) {
    int i = blockIdx.x * 256 + threadIdx.x;
    if (i < NN * 128) {
        int n = i >> 7, c = i & 127;
        nf[(size_t)n * 128 + c] = embed[node_types[n] * 128 + c];
    }
}

__global__ void k_prep(const float* __restrict__ Wni, const float* __restrict__ Wnj,
                       const float* __restrict__ Wsrc, const float* __restrict__ bsrc,
                       const float* __restrict__ Wfij,
                       float* __restrict__ bcat,
                       __nv_bfloat16* __restrict__ btn_hi, __nv_bfloat16* __restrict__ btn_lo,
                       __nv_bfloat16* __restrict__ bte_hi, __nv_bfloat16* __restrict__ bte_lo,
                       int in_n, int in_e) {
    int i = blockIdx.x * 256 + threadIdx.x;
    int nn = 512 * in_n;
    if (i < nn) {
        int n = i / in_n, k = i - n * in_n;
        float v;
        if (n < 128)      v = Wni[k * 128 + n];
        else if (n < 256) v = Wnj[k * 128 + (n - 128)];
        else              v = Wsrc[k * 256 + (n - 256)];
        __nv_bfloat16 h = __float2bfloat16_rn(v);
        __nv_bfloat16 l = __float2bfloat16_rn(v - __bfloat162float(h));
        btn_hi[(size_t)n * in_n + k] = h;
        btn_lo[(size_t)n * in_n + k] = l;
    } else if (i < nn + 128 * in_e) {
        int j = i - nn;
        int n = j / in_e, k = j - n * in_e;
        float v = Wfij[k * 128 + n];
        __nv_bfloat16 h = __float2bfloat16_rn(v);
        __nv_bfloat16 l = __float2bfloat16_rn(v - __bfloat162float(h));
        bte_hi[(size_t)n * in_e + k] = h;
        bte_lo[(size_t)n * in_e + k] = l;
    }
    if (i < 512) bcat[i] = (i < 256) ? 0.f : bsrc[i - 256];
}

// ---------------- CSR build ----------------
__global__ void k_zero_deg(int* __restrict__ deg) {
    int i = blockIdx.x * 256 + threadIdx.x;
    if (i < NN) deg[i] = 0;
}
__global__ void k_hist(const int* __restrict__ dst, int* __restrict__ deg) {
    int e = blockIdx.x * 256 + threadIdx.x;
    if (e < EE) atomicAdd(&deg[dst[e]], 1);
}
__global__ void k_scanA(const int* __restrict__ deg, int* __restrict__ bsum) {
    __shared__ int sh[256];
    int i = blockIdx.x * 256 + threadIdx.x;
    sh[threadIdx.x] = (i < NN) ? deg[i] : 0;
    __syncthreads();
    for (int o = 128; o > 0; o >>= 1) {
        if (threadIdx.x < o) sh[threadIdx.x] += sh[threadIdx.x + o];
        __syncthreads();
    }
    if (threadIdx.x == 0) bsum[blockIdx.x] = sh[0];
}
__global__ void k_scanB(int* __restrict__ bsum) {
    __shared__ int sh[256];
    int t = threadIdx.x;
    int v = (t < NB_SCAN) ? bsum[t] : 0;
    sh[t] = v;
    __syncthreads();
    for (int o = 1; o < 256; o <<= 1) {
        int add = (t >= o) ? sh[t - o] : 0;
        __syncthreads();
        sh[t] += add;
        __syncthreads();
    }
    if (t < NB_SCAN) bsum[t] = sh[t] - v;
}
__global__ void k_scanC(const int* __restrict__ deg, const int* __restrict__ bsum,
                        int* __restrict__ offs, int* __restrict__ cursor) {
    __shared__ int sh[256];
    int i = blockIdx.x * 256 + threadIdx.x;
    int t = threadIdx.x;
    int v = (i < NN) ? deg[i] : 0;
    sh[t] = v;
    __syncthreads();
    for (int o = 1; o < 256; o <<= 1) {
        int add = (t >= o) ? sh[t - o] : 0;
        __syncthreads();
        sh[t] += add;
        __syncthreads();
    }
    if (i < NN) {
        int ex = bsum[blockIdx.x] + sh[t] - v;
        offs[i] = ex;
        cursor[i] = ex;
    }
    if (i == 0) offs[NN] = EE;
}
__global__ void k_scatter(const int* __restrict__ dst, int* __restrict__ cursor,
                          int* __restrict__ eidx) {
    int e = blockIdx.x * 256 + threadIdx.x;
    if (e < EE) {
        int pos = atomicAdd(&cursor[dst[e]], 1);
        eidx[pos] = e;
    }
}

// ---------------- pipelined GEMM mainloop (R5, unchanged) ----------------
__device__ __forceinline__ void b_cpasync(uint32_t sb, int buf,
                                          const __nv_bfloat16* __restrict__ Bth,
                                          const __nv_bfloat16* __restrict__ Btl,
                                          int n0, int K, int k0) {
    int tid = threadIdx.x;
#pragma unroll
    for (int i = 0; i < 2; i++) {
        int c = tid + i * 256;
        int n = c >> 2, k16 = c & 3;
        size_t go = (size_t)(n0 + n) * K + k0 + k16 * 8;
        uint32_t da = sb + buf * BUFSZ + BHI + n * 80 + k16 * 16;
        CP_ASYNC16(da, Bth + go);
        CP_ASYNC16(da + (BLO - BHI), Btl + go);
    }
}

__device__ __forceinline__ void a_convert_sts(uint32_t sb, int buf, int r, int hk,
                                              const float4 pa[4]) {
    uint32_t ah = sb + buf * BUFSZ + AHI + r * 80 + hk * 32;
    uint32_t al = ah + (ALO - AHI);
#pragma unroll
    for (int q = 0; q < 2; q++) {
        unsigned h0, l0, h1, l1, h2, l2, h3, l3;
        split2(pa[2 * q].x,     pa[2 * q].y,     h0, l0);
        split2(pa[2 * q].z,     pa[2 * q].w,     h1, l1);
        split2(pa[2 * q + 1].x, pa[2 * q + 1].y, h2, l2);
        split2(pa[2 * q + 1].z, pa[2 * q + 1].w, h3, l3);
        sts128(ah + q * 16, make_uint4(h0, h1, h2, h3));
        sts128(al + q * 16, make_uint4(l0, l1, l2, l3));
    }
}

__device__ __forceinline__ void mma_compute(uint32_t sb, int buf, float acc[2][8][4]) {
    int tid = threadIdx.x, lane = tid & 31, wid = tid >> 5;
    int g = lane >> 2, tig = lane & 3;
    int wm = wid & 3, wn = wid >> 2;
    uint32_t bo = sb + buf * BUFSZ;
#pragma unroll
    for (int ks = 0; ks < 2; ks++) {
        unsigned ahr[2][4], alr[2][4];
        uint32_t abase = bo + AHI + (wm * 32 + g) * 80 + ks * 32 + tig * 4;
#pragma unroll
        for (int mt = 0; mt < 2; mt++) {
            uint32_t a0 = abase + mt * (16 * 80);
            ahr[mt][0] = lds32(a0);
            ahr[mt][1] = lds32(a0 + 8 * 80);
            ahr[mt][2] = lds32(a0 + 16);
            ahr[mt][3] = lds32(a0 + 8 * 80 + 16);
            uint32_t a0l = a0 + (ALO - AHI);
            alr[mt][0] = lds32(a0l);
            alr[mt][1] = lds32(a0l + 8 * 80);
            alr[mt][2] = lds32(a0l + 16);
            alr[mt][3] = lds32(a0l + 8 * 80 + 16);
        }
        uint32_t bbase = bo + BHI + (wn * 64 + g) * 80 + ks * 32 + tig * 4;
#pragma unroll
        for (int nt = 0; nt < 8; nt++) {
            uint32_t b0a = bbase + nt * (8 * 80);
            unsigned bh0 = lds32(b0a), bh1 = lds32(b0a + 16);
            unsigned bl0 = lds32(b0a + (BLO - BHI)), bl1 = lds32(b0a + (BLO - BHI) + 16);
#pragma unroll
            for (int mt = 0; mt < 2; mt++) {
                float* d = acc[mt][nt];
                mma_bf16(d[0], d[1], d[2], d[3],
                         ahr[mt][0], ahr[mt][1], ahr[mt][2], ahr[mt][3], bh0, bh1);
                mma_bf16(d[0], d[1], d[2], d[3],
                         ahr[mt][0], ahr[mt][1], ahr[mt][2], ahr[mt][3], bl0, bl1);
                mma_bf16(d[0], d[1], d[2], d[3],
                         alr[mt][0], alr[mt][1], alr[mt][2], alr[mt][3], bh0, bh1);
            }
        }
    }
}

__device__ __forceinline__ void mma_mainloop(
    uint32_t sb, const float* __restrict__ A,
    const __nv_bfloat16* __restrict__ Bth, const __nv_bfloat16* __restrict__ Btl,
    int row0, int n0, int M, int K, float acc[2][8][4]) {
    int tid = threadIdx.x;
    int r = tid >> 1, hk = tid & 1;
    int arow = row0 + r;
    bool aval = arow < M;
    const float* abase = A + (size_t)arow * K + hk * 16;
    int nst = K >> 5;

    float4 pa[4];
    const float4 z4 = make_float4(0.f, 0.f, 0.f, 0.f);
#pragma unroll
    for (int q = 0; q < 4; q++) pa[q] = aval ? *(const float4*)(abase + q * 4) : z4;
    b_cpasync(sb, 0, Bth, Btl, n0, K, 0);
    CP_COMMIT();
    a_convert_sts(sb, 0, r, hk, pa);
    CP_WAIT0();
    __syncthreads();

    for (int s = 0; s < nst; s++) {
        int buf = s & 1, nb = buf ^ 1;
        bool more = (s + 1) < nst;
        if (more) {
            b_cpasync(sb, nb, Bth, Btl, n0, K, (s + 1) * 32);
            CP_COMMIT();
            const float* ap = abase + (s + 1) * 32;
#pragma unroll
            for (int q = 0; q < 4; q++) pa[q] = aval ? *(const float4*)(ap + q * 4) : z4;
        }
        mma_compute(sb, buf, acc);
        if (more) {
            a_convert_sts(sb, nb, r, hk, pa);
            CP_WAIT0();
        }
        __syncthreads();
    }
}

// ---------------- node GEMM ----------------
__global__ __launch_bounds__(256, 2) void gemm_node_mma(
    const float* __restrict__ A,
    const __nv_bfloat16* __restrict__ Bth, const __nv_bfloat16* __restrict__ Btl,
    const float* __restrict__ bias, float* __restrict__ Cout, int M, int K) {
    extern __shared__ __align__(16) char smem[];
    uint32_t sb = smem_u32(smem);
    float* bsm = (float*)(smem + NODE_BIAS);
    int tid = threadIdx.x;
    ((float2*)bsm)[tid] = ((const float2*)bias)[tid];

    int row0 = blockIdx.x * 128, n0 = blockIdx.y * 128;
    float acc[2][8][4];
#pragma unroll
    for (int mt = 0; mt < 2; mt++)
#pragma unroll
        for (int nt = 0; nt < 8; nt++)
#pragma unroll
            for (int q = 0; q < 4; q++) acc[mt][nt][q] = 0.f;

    mma_mainloop(sb, A, Bth, Btl, row0, n0, M, K, acc);

    int lane = tid & 31, wid = tid >> 5;
    int g = lane >> 2, tig = lane & 3;
    int wm = wid & 3, wn = wid >> 2;
#pragma unroll
    for (int mt = 0; mt < 2; mt++) {
        int r0 = row0 + wm * 32 + mt * 16 + g;
#pragma unroll
        for (int nt = 0; nt < 8; nt++) {
            int cc = n0 + wn * 64 + nt * 8 + 2 * tig;
            float b0 = bsm[cc], b1 = bsm[cc + 1];
            float* d = acc[mt][nt];
            if (r0 < M)
                *(float2*)(Cout + (size_t)r0 * 512 + cc) = make_float2(d[0] + b0, d[1] + b1);
            if (r0 + 8 < M)
                *(float2*)(Cout + (size_t)(r0 + 8) * 512 + cc) = make_float2(d[2] + b0, d[3] + b1);
        }
    }
}

// ---------------- edge GEMM: direct-from-fragment fused epilogue ----------------
__global__ __launch_bounds__(256, 2) void gemm_edge_mma(
    const float* __restrict__ A,
    const __nv_bfloat16* __restrict__ Bth, const __nv_bfloat16* __restrict__ Btl,
    const float* __restrict__ node_out,
    const int* __restrict__ src, const int* __restrict__ dst,
    const float* __restrict__ bias, const float* __restrict__ attn,
    float* __restrict__ ef_out, float* __restrict__ elog, int M, int K) {
    extern __shared__ __align__(16) char smem[];
    uint32_t sb = smem_u32(smem);
    int*   ssh = (int*)(smem + ESRC);
    int*   dsh = (int*)(smem + EDST);
    float* bsh = (float*)(smem + EBIAS);
    float* ash = (float*)(smem + EATTN);

    int tid = threadIdx.x;
    int e0 = blockIdx.x * 128;
    if (tid < 128) {
        int e = e0 + tid;
        ssh[tid] = (e < M) ? src[e] : 0;
        dsh[tid] = (e < M) ? dst[e] : 0;
        bsh[tid] = bias[tid];
        ash[tid] = attn[tid];
    }

    float acc[2][8][4];
#pragma unroll
    for (int mt = 0; mt < 2; mt++)
#pragma unroll
        for (int nt = 0; nt < 8; nt++)
#pragma unroll
            for (int q = 0; q < 4; q++) acc[mt][nt][q] = 0.f;

    mma_mainloop(sb, A, Bth, Btl, e0, 0, M, K, acc);
    // mainloop ends with __syncthreads(): ssh/dsh visible, smem tiles done

    int lane = tid & 31, wid = tid >> 5;
    int g = lane >> 2, tig = lane & 3;
    int wm = wid & 3, wn = wid >> 2;

#pragma unroll
    for (int mt = 0; mt < 2; mt++) {
        int r = wm * 32 + mt * 16 + g;       // rows r and r+8
        int rA = r, rB = r + 8;
        int eA = e0 + rA, eB = e0 + rB;
        int siA = ssh[rA], djA = dsh[rA];
        int siB = ssh[rB], djB = dsh[rB];
        const float* niA = node_out + (size_t)siA * 512;
        const float* njA = node_out + (size_t)djA * 512 + 128;
        const float* niB = node_out + (size_t)siB * 512;
        const float* njB = node_out + (size_t)djB * 512 + 128;
        float partA[2] = {0.f, 0.f};         // two heads for this wn
        float partB[2] = {0.f, 0.f};
#pragma unroll
        for (int nt = 0; nt < 8; nt++) {
            int cc = wn * 64 + nt * 8 + 2 * tig;
            int hl = nt >> 2;
            float b0 = bsh[cc], b1 = bsh[cc + 1];
            float a0 = ash[cc], a1 = ash[cc + 1];
            float2 nA0 = *(const float2*)(niA + cc);
            float2 nA1 = *(const float2*)(njA + cc);
            float2 nB0 = *(const float2*)(niB + cc);
            float2 nB1 = *(const float2*)(njB + cc);
            float* d = acc[mt][nt];
            float v0 = lrelu_f(d[0] + nA0.x + nA1.x + b0);
            float v1 = lrelu_f(d[1] + nA0.y + nA1.y + b1);
            partA[hl] += v0 * a0 + v1 * a1;
            if (eA < M)
                *(float2*)(ef_out + (size_t)eA * 128 + cc) = make_float2(elu_f(v0), elu_f(v1));
            float w0 = lrelu_f(d[2] + nB0.x + nB1.x + b0);
            float w1 = lrelu_f(d[3] + nB0.y + nB1.y + b1);
            partB[hl] += w0 * a0 + w1 * a1;
            if (eB < M)
                *(float2*)(ef_out + (size_t)eB * 128 + cc) = make_float2(elu_f(w0), elu_f(w1));
        }
        // reduce over the 4 tig lanes (lane bits 0,1)
#pragma unroll
        for (int o = 1; o <= 2; o <<= 1) {
            partA[0] += __shfl_xor_sync(0xFFFFFFFFu, partA[0], o);
            partA[1] += __shfl_xor_sync(0xFFFFFFFFu, partA[1], o);
            partB[0] += __shfl_xor_sync(0xFFFFFFFFu, partB[0], o);
            partB[1] += __shfl_xor_sync(0xFFFFFFFFu, partB[1], o);
        }
        if (tig == 0) {
            int h0 = wn * 2, h1 = wn * 2 + 1;
            if (eA < M) {
                elog[(size_t)eA * 4 + h0] = partA[0];
                elog[(size_t)eA * 4 + h1] = partA[1];
            }
            if (eB < M) {
                elog[(size_t)eB * 4 + h0] = partB[0];
                elog[(size_t)eB * 4 + h1] = partB[1];
            }
        }
    }
}

// ---------------- CSR aggregation (2-way unrolled accumulation) ----------------
__global__ __launch_bounds__(256) void k_aggr(
    const int* __restrict__ srcs, const int* __restrict__ eidx,
    const int* __restrict__ offs, const float* __restrict__ elog,
    const float* __restrict__ node_out, float* __restrict__ outp) {
    int node = (blockIdx.x * 256 + threadIdx.x) >> 5;
    int lane = threadIdx.x & 31;
    if (node >= NN) return;
    int beg = offs[node], end = offs[node + 1];

    float4 mx = make_float4(-1e30f, -1e30f, -1e30f, -1e30f);
    for (int j = beg + lane; j < end; j += 32) {
        int e = eidx[j];
        float4 l = *(const float4*)(elog + (size_t)e * 4);
        mx.x = fmaxf(mx.x, l.x); mx.y = fmaxf(mx.y, l.y);
        mx.z = fmaxf(mx.z, l.z); mx.w = fmaxf(mx.w, l.w);
    }
#pragma unroll
    for (int o = 16; o > 0; o >>= 1) {
        mx.x = fmaxf(mx.x, __shfl_xor_sync(0xFFFFFFFFu, mx.x, o));
        mx.y = fmaxf(mx.y, __shfl_xor_sync(0xFFFFFFFFu, mx.y, o));
        mx.z = fmaxf(mx.z, __shfl_xor_sync(0xFFFFFFFFu, mx.z, o));
        mx.w = fmaxf(mx.w, __shfl_xor_sync(0xFFFFFFFFu, mx.w, o));
    }
    int h = lane >> 3;
    float mh = (h == 0) ? mx.x : (h == 1) ? mx.y : (h == 2) ? mx.z : mx.w;

    float acc[8] = {0.f, 0.f, 0.f, 0.f, 0.f, 0.f, 0.f, 0.f};
    float ssum = 0.f;
    int j = beg;
    for (; j + 1 < end; j += 2) {
        int ea = eidx[j], eb = eidx[j + 1];
        int sa = srcs[ea], sbn = srcs[eb];
        float la = elog[(size_t)ea * 4 + h], lb = elog[(size_t)eb * 4 + h];
        const float4* pa = (const float4*)(node_out + (size_t)sa * 512 + 256) + lane * 2;
        const float4* pb = (const float4*)(node_out + (size_t)sbn * 512 + 256) + lane * 2;
        float4 a0 = pa[0], a1 = pa[1];
        float4 b0 = pb[0], b1 = pb[1];
        float wa = expf(la - mh), wb = expf(lb - mh);
        ssum += wa + wb;
        acc[0] += wa * a0.x + wb * b0.x; acc[1] += wa * a0.y + wb * b0.y;
        acc[2] += wa * a0.z + wb * b0.z; acc[3] += wa * a0.w + wb * b0.w;
        acc[4] += wa * a1.x + wb * b1.x; acc[5] += wa * a1.y + wb * b1.y;
        acc[6] += wa * a1.z + wb * b1.z; acc[7] += wa * a1.w + wb * b1.w;
    }
    if (j < end) {
        int e = eidx[j];
        float w = expf(elog[(size_t)e * 4 + h] - mh);
        ssum += w;
        const float4* hp = (const float4*)(node_out + (size_t)srcs[e] * 512 + 256) + lane * 2;
        float4 v0 = hp[0], v1 = hp[1];
        acc[0] += w * v0.x; acc[1] += w * v0.y; acc[2] += w * v0.z; acc[3] += w * v0.w;
        acc[4] += w * v1.x; acc[5] += w * v1.y; acc[6] += w * v1.z; acc[7] += w * v1.w;
    }
    float inv = (end > beg) ? 1.f / ssum : 0.f;
    float* op = outp + (size_t)node * 256 + lane * 8;
    float4 o0, o1;
    o0.x = elu_f(acc[0] * inv); o0.y = elu_f(acc[1] * inv);
    o0.z = elu_f(acc[2] * inv); o0.w = elu_f(acc[3] * inv);
    o1.x = elu_f(acc[4] * inv); o1.y = elu_f(acc[5] * inv);
    o1.z = elu_f(acc[6] * inv); o1.w = elu_f(acc[7] * inv);
    *(float4*)op = o0;
    *(float4*)(op + 4) = o1;
}

// ---------------- host ----------------
extern "C" void kernel_launch(void* const* d_in, const int* in_sizes, int n_in,
                              void* d_out, int out_size) {
    const int*   node_types = (const int*)d_in[0];
    const int*   src        = (const int*)d_in[1];
    const int*   dst        = (const int*)d_in[2];
    const float* efeats     = (const float*)d_in[3];
    const float* embed      = (const float*)d_in[4];
    const float* W_src[2] = {(const float*)d_in[5],  (const float*)d_in[12]};
    const float* b_src[2] = {(const float*)d_in[6],  (const float*)d_in[13]};
    const float* W_ni[2]  = {(const float*)d_in[7],  (const float*)d_in[14]};
    const float* W_nj[2]  = {(const float*)d_in[8],  (const float*)d_in[15]};
    const float* W_fij[2] = {(const float*)d_in[9],  (const float*)d_in[16]};
    const float* attn[2]  = {(const float*)d_in[10], (const float*)d_in[17]};
    const float* bias[2]  = {(const float*)d_in[11], (const float*)d_in[18]};

    float *nf, *node_out, *efbuf, *elog, *bcat;
    int *deg, *offs, *cursor, *eidx, *bsum;
    __nv_bfloat16 *btnh, *btnl, *bteh, *btel;
    cudaGetSymbolAddress((void**)&nf, g_nf);
    cudaGetSymbolAddress((void**)&node_out, g_node_out);
    cudaGetSymbolAddress((void**)&efbuf, g_efbuf);
    cudaGetSymbolAddress((void**)&elog, g_elog);
    cudaGetSymbolAddress((void**)&bcat, g_bcat);
    cudaGetSymbolAddress((void**)&btnh, g_btn_hi);
    cudaGetSymbolAddress((void**)&btnl, g_btn_lo);
    cudaGetSymbolAddress((void**)&bteh, g_bte_hi);
    cudaGetSymbolAddress((void**)&btel, g_bte_lo);
    cudaGetSymbolAddress((void**)&deg, g_deg);
    cudaGetSymbolAddress((void**)&offs, g_offs);
    cudaGetSymbolAddress((void**)&cursor, g_cursor);
    cudaGetSymbolAddress((void**)&eidx, g_eidx);
    cudaGetSymbolAddress((void**)&bsum, g_bsum);

    cudaFuncSetAttribute(gemm_node_mma, cudaFuncAttributeMaxDynamicSharedMemorySize, NODE_SMEM);
    cudaFuncSetAttribute(gemm_edge_mma, cudaFuncAttributeMaxDynamicSharedMemorySize, EDGE_SMEM);

    float* out_nf = (float*)d_out;
    float* out_ef = out_nf + (size_t)NN * 256;

    k_embed<<<(NN * 128 + 255) / 256, 256>>>(node_types, embed, nf);

    // CSR by dst (edges identical across layers)
    k_zero_deg<<<NB_SCAN, 256>>>(deg);
    k_hist<<<(EE + 255) / 256, 256>>>(dst, deg);
    k_scanA<<<NB_SCAN, 256>>>(deg, bsum);
    k_scanB<<<1, 256>>>(bsum);
    k_scanC<<<NB_SCAN, 256>>>(deg, bsum, offs, cursor);
    k_scatter<<<(EE + 255) / 256, 256>>>(dst, cursor, eidx);

    const float* ef_in = efeats;
    for (int L = 0; L < 2; L++) {
        int in_n = L ? 256 : 128;
        int in_e = L ? 128 : 64;
        int prep_items = 512 * in_n + 128 * in_e;
        k_prep<<<(prep_items + 255) / 256, 256>>>(W_ni[L], W_nj[L], W_src[L], b_src[L],
                                                  W_fij[L], bcat, btnh, btnl, bteh, btel,
                                                  in_n, in_e);

        dim3 gn((NN + 127) / 128, 4);
        gemm_node_mma<<<gn, 256, NODE_SMEM>>>(nf, btnh, btnl, bcat, node_out, NN, in_n);

        float* ef_out = L ? out_ef : efbuf;
        gemm_edge_mma<<<(EE + 127) / 128, 256, EDGE_SMEM>>>(ef_in, bteh, btel, node_out,
                                                            src, dst, bias[L], attn[L],
                                                            ef_out, elog, EE, in_e);

        float* nf_out = L ? out_nf : nf;
        k_aggr<<<(NN * 32 + 255) / 256, 256>>>(src, eidx, offs, elog, node_out, nf_out);
        ef_in = ef_out;
    }
}

// round 11
// speedup vs baseline: 1.4328x; 1.0172x over previous
#include <cuda_runtime.h>
#include <cuda_bf16.h>
#include <cuda_fp16.h>
#include <math.h>
#include <stdint.h>

#define NN 50000
#define EE 500000
#define NB_SCAN ((NN + 255) / 256)   // 196

// ---------------- scratch ----------------
__device__ float    g_nf[(size_t)NN * 256];
__device__ float    g_node_out[(size_t)NN * 256];  // [f_ni(128) | f_nj(128)] fp32
__device__ __half   g_hsrc[(size_t)NN * 256];      // h_src in fp16
__device__ float    g_efbuf[(size_t)EE * 128];
__device__ float    g_elog[(size_t)EE * 4];        // raw attention logits
__device__ float    g_bcat[512];
__device__ __nv_bfloat16 g_btn_hi[512 * 256];
__device__ __nv_bfloat16 g_btn_lo[512 * 256];
__device__ __nv_bfloat16 g_bte_hi[128 * 128];
__device__ __nv_bfloat16 g_bte_lo[128 * 128];
// CSR by dst
__device__ int g_deg[NN];
__device__ int g_offs[NN + 1];
__device__ int g_cursor[NN];
__device__ int g_eidx[EE];
__device__ int g_bsum[256];

// ---------------- helpers ----------------
__device__ __forceinline__ uint32_t smem_u32(const void* p) {
    uint32_t a;
    asm("{ .reg .u64 t; cvta.to.shared.u64 t, %1; cvt.u32.u64 %0, t; }" : "=r"(a) : "l"(p));
    return a;
}
__device__ __forceinline__ unsigned lds32(uint32_t a) {
    unsigned v;
    asm volatile("ld.shared.b32 %0, [%1];" : "=r"(v) : "r"(a));
    return v;
}
__device__ __forceinline__ void sts128(uint32_t a, uint4 v) {
    asm volatile("st.shared.v4.b32 [%0], {%1, %2, %3, %4};"
                 :: "r"(a), "r"(v.x), "r"(v.y), "r"(v.z), "r"(v.w) : "memory");
}
#define CP_ASYNC16(dst, src) \
    asm volatile("cp.async.ca.shared.global [%0], [%1], 16;" :: "r"(dst), "l"(src) : "memory")
#define CP_COMMIT() asm volatile("cp.async.commit_group;" ::: "memory")
#define CP_WAIT0()  asm volatile("cp.async.wait_group 0;" ::: "memory")

__device__ __forceinline__ void mma_bf16(float& d0, float& d1, float& d2, float& d3,
                                         unsigned a0, unsigned a1, unsigned a2, unsigned a3,
                                         unsigned b0, unsigned b1) {
    asm volatile(
        "mma.sync.aligned.m16n8k16.row.col.f32.bf16.bf16.f32 "
        "{%0,%1,%2,%3}, {%4,%5,%6,%7}, {%8,%9}, {%0,%1,%2,%3};"
        : "+f"(d0), "+f"(d1), "+f"(d2), "+f"(d3)
        : "r"(a0), "r"(a1), "r"(a2), "r"(a3), "r"(b0), "r"(b1));
}
__device__ __forceinline__ void split2(float a, float b, unsigned& hi, unsigned& lo) {
    __nv_bfloat16 ah = __float2bfloat16_rn(a), bh = __float2bfloat16_rn(b);
    __nv_bfloat16 al = __float2bfloat16_rn(a - __bfloat162float(ah));
    __nv_bfloat16 bl = __float2bfloat16_rn(b - __bfloat162float(bh));
    hi = (unsigned)__bfloat16_as_ushort(ah) | ((unsigned)__bfloat16_as_ushort(bh) << 16);
    lo = (unsigned)__bfloat16_as_ushort(al) | ((unsigned)__bfloat16_as_ushort(bl) << 16);
}
__device__ __forceinline__ float elu_f(float v)   { return v > 0.f ? v : expm1f(v); }
__device__ __forceinline__ float lrelu_f(float v) { return v > 0.f ? v : 0.01f * v; }

// ---------------- smem layout (bytes) ----------------
#define AHI    0
#define ALO    10240
#define BHI    20480
#define BLO    30720
#define BUFSZ  40960
#define NODE_BIAS 81920
#define NODE_SMEM (81920 + 2048)
#define ESRC     81920
#define EDST     82432
#define EBIAS    82944
#define EATTN    83456
#define EDGE_SMEM 83968

// ---------------- small kernels ----------------
__global__ void k_embed(const int* __restrict__ node_types,
                        const float* __restrict__ embed, float* __restrict__ nf) {
    int i = blockIdx.x * 256 + threadIdx.x;
    if (i < NN * 128) {
        int n = i >> 7, c = i & 127;
        nf[(size_t)n * 128 + c] = embed[node_types[n] * 128 + c];
    }
}

__global__ void k_prep(const float* __restrict__ Wni, const float* __restrict__ Wnj,
                       const float* __restrict__ Wsrc, const float* __restrict__ bsrc,
                       const float* __restrict__ Wfij,
                       float* __restrict__ bcat,
                       __nv_bfloat16* __restrict__ btn_hi, __nv_bfloat16* __restrict__ btn_lo,
                       __nv_bfloat16* __restrict__ bte_hi, __nv_bfloat16* __restrict__ bte_lo,
                       int in_n, int in_e) {
    int i = blockIdx.x * 256 + threadIdx.x;
    int nn = 512 * in_n;
    if (i < nn) {
        int n = i / in_n, k = i - n * in_n;
        float v;
        if (n < 128)      v = Wni[k * 128 + n];
        else if (n < 256) v = Wnj[k * 128 + (n - 128)];
        else              v = Wsrc[k * 256 + (n - 256)];
        __nv_bfloat16 h = __float2bfloat16_rn(v);
        __nv_bfloat16 l = __float2bfloat16_rn(v - __bfloat162float(h));
        btn_hi[(size_t)n * in_n + k] = h;
        btn_lo[(size_t)n * in_n + k] = l;
    } else if (i < nn + 128 * in_e) {
        int j = i - nn;
        int n = j / in_e, k = j - n * in_e;
        float v = Wfij[k * 128 + n];
        __nv_bfloat16 h = __float2bfloat16_rn(v);
        __nv_bfloat16 l = __float2bfloat16_rn(v - __bfloat162float(h));
        bte_hi[(size_t)n * in_e + k] = h;
        bte_lo[(size_t)n * in_e + k] = l;
    }
    if (i < 512) bcat[i] = (i < 256) ? 0.f : bsrc[i - 256];
}

// ---------------- CSR build ----------------
__global__ void k_zero_deg(int* __restrict__ deg) {
    int i = blockIdx.x * 256 + threadIdx.x;
    if (i < NN) deg[i] = 0;
}
__global__ void k_hist(const int* __restrict__ dst, int* __restrict__ deg) {
    int e = blockIdx.x * 256 + threadIdx.x;
    if (e < EE) atomicAdd(&deg[dst[e]], 1);
}
__global__ void k_scanA(const int* __restrict__ deg, int* __restrict__ bsum) {
    __shared__ int sh[256];
    int i = blockIdx.x * 256 + threadIdx.x;
    sh[threadIdx.x] = (i < NN) ? deg[i] : 0;
    __syncthreads();
    for (int o = 128; o > 0; o >>= 1) {
        if (threadIdx.x < o) sh[threadIdx.x] += sh[threadIdx.x + o];
        __syncthreads();
    }
    if (threadIdx.x == 0) bsum[blockIdx.x] = sh[0];
}
__global__ void k_scanB(int* __restrict__ bsum) {
    __shared__ int sh[256];
    int t = threadIdx.x;
    int v = (t < NB_SCAN) ? bsum[t] : 0;
    sh[t] = v;
    __syncthreads();
    for (int o = 1; o < 256; o <<= 1) {
        int add = (t >= o) ? sh[t - o] : 0;
        __syncthreads();
        sh[t] += add;
        __syncthreads();
    }
    if (t < NB_SCAN) bsum[t] = sh[t] - v;
}
__global__ void k_scanC(const int* __restrict__ deg, const int* __restrict__ bsum,
                        int* __restrict__ offs, int* __restrict__ cursor) {
    __shared__ int sh[256];
    int i = blockIdx.x * 256 + threadIdx.x;
    int t = threadIdx.x;
    int v = (i < NN) ? deg[i] : 0;
    sh[t] = v;
    __syncthreads();
    for (int o = 1; o < 256; o <<= 1) {
        int add = (t >= o) ? sh[t - o] : 0;
        __syncthreads();
        sh[t] += add;
        __syncthreads();
    }
    if (i < NN) {
        int ex = bsum[blockIdx.x] + sh[t] - v;
        offs[i] = ex;
        cursor[i] = ex;
    }
    if (i == 0) offs[NN] = EE;
}
__global__ void k_scatter(const int* __restrict__ dst, int* __restrict__ cursor,
                          int* __restrict__ eidx) {
    int e = blockIdx.x * 256 + threadIdx.x;
    if (e < EE) {
        int pos = atomicAdd(&cursor[dst[e]], 1);
        eidx[pos] = e;
    }
}

// ---------------- pipelined GEMM mainloop (R5, unchanged) ----------------
__device__ __forceinline__ void b_cpasync(uint32_t sb, int buf,
                                          const __nv_bfloat16* __restrict__ Bth,
                                          const __nv_bfloat16* __restrict__ Btl,
                                          int n0, int K, int k0) {
    int tid = threadIdx.x;
#pragma unroll
    for (int i = 0; i < 2; i++) {
        int c = tid + i * 256;
        int n = c >> 2, k16 = c & 3;
        size_t go = (size_t)(n0 + n) * K + k0 + k16 * 8;
        uint32_t da = sb + buf * BUFSZ + BHI + n * 80 + k16 * 16;
        CP_ASYNC16(da, Bth + go);
        CP_ASYNC16(da + (BLO - BHI), Btl + go);
    }
}

__device__ __forceinline__ void a_convert_sts(uint32_t sb, int buf, int r, int hk,
                                              const float4 pa[4]) {
    uint32_t ah = sb + buf * BUFSZ + AHI + r * 80 + hk * 32;
    uint32_t al = ah + (ALO - AHI);
#pragma unroll
    for (int q = 0; q < 2; q++) {
        unsigned h0, l0, h1, l1, h2, l2, h3, l3;
        split2(pa[2 * q].x,     pa[2 * q].y,     h0, l0);
        split2(pa[2 * q].z,     pa[2 * q].w,     h1, l1);
        split2(pa[2 * q + 1].x, pa[2 * q + 1].y, h2, l2);
        split2(pa[2 * q + 1].z, pa[2 * q + 1].w, h3, l3);
        sts128(ah + q * 16, make_uint4(h0, h1, h2, h3));
        sts128(al + q * 16, make_uint4(l0, l1, l2, l3));
    }
}

__device__ __forceinline__ void mma_compute(uint32_t sb, int buf, float acc[2][8][4]) {
    int tid = threadIdx.x, lane = tid & 31, wid = tid >> 5;
    int g = lane >> 2, tig = lane & 3;
    int wm = wid & 3, wn = wid >> 2;
    uint32_t bo = sb + buf * BUFSZ;
#pragma unroll
    for (int ks = 0; ks < 2; ks++) {
        unsigned ahr[2][4], alr[2][4];
        uint32_t abase = bo + AHI + (wm * 32 + g) * 80 + ks * 32 + tig * 4;
#pragma unroll
        for (int mt = 0; mt < 2; mt++) {
            uint32_t a0 = abase + mt * (16 * 80);
            ahr[mt][0] = lds32(a0);
            ahr[mt][1] = lds32(a0 + 8 * 80);
            ahr[mt][2] = lds32(a0 + 16);
            ahr[mt][3] = lds32(a0 + 8 * 80 + 16);
            uint32_t a0l = a0 + (ALO - AHI);
            alr[mt][0] = lds32(a0l);
            alr[mt][1] = lds32(a0l + 8 * 80);
            alr[mt][2] = lds32(a0l + 16);
            alr[mt][3] = lds32(a0l + 8 * 80 + 16);
        }
        uint32_t bbase = bo + BHI + (wn * 64 + g) * 80 + ks * 32 + tig * 4;
#pragma unroll
        for (int nt = 0; nt < 8; nt++) {
            uint32_t b0a = bbase + nt * (8 * 80);
            unsigned bh0 = lds32(b0a), bh1 = lds32(b0a + 16);
            unsigned bl0 = lds32(b0a + (BLO - BHI)), bl1 = lds32(b0a + (BLO - BHI) + 16);
#pragma unroll
            for (int mt = 0; mt < 2; mt++) {
                float* d = acc[mt][nt];
                mma_bf16(d[0], d[1], d[2], d[3],
                         ahr[mt][0], ahr[mt][1], ahr[mt][2], ahr[mt][3], bh0, bh1);
                mma_bf16(d[0], d[1], d[2], d[3],
                         ahr[mt][0], ahr[mt][1], ahr[mt][2], ahr[mt][3], bl0, bl1);
                mma_bf16(d[0], d[1], d[2], d[3],
                         alr[mt][0], alr[mt][1], alr[mt][2], alr[mt][3], bh0, bh1);
            }
        }
    }
}

__device__ __forceinline__ void mma_mainloop(
    uint32_t sb, const float* __restrict__ A,
    const __nv_bfloat16* __restrict__ Bth, const __nv_bfloat16* __restrict__ Btl,
    int row0, int n0, int M, int K, float acc[2][8][4]) {
    int tid = threadIdx.x;
    int r = tid >> 1, hk = tid & 1;
    int arow = row0 + r;
    bool aval = arow < M;
    const float* abase = A + (size_t)arow * K + hk * 16;
    int nst = K >> 5;

    float4 pa[4];
    const float4 z4 = make_float4(0.f, 0.f, 0.f, 0.f);
#pragma unroll
    for (int q = 0; q < 4; q++) pa[q] = aval ? *(const float4*)(abase + q * 4) : z4;
    b_cpasync(sb, 0, Bth, Btl, n0, K, 0);
    CP_COMMIT();
    a_convert_sts(sb, 0, r, hk, pa);
    CP_WAIT0();
    __syncthreads();

    for (int s = 0; s < nst; s++) {
        int buf = s & 1, nb = buf ^ 1;
        bool more = (s + 1) < nst;
        if (more) {
            b_cpasync(sb, nb, Bth, Btl, n0, K, (s + 1) * 32);
            CP_COMMIT();
            const float* ap = abase + (s + 1) * 32;
#pragma unroll
            for (int q = 0; q < 4; q++) pa[q] = aval ? *(const float4*)(ap + q * 4) : z4;
        }
        mma_compute(sb, buf, acc);
        if (more) {
            a_convert_sts(sb, nb, r, hk, pa);
            CP_WAIT0();
        }
        __syncthreads();
    }
}

// ---------------- node GEMM: fp32 f_ni/f_nj, fp16 h_src ----------------
__global__ __launch_bounds__(256, 2) void gemm_node_mma(
    const float* __restrict__ A,
    const __nv_bfloat16* __restrict__ Bth, const __nv_bfloat16* __restrict__ Btl,
    const float* __restrict__ bias, float* __restrict__ Cout,
    __half* __restrict__ hsrc, int M, int K) {
    extern __shared__ __align__(16) char smem[];
    uint32_t sb = smem_u32(smem);
    float* bsm = (float*)(smem + NODE_BIAS);
    int tid = threadIdx.x;
    ((float2*)bsm)[tid] = ((const float2*)bias)[tid];

    int row0 = blockIdx.x * 128, n0 = blockIdx.y * 128;
    float acc[2][8][4];
#pragma unroll
    for (int mt = 0; mt < 2; mt++)
#pragma unroll
        for (int nt = 0; nt < 8; nt++)
#pragma unroll
            for (int q = 0; q < 4; q++) acc[mt][nt][q] = 0.f;

    mma_mainloop(sb, A, Bth, Btl, row0, n0, M, K, acc);

    int lane = tid & 31, wid = tid >> 5;
    int g = lane >> 2, tig = lane & 3;
    int wm = wid & 3, wn = wid >> 2;
    bool to_half = n0 >= 256;
#pragma unroll
    for (int mt = 0; mt < 2; mt++) {
        int r0 = row0 + wm * 32 + mt * 16 + g;
#pragma unroll
        for (int nt = 0; nt < 8; nt++) {
            int cc = n0 + wn * 64 + nt * 8 + 2 * tig;
            float b0 = bsm[cc], b1 = bsm[cc + 1];
            float* d = acc[mt][nt];
            if (to_half) {
                int hc = cc - 256;
                if (r0 < M)
                    *(__half2*)(hsrc + (size_t)r0 * 256 + hc) =
                        __floats2half2_rn(d[0] + b0, d[1] + b1);
                if (r0 + 8 < M)
                    *(__half2*)(hsrc + (size_t)(r0 + 8) * 256 + hc) =
                        __floats2half2_rn(d[2] + b0, d[3] + b1);
            } else {
                if (r0 < M)
                    *(float2*)(Cout + (size_t)r0 * 256 + cc) = make_float2(d[0] + b0, d[1] + b1);
                if (r0 + 8 < M)
                    *(float2*)(Cout + (size_t)(r0 + 8) * 256 + cc) = make_float2(d[2] + b0, d[3] + b1);
            }
        }
    }
}

// ---------------- edge GEMM: direct-from-fragment fused epilogue ----------------
__global__ __launch_bounds__(256, 2) void gemm_edge_mma(
    const float* __restrict__ A,
    const __nv_bfloat16* __restrict__ Bth, const __nv_bfloat16* __restrict__ Btl,
    const float* __restrict__ node_out,
    const int* __restrict__ src, const int* __restrict__ dst,
    const float* __restrict__ bias, const float* __restrict__ attn,
    float* __restrict__ ef_out, float* __restrict__ elog, int M, int K) {
    extern __shared__ __align__(16) char smem[];
    uint32_t sb = smem_u32(smem);
    int*   ssh = (int*)(smem + ESRC);
    int*   dsh = (int*)(smem + EDST);
    float* bsh = (float*)(smem + EBIAS);
    float* ash = (float*)(smem + EATTN);

    int tid = threadIdx.x;
    int e0 = blockIdx.x * 128;
    if (tid < 128) {
        int e = e0 + tid;
        ssh[tid] = (e < M) ? src[e] : 0;
        dsh[tid] = (e < M) ? dst[e] : 0;
        bsh[tid] = bias[tid];
        ash[tid] = attn[tid];
    }

    float acc[2][8][4];
#pragma unroll
    for (int mt = 0; mt < 2; mt++)
#pragma unroll
        for (int nt = 0; nt < 8; nt++)
#pragma unroll
            for (int q = 0; q < 4; q++) acc[mt][nt][q] = 0.f;

    mma_mainloop(sb, A, Bth, Btl, e0, 0, M, K, acc);

    int lane = tid & 31, wid = tid >> 5;
    int g = lane >> 2, tig = lane & 3;
    int wm = wid & 3, wn = wid >> 2;

#pragma unroll
    for (int mt = 0; mt < 2; mt++) {
        int r = wm * 32 + mt * 16 + g;
        int rA = r, rB = r + 8;
        int eA = e0 + rA, eB = e0 + rB;
        int siA = ssh[rA], djA = dsh[rA];
        int siB = ssh[rB], djB = dsh[rB];
        const float* niA = node_out + (size_t)siA * 256;
        const float* njA = node_out + (size_t)djA * 256 + 128;
        const float* niB = node_out + (size_t)siB * 256;
        const float* njB = node_out + (size_t)djB * 256 + 128;
        float partA[2] = {0.f, 0.f};
        float partB[2] = {0.f, 0.f};
#pragma unroll
        for (int nt = 0; nt < 8; nt++) {
            int cc = wn * 64 + nt * 8 + 2 * tig;
            int hl = nt >> 2;
            float b0 = bsh[cc], b1 = bsh[cc + 1];
            float a0 = ash[cc], a1 = ash[cc + 1];
            float2 nA0 = *(const float2*)(niA + cc);
            float2 nA1 = *(const float2*)(njA + cc);
            float2 nB0 = *(const float2*)(niB + cc);
            float2 nB1 = *(const float2*)(njB + cc);
            float* d = acc[mt][nt];
            float v0 = lrelu_f(d[0] + nA0.x + nA1.x + b0);
            float v1 = lrelu_f(d[1] + nA0.y + nA1.y + b1);
            partA[hl] += v0 * a0 + v1 * a1;
            if (eA < M)
                *(float2*)(ef_out + (size_t)eA * 128 + cc) = make_float2(elu_f(v0), elu_f(v1));
            float w0 = lrelu_f(d[2] + nB0.x + nB1.x + b0);
            float w1 = lrelu_f(d[3] + nB0.y + nB1.y + b1);
            partB[hl] += w0 * a0 + w1 * a1;
            if (eB < M)
                *(float2*)(ef_out + (size_t)eB * 128 + cc) = make_float2(elu_f(w0), elu_f(w1));
        }
#pragma unroll
        for (int o = 1; o <= 2; o <<= 1) {
            partA[0] += __shfl_xor_sync(0xFFFFFFFFu, partA[0], o);
            partA[1] += __shfl_xor_sync(0xFFFFFFFFu, partA[1], o);
            partB[0] += __shfl_xor_sync(0xFFFFFFFFu, partB[0], o);
            partB[1] += __shfl_xor_sync(0xFFFFFFFFu, partB[1], o);
        }
        if (tig == 0) {
            int h0 = wn * 2, h1 = wn * 2 + 1;
            if (eA < M) {
                elog[(size_t)eA * 4 + h0] = partA[0];
                elog[(size_t)eA * 4 + h1] = partA[1];
            }
            if (eB < M) {
                elog[(size_t)eB * 4 + h0] = partB[0];
                elog[(size_t)eB * 4 + h1] = partB[1];
            }
        }
    }
}

// ---------------- CSR aggregation (fp16 h_src gather) ----------------
__global__ __launch_bounds__(256) void k_aggr(
    const int* __restrict__ srcs, const int* __restrict__ eidx,
    const int* __restrict__ offs, const float* __restrict__ elog,
    const __half* __restrict__ hsrc, float* __restrict__ outp) {
    int node = (blockIdx.x * 256 + threadIdx.x) >> 5;
    int lane = threadIdx.x & 31;
    if (node >= NN) return;
    int beg = offs[node], end = offs[node + 1];

    float4 mx = make_float4(-1e30f, -1e30f, -1e30f, -1e30f);
    for (int j = beg + lane; j < end; j += 32) {
        int e = eidx[j];
        float4 l = *(const float4*)(elog + (size_t)e * 4);
        mx.x = fmaxf(mx.x, l.x); mx.y = fmaxf(mx.y, l.y);
        mx.z = fmaxf(mx.z, l.z); mx.w = fmaxf(mx.w, l.w);
    }
#pragma unroll
    for (int o = 16; o > 0; o >>= 1) {
        mx.x = fmaxf(mx.x, __shfl_xor_sync(0xFFFFFFFFu, mx.x, o));
        mx.y = fmaxf(mx.y, __shfl_xor_sync(0xFFFFFFFFu, mx.y, o));
        mx.z = fmaxf(mx.z, __shfl_xor_sync(0xFFFFFFFFu, mx.z, o));
        mx.w = fmaxf(mx.w, __shfl_xor_sync(0xFFFFFFFFu, mx.w, o));
    }
    int h = lane >> 3;
    float mh = (h == 0) ? mx.x : (h == 1) ? mx.y : (h == 2) ? mx.z : mx.w;

    float acc[8] = {0.f, 0.f, 0.f, 0.f, 0.f, 0.f, 0.f, 0.f};
    float ssum = 0.f;
    int j = beg;
    for (; j + 1 < end; j += 2) {
        int ea = eidx[j], eb = eidx[j + 1];
        int sa = srcs[ea], sbn = srcs[eb];
        float la = elog[(size_t)ea * 4 + h], lb = elog[(size_t)eb * 4 + h];
        uint4 ra = *((const uint4*)(hsrc + (size_t)sa * 256) + lane);
        uint4 rb = *((const uint4*)(hsrc + (size_t)sbn * 256) + lane);
        float wa = expf(la - mh), wb = expf(lb - mh);
        ssum += wa + wb;
        float2 t;
        t = __half22float2(*(__half2*)&ra.x); acc[0] += wa * t.x; acc[1] += wa * t.y;
        t = __half22float2(*(__half2*)&ra.y); acc[2] += wa * t.x; acc[3] += wa * t.y;
        t = __half22float2(*(__half2*)&ra.z); acc[4] += wa * t.x; acc[5] += wa * t.y;
        t = __half22float2(*(__half2*)&ra.w); acc[6] += wa * t.x; acc[7] += wa * t.y;
        t = __half22float2(*(__half2*)&rb.x); acc[0] += wb * t.x; acc[1] += wb * t.y;
        t = __half22float2(*(__half2*)&rb.y); acc[2] += wb * t.x; acc[3] += wb * t.y;
        t = __half22float2(*(__half2*)&rb.z); acc[4] += wb * t.x; acc[5] += wb * t.y;
        t = __half22float2(*(__half2*)&rb.w); acc[6] += wb * t.x; acc[7] += wb * t.y;
    }
    if (j < end) {
        int e = eidx[j];
        float w = expf(elog[(size_t)e * 4 + h] - mh);
        ssum += w;
        uint4 ra = *((const uint4*)(hsrc + (size_t)srcs[e] * 256) + lane);
        float2 t;
        t = __half22float2(*(__half2*)&ra.x); acc[0] += w * t.x; acc[1] += w * t.y;
        t = __half22float2(*(__half2*)&ra.y); acc[2] += w * t.x; acc[3] += w * t.y;
        t = __half22float2(*(__half2*)&ra.z); acc[4] += w * t.x; acc[5] += w * t.y;
        t = __half22float2(*(__half2*)&ra.w); acc[6] += w * t.x; acc[7] += w * t.y;
    }
    float inv = (end > beg) ? 1.f / ssum : 0.f;
    float* op = outp + (size_t)node * 256 + lane * 8;
    float4 o0, o1;
    o0.x = elu_f(acc[0] * inv); o0.y = elu_f(acc[1] * inv);
    o0.z = elu_f(acc[2] * inv); o0.w = elu_f(acc[3] * inv);
    o1.x = elu_f(acc[4] * inv); o1.y = elu_f(acc[5] * inv);
    o1.z = elu_f(acc[6] * inv); o1.w = elu_f(acc[7] * inv);
    *(float4*)op = o0;
    *(float4*)(op + 4) = o1;
}

// ---------------- host ----------------
extern "C" void kernel_launch(void* const* d_in, const int* in_sizes, int n_in,
                              void* d_out, int out_size) {
    const int*   node_types = (const int*)d_in[0];
    const int*   src        = (const int*)d_in[1];
    const int*   dst        = (const int*)d_in[2];
    const float* efeats     = (const float*)d_in[3];
    const float* embed      = (const float*)d_in[4];
    const float* W_src[2] = {(const float*)d_in[5],  (const float*)d_in[12]};
    const float* b_src[2] = {(const float*)d_in[6],  (const float*)d_in[13]};
    const float* W_ni[2]  = {(const float*)d_in[7],  (const float*)d_in[14]};
    const float* W_nj[2]  = {(const float*)d_in[8],  (const float*)d_in[15]};
    const float* W_fij[2] = {(const float*)d_in[9],  (const float*)d_in[16]};
    const float* attn[2]  = {(const float*)d_in[10], (const float*)d_in[17]};
    const float* bias[2]  = {(const float*)d_in[11], (const float*)d_in[18]};

    float *nf, *node_out, *efbuf, *elog, *bcat;
    __half* hsrc;
    int *deg, *offs, *cursor, *eidx, *bsum;
    __nv_bfloat16 *btnh, *btnl, *bteh, *btel;
    cudaGetSymbolAddress((void**)&nf, g_nf);
    cudaGetSymbolAddress((void**)&node_out, g_node_out);
    cudaGetSymbolAddress((void**)&hsrc, g_hsrc);
    cudaGetSymbolAddress((void**)&efbuf, g_efbuf);
    cudaGetSymbolAddress((void**)&elog, g_elog);
    cudaGetSymbolAddress((void**)&bcat, g_bcat);
    cudaGetSymbolAddress((void**)&btnh, g_btn_hi);
    cudaGetSymbolAddress((void**)&btnl, g_btn_lo);
    cudaGetSymbolAddress((void**)&bteh, g_bte_hi);
    cudaGetSymbolAddress((void**)&btel, g_bte_lo);
    cudaGetSymbolAddress((void**)&deg, g_deg);
    cudaGetSymbolAddress((void**)&offs, g_offs);
    cudaGetSymbolAddress((void**)&cursor, g_cursor);
    cudaGetSymbolAddress((void**)&eidx, g_eidx);
    cudaGetSymbolAddress((void**)&bsum, g_bsum);

    cudaFuncSetAttribute(gemm_node_mma, cudaFuncAttributeMaxDynamicSharedMemorySize, NODE_SMEM);
    cudaFuncSetAttribute(gemm_edge_mma, cudaFuncAttributeMaxDynamicSharedMemorySize, EDGE_SMEM);

    float* out_nf = (float*)d_out;
    float* out_ef = out_nf + (size_t)NN * 256;

    k_embed<<<(NN * 128 + 255) / 256, 256>>>(node_types, embed, nf);

    // CSR by dst (edges identical across layers)
    k_zero_deg<<<NB_SCAN, 256>>>(deg);
    k_hist<<<(EE + 255) / 256, 256>>>(dst, deg);
    k_scanA<<<NB_SCAN, 256>>>(deg, bsum);
    k_scanB<<<1, 256>>>(bsum);
    k_scanC<<<NB_SCAN, 256>>>(deg, bsum, offs, cursor);
    k_scatter<<<(EE + 255) / 256, 256>>>(dst, cursor, eidx);

    const float* ef_in = efeats;
    for (int L = 0; L < 2; L++) {
        int in_n = L ? 256 : 128;
        int in_e = L ? 128 : 64;
        int prep_items = 512 * in_n + 128 * in_e;
        k_prep<<<(prep_items + 255) / 256, 256>>>(W_ni[L], W_nj[L], W_src[L], b_src[L],
                                                  W_fij[L], bcat, btnh, btnl, bteh, btel,
                                                  in_n, in_e);

        dim3 gn((NN + 127) / 128, 4);
        gemm_node_mma<<<gn, 256, NODE_SMEM>>>(nf, btnh, btnl, bcat, node_out, hsrc, NN, in_n);

        float* ef_out = L ? out_ef : efbuf;
        gemm_edge_mma<<<(EE + 127) / 128, 256, EDGE_SMEM>>>(ef_in, bteh, btel, node_out,
                                                            src, dst, bias[L], attn[L],
                                                            ef_out, elog, EE, in_e);

        float* nf_out = L ? out_nf : nf;
        k_aggr<<<(NN * 32 + 255) / 256, 256>>>(src, eidx, offs, elog, hsrc, nf_out);
        ef_in = ef_out;
    }
}

// round 12
// speedup vs baseline: 1.5150x; 1.0573x over previous
#include <cuda_runtime.h>
#include <cuda_bf16.h>
#include <cuda_fp16.h>
#include <math.h>
#include <stdint.h>

#define NN 50000
#define EE 500000
#define NB_SCAN ((NN + 255) / 256)   // 196

// ---------------- scratch ----------------
__device__ float    g_nf[(size_t)NN * 256];
__device__ float    g_node_out[(size_t)NN * 256];  // [f_ni(128) | f_nj(128)] fp32
__device__ __half   g_hsrc[(size_t)NN * 256];      // h_src in fp16
__device__ float    g_efbuf[(size_t)EE * 128];
__device__ float    g_elog[(size_t)EE * 4];        // raw attention logits
__device__ float    g_bcat[512];
__device__ __nv_bfloat16 g_btn_hi[512 * 256];
__device__ __nv_bfloat16 g_btn_lo[512 * 256];
__device__ __nv_bfloat16 g_bte_hi[128 * 128];
__device__ __nv_bfloat16 g_bte_lo[128 * 128];
// CSR by dst
__device__ int g_deg[NN];
__device__ int g_offs[NN + 1];
__device__ int g_cursor[NN];
__device__ int g_eidx[EE];
__device__ int g_bsum[256];

// ---------------- helpers ----------------
__device__ __forceinline__ uint32_t smem_u32(const void* p) {
    uint32_t a;
    asm("{ .reg .u64 t; cvta.to.shared.u64 t, %1; cvt.u32.u64 %0, t; }" : "=r"(a) : "l"(p));
    return a;
}
__device__ __forceinline__ void sts128(uint32_t a, uint4 v) {
    asm volatile("st.shared.v4.b32 [%0], {%1, %2, %3, %4};"
                 :: "r"(a), "r"(v.x), "r"(v.y), "r"(v.z), "r"(v.w) : "memory");
}
__device__ __forceinline__ void ldsm_x4(unsigned& r0, unsigned& r1, unsigned& r2,
                                        unsigned& r3, uint32_t addr) {
    asm volatile("ldmatrix.sync.aligned.m8n8.x4.shared.b16 {%0,%1,%2,%3}, [%4];"
                 : "=r"(r0), "=r"(r1), "=r"(r2), "=r"(r3) : "r"(addr));
}
#define CP_ASYNC16(dst, src) \
    asm volatile("cp.async.ca.shared.global [%0], [%1], 16;" :: "r"(dst), "l"(src) : "memory")
#define CP_COMMIT() asm volatile("cp.async.commit_group;" ::: "memory")
#define CP_WAIT0()  asm volatile("cp.async.wait_group 0;" ::: "memory")

__device__ __forceinline__ void mma_bf16(float& d0, float& d1, float& d2, float& d3,
                                         unsigned a0, unsigned a1, unsigned a2, unsigned a3,
                                         unsigned b0, unsigned b1) {
    asm volatile(
        "mma.sync.aligned.m16n8k16.row.col.f32.bf16.bf16.f32 "
        "{%0,%1,%2,%3}, {%4,%5,%6,%7}, {%8,%9}, {%0,%1,%2,%3};"
        : "+f"(d0), "+f"(d1), "+f"(d2), "+f"(d3)
        : "r"(a0), "r"(a1), "r"(a2), "r"(a3), "r"(b0), "r"(b1));
}
__device__ __forceinline__ void split2(float a, float b, unsigned& hi, unsigned& lo) {
    __nv_bfloat16 ah = __float2bfloat16_rn(a), bh = __float2bfloat16_rn(b);
    __nv_bfloat16 al = __float2bfloat16_rn(a - __bfloat162float(ah));
    __nv_bfloat16 bl = __float2bfloat16_rn(b - __bfloat162float(bh));
    hi = (unsigned)__bfloat16_as_ushort(ah) | ((unsigned)__bfloat16_as_ushort(bh) << 16);
    lo = (unsigned)__bfloat16_as_ushort(al) | ((unsigned)__bfloat16_as_ushort(bl) << 16);
}
__device__ __forceinline__ float elu_f(float v)   { return v > 0.f ? v : expm1f(v); }
__device__ __forceinline__ float lrelu_f(float v) { return v > 0.f ? v : 0.01f * v; }

// ---------------- smem layout (bytes) ----------------
#define AHI    0
#define ALO    10240
#define BHI    20480
#define BLO    30720
#define BUFSZ  40960
#define NODE_BIAS 81920
#define NODE_SMEM (81920 + 2048)
#define ESRC     81920
#define EDST     82432
#define EBIAS    82944
#define EATTN    83456
#define EDGE_SMEM 83968

// ---------------- small kernels ----------------
__global__ void k_embed(const int* __restrict__ node_types,
                        const float* __restrict__ embed, float* __restrict__ nf) {
    int i = blockIdx.x * 256 + threadIdx.x;
    if (i < NN * 128) {
        int n = i >> 7, c = i & 127;
        nf[(size_t)n * 128 + c] = embed[node_types[n] * 128 + c];
    }
}

__global__ void k_prep(const float* __restrict__ Wni, const float* __restrict__ Wnj,
                       const float* __restrict__ Wsrc, const float* __restrict__ bsrc,
                       const float* __restrict__ Wfij,
                       float* __restrict__ bcat,
                       __nv_bfloat16* __restrict__ btn_hi, __nv_bfloat16* __restrict__ btn_lo,
                       __nv_bfloat16* __restrict__ bte_hi, __nv_bfloat16* __restrict__ bte_lo,
                       int in_n, int in_e) {
    int i = blockIdx.x * 256 + threadIdx.x;
    int nn = 512 * in_n;
    if (i < nn) {
        int n = i / in_n, k = i - n * in_n;
        float v;
        if (n < 128)      v = Wni[k * 128 + n];
        else if (n < 256) v = Wnj[k * 128 + (n - 128)];
        else              v = Wsrc[k * 256 + (n - 256)];
        __nv_bfloat16 h = __float2bfloat16_rn(v);
        __nv_bfloat16 l = __float2bfloat16_rn(v - __bfloat162float(h));
        btn_hi[(size_t)n * in_n + k] = h;
        btn_lo[(size_t)n * in_n + k] = l;
    } else if (i < nn + 128 * in_e) {
        int j = i - nn;
        int n = j / in_e, k = j - n * in_e;
        float v = Wfij[k * 128 + n];
        __nv_bfloat16 h = __float2bfloat16_rn(v);
        __nv_bfloat16 l = __float2bfloat16_rn(v - __bfloat162float(h));
        bte_hi[(size_t)n * in_e + k] = h;
        bte_lo[(size_t)n * in_e + k] = l;
    }
    if (i < 512) bcat[i] = (i < 256) ? 0.f : bsrc[i - 256];
}

// ---------------- CSR build ----------------
__global__ void k_zero_deg(int* __restrict__ deg) {
    int i = blockIdx.x * 256 + threadIdx.x;
    if (i < NN) deg[i] = 0;
}
__global__ void k_hist(const int* __restrict__ dst, int* __restrict__ deg) {
    int e = blockIdx.x * 256 + threadIdx.x;
    if (e < EE) atomicAdd(&deg[dst[e]], 1);
}
__global__ void k_scanA(const int* __restrict__ deg, int* __restrict__ bsum) {
    __shared__ int sh[256];
    int i = blockIdx.x * 256 + threadIdx.x;
    sh[threadIdx.x] = (i < NN) ? deg[i] : 0;
    __syncthreads();
    for (int o = 128; o > 0; o >>= 1) {
        if (threadIdx.x < o) sh[threadIdx.x] += sh[threadIdx.x + o];
        __syncthreads();
    }
    if (threadIdx.x == 0) bsum[blockIdx.x] = sh[0];
}
__global__ void k_scanB(int* __restrict__ bsum) {
    __shared__ int sh[256];
    int t = threadIdx.x;
    int v = (t < NB_SCAN) ? bsum[t] : 0;
    sh[t] = v;
    __syncthreads();
    for (int o = 1; o < 256; o <<= 1) {
        int add = (t >= o) ? sh[t - o] : 0;
        __syncthreads();
        sh[t] += add;
        __syncthreads();
    }
    if (t < NB_SCAN) bsum[t] = sh[t] - v;
}
__global__ void k_scanC(const int* __restrict__ deg, const int* __restrict__ bsum,
                        int* __restrict__ offs, int* __restrict__ cursor) {
    __shared__ int sh[256];
    int i = blockIdx.x * 256 + threadIdx.x;
    int t = threadIdx.x;
    int v = (i < NN) ? deg[i] : 0;
    sh[t] = v;
    __syncthreads();
    for (int o = 1; o < 256; o <<= 1) {
        int add = (t >= o) ? sh[t - o] : 0;
        __syncthreads();
        sh[t] += add;
        __syncthreads();
    }
    if (i < NN) {
        int ex = bsum[blockIdx.x] + sh[t] - v;
        offs[i] = ex;
        cursor[i] = ex;
    }
    if (i == 0) offs[NN] = EE;
}
__global__ void k_scatter(const int* __restrict__ dst, int* __restrict__ cursor,
                          int* __restrict__ eidx) {
    int e = blockIdx.x * 256 + threadIdx.x;
    if (e < EE) {
        int pos = atomicAdd(&cursor[dst[e]], 1);
        eidx[pos] = e;
    }
}

// ---------------- pipelined GEMM mainloop (ldmatrix fragment loads) ----------------
__device__ __forceinline__ void b_cpasync(uint32_t sb, int buf,
                                          const __nv_bfloat16* __restrict__ Bth,
                                          const __nv_bfloat16* __restrict__ Btl,
                                          int n0, int K, int k0) {
    int tid = threadIdx.x;
#pragma unroll
    for (int i = 0; i < 2; i++) {
        int c = tid + i * 256;
        int n = c >> 2, k16 = c & 3;
        size_t go = (size_t)(n0 + n) * K + k0 + k16 * 8;
        uint32_t da = sb + buf * BUFSZ + BHI + n * 80 + k16 * 16;
        CP_ASYNC16(da, Bth + go);
        CP_ASYNC16(da + (BLO - BHI), Btl + go);
    }
}

__device__ __forceinline__ void a_convert_sts(uint32_t sb, int buf, int r, int hk,
                                              const float4 pa[4]) {
    uint32_t ah = sb + buf * BUFSZ + AHI + r * 80 + hk * 32;
    uint32_t al = ah + (ALO - AHI);
#pragma unroll
    for (int q = 0; q < 2; q++) {
        unsigned h0, l0, h1, l1, h2, l2, h3, l3;
        split2(pa[2 * q].x,     pa[2 * q].y,     h0, l0);
        split2(pa[2 * q].z,     pa[2 * q].w,     h1, l1);
        split2(pa[2 * q + 1].x, pa[2 * q + 1].y, h2, l2);
        split2(pa[2 * q + 1].z, pa[2 * q + 1].w, h3, l3);
        sts128(ah + q * 16, make_uint4(h0, h1, h2, h3));
        sts128(al + q * 16, make_uint4(l0, l1, l2, l3));
    }
}

__device__ __forceinline__ void mma_compute(uint32_t sb, int buf, float acc[2][8][4]) {
    int tid = threadIdx.x, lane = tid & 31, wid = tid >> 5;
    int wm = wid & 3, wn = wid >> 2;
    uint32_t bo = sb + buf * BUFSZ;
    // ldmatrix per-lane addresses on the SAME 80B-stride layout:
    // A x4: m0=rows0-7/k0-7, m1=rows8-15/k0-7, m2=rows0-7/k8-15, m3=rows8-15/k8-15
    uint32_t aAddr = bo + AHI + (wm * 32 + (lane & 15)) * 80 + ((lane & 16) ? 16 : 0);
    // B x4 (covers nt pair p): m0=rows(p*16+0..7)/k0-7, m1=same rows/k8-15,
    //                          m2=rows+8/k0-7, m3=rows+8/k8-15
    uint32_t bAddr = bo + BHI + (wn * 64 + ((lane & 16) ? 8 : 0) + (lane & 7)) * 80 +
                     ((lane & 8) ? 16 : 0);
#pragma unroll
    for (int ks = 0; ks < 2; ks++) {
        unsigned ahr[2][4], alr[2][4];
#pragma unroll
        for (int mt = 0; mt < 2; mt++) {
            uint32_t aa = aAddr + mt * 1280 + ks * 32;
            ldsm_x4(ahr[mt][0], ahr[mt][1], ahr[mt][2], ahr[mt][3], aa);
            ldsm_x4(alr[mt][0], alr[mt][1], alr[mt][2], alr[mt][3], aa + (ALO - AHI));
        }
#pragma unroll
        for (int p = 0; p < 4; p++) {
            uint32_t ba = bAddr + p * 1280 + ks * 32;
            unsigned bh[4], bl[4];
            ldsm_x4(bh[0], bh[1], bh[2], bh[3], ba);
            ldsm_x4(bl[0], bl[1], bl[2], bl[3], ba + (BLO - BHI));
#pragma unroll
            for (int sub = 0; sub < 2; sub++) {
                int nt = p * 2 + sub;
                unsigned bh0 = bh[sub * 2], bh1 = bh[sub * 2 + 1];
                unsigned bl0 = bl[sub * 2], bl1 = bl[sub * 2 + 1];
#pragma unroll
                for (int mt = 0; mt < 2; mt++) {
                    float* d = acc[mt][nt];
                    mma_bf16(d[0], d[1], d[2], d[3],
                             ahr[mt][0], ahr[mt][1], ahr[mt][2], ahr[mt][3], bh0, bh1);
                    mma_bf16(d[0], d[1], d[2], d[3],
                             ahr[mt][0], ahr[mt][1], ahr[mt][2], ahr[mt][3], bl0, bl1);
                    mma_bf16(d[0], d[1], d[2], d[3],
                             alr[mt][0], alr[mt][1], alr[mt][2], alr[mt][3], bh0, bh1);
                }
            }
        }
    }
}

__device__ __forceinline__ void mma_mainloop(
    uint32_t sb, const float* __restrict__ A,
    const __nv_bfloat16* __restrict__ Bth, const __nv_bfloat16* __restrict__ Btl,
    int row0, int n0, int M, int K, float acc[2][8][4]) {
    int tid = threadIdx.x;
    int r = tid >> 1, hk = tid & 1;
    int arow = row0 + r;
    bool aval = arow < M;
    const float* abase = A + (size_t)arow * K + hk * 16;
    int nst = K >> 5;

    float4 pa[4];
    const float4 z4 = make_float4(0.f, 0.f, 0.f, 0.f);
#pragma unroll
    for (int q = 0; q < 4; q++) pa[q] = aval ? *(const float4*)(abase + q * 4) : z4;
    b_cpasync(sb, 0, Bth, Btl, n0, K, 0);
    CP_COMMIT();
    a_convert_sts(sb, 0, r, hk, pa);
    CP_WAIT0();
    __syncthreads();

    for (int s = 0; s < nst; s++) {
        int buf = s & 1, nb = buf ^ 1;
        bool more = (s + 1) < nst;
        if (more) {
            b_cpasync(sb, nb, Bth, Btl, n0, K, (s + 1) * 32);
            CP_COMMIT();
            const float* ap = abase + (s + 1) * 32;
#pragma unroll
            for (int q = 0; q < 4; q++) pa[q] = aval ? *(const float4*)(ap + q * 4) : z4;
        }
        mma_compute(sb, buf, acc);
        if (more) {
            a_convert_sts(sb, nb, r, hk, pa);
            CP_WAIT0();
        }
        __syncthreads();
    }
}

// ---------------- node GEMM: fp32 f_ni/f_nj, fp16 h_src ----------------
__global__ __launch_bounds__(256, 2) void gemm_node_mma(
    const float* __restrict__ A,
    const __nv_bfloat16* __restrict__ Bth, const __nv_bfloat16* __restrict__ Btl,
    const float* __restrict__ bias, float* __restrict__ Cout,
    __half* __restrict__ hsrc, int M, int K) {
    extern __shared__ __align__(16) char smem[];
    uint32_t sb = smem_u32(smem);
    float* bsm = (float*)(smem + NODE_BIAS);
    int tid = threadIdx.x;
    ((float2*)bsm)[tid] = ((const float2*)bias)[tid];

    int row0 = blockIdx.x * 128, n0 = blockIdx.y * 128;
    float acc[2][8][4];
#pragma unroll
    for (int mt = 0; mt < 2; mt++)
#pragma unroll
        for (int nt = 0; nt < 8; nt++)
#pragma unroll
            for (int q = 0; q < 4; q++) acc[mt][nt][q] = 0.f;

    mma_mainloop(sb, A, Bth, Btl, row0, n0, M, K, acc);

    int lane = tid & 31, wid = tid >> 5;
    int g = lane >> 2, tig = lane & 3;
    int wm = wid & 3, wn = wid >> 2;
    bool to_half = n0 >= 256;
#pragma unroll
    for (int mt = 0; mt < 2; mt++) {
        int r0 = row0 + wm * 32 + mt * 16 + g;
#pragma unroll
        for (int nt = 0; nt < 8; nt++) {
            int cc = n0 + wn * 64 + nt * 8 + 2 * tig;
            float b0 = bsm[cc], b1 = bsm[cc + 1];
            float* d = acc[mt][nt];
            if (to_half) {
                int hc = cc - 256;
                if (r0 < M)
                    *(__half2*)(hsrc + (size_t)r0 * 256 + hc) =
                        __floats2half2_rn(d[0] + b0, d[1] + b1);
                if (r0 + 8 < M)
                    *(__half2*)(hsrc + (size_t)(r0 + 8) * 256 + hc) =
                        __floats2half2_rn(d[2] + b0, d[3] + b1);
            } else {
                if (r0 < M)
                    *(float2*)(Cout + (size_t)r0 * 256 + cc) = make_float2(d[0] + b0, d[1] + b1);
                if (r0 + 8 < M)
                    *(float2*)(Cout + (size_t)(r0 + 8) * 256 + cc) = make_float2(d[2] + b0, d[3] + b1);
            }
        }
    }
}

// ---------------- edge GEMM: direct-from-fragment fused epilogue ----------------
__global__ __launch_bounds__(256, 2) void gemm_edge_mma(
    const float* __restrict__ A,
    const __nv_bfloat16* __restrict__ Bth, const __nv_bfloat16* __restrict__ Btl,
    const float* __restrict__ node_out,
    const int* __restrict__ src, const int* __restrict__ dst,
    const float* __restrict__ bias, const float* __restrict__ attn,
    float* __restrict__ ef_out, float* __restrict__ elog, int M, int K) {
    extern __shared__ __align__(16) char smem[];
    uint32_t sb = smem_u32(smem);
    int*   ssh = (int*)(smem + ESRC);
    int*   dsh = (int*)(smem + EDST);
    float* bsh = (float*)(smem + EBIAS);
    float* ash = (float*)(smem + EATTN);

    int tid = threadIdx.x;
    int e0 = blockIdx.x * 128;
    if (tid < 128) {
        int e = e0 + tid;
        ssh[tid] = (e < M) ? src[e] : 0;
        dsh[tid] = (e < M) ? dst[e] : 0;
        bsh[tid] = bias[tid];
        ash[tid] = attn[tid];
    }

    float acc[2][8][4];
#pragma unroll
    for (int mt = 0; mt < 2; mt++)
#pragma unroll
        for (int nt = 0; nt < 8; nt++)
#pragma unroll
            for (int q = 0; q < 4; q++) acc[mt][nt][q] = 0.f;

    mma_mainloop(sb, A, Bth, Btl, e0, 0, M, K, acc);

    int lane = tid & 31, wid = tid >> 5;
    int g = lane >> 2, tig = lane & 3;
    int wm = wid & 3, wn = wid >> 2;

#pragma unroll
    for (int mt = 0; mt < 2; mt++) {
        int r = wm * 32 + mt * 16 + g;
        int rA = r, rB = r + 8;
        int eA = e0 + rA, eB = e0 + rB;
        int siA = ssh[rA], djA = dsh[rA];
        int siB = ssh[rB], djB = dsh[rB];
        const float* niA = node_out + (size_t)siA * 256;
        const float* njA = node_out + (size_t)djA * 256 + 128;
        const float* niB = node_out + (size_t)siB * 256;
        const float* njB = node_out + (size_t)djB * 256 + 128;
        float partA[2] = {0.f, 0.f};
        float partB[2] = {0.f, 0.f};
#pragma unroll
        for (int nt = 0; nt < 8; nt++) {
            int cc = wn * 64 + nt * 8 + 2 * tig;
            int hl = nt >> 2;
            float b0 = bsh[cc], b1 = bsh[cc + 1];
            float a0 = ash[cc], a1 = ash[cc + 1];
            float2 nA0 = *(const float2*)(niA + cc);
            float2 nA1 = *(const float2*)(njA + cc);
            float2 nB0 = *(const float2*)(niB + cc);
            float2 nB1 = *(const float2*)(njB + cc);
            float* d = acc[mt][nt];
            float v0 = lrelu_f(d[0] + nA0.x + nA1.x + b0);
            float v1 = lrelu_f(d[1] + nA0.y + nA1.y + b1);
            partA[hl] += v0 * a0 + v1 * a1;
            if (eA < M)
                *(float2*)(ef_out + (size_t)eA * 128 + cc) = make_float2(elu_f(v0), elu_f(v1));
            float w0 = lrelu_f(d[2] + nB0.x + nB1.x + b0);
            float w1 = lrelu_f(d[3] + nB0.y + nB1.y + b1);
            partB[hl] += w0 * a0 + w1 * a1;
            if (eB < M)
                *(float2*)(ef_out + (size_t)eB * 128 + cc) = make_float2(elu_f(w0), elu_f(w1));
        }
#pragma unroll
        for (int o = 1; o <= 2; o <<= 1) {
            partA[0] += __shfl_xor_sync(0xFFFFFFFFu, partA[0], o);
            partA[1] += __shfl_xor_sync(0xFFFFFFFFu, partA[1], o);
            partB[0] += __shfl_xor_sync(0xFFFFFFFFu, partB[0], o);
            partB[1] += __shfl_xor_sync(0xFFFFFFFFu, partB[1], o);
        }
        if (tig == 0) {
            int h0 = wn * 2, h1 = wn * 2 + 1;
            if (eA < M) {
                elog[(size_t)eA * 4 + h0] = partA[0];
                elog[(size_t)eA * 4 + h1] = partA[1];
            }
            if (eB < M) {
                elog[(size_t)eB * 4 + h0] = partB[0];
                elog[(size_t)eB * 4 + h1] = partB[1];
            }
        }
    }
}

// ---------------- CSR aggregation (fp16 h_src gather) ----------------
__global__ __launch_bounds__(256) void k_aggr(
    const int* __restrict__ srcs, const int* __restrict__ eidx,
    const int* __restrict__ offs, const float* __restrict__ elog,
    const __half* __restrict__ hsrc, float* __restrict__ outp) {
    int node = (blockIdx.x * 256 + threadIdx.x) >> 5;
    int lane = threadIdx.x & 31;
    if (node >= NN) return;
    int beg = offs[node], end = offs[node + 1];

    float4 mx = make_float4(-1e30f, -1e30f, -1e30f, -1e30f);
    for (int j = beg + lane; j < end; j += 32) {
        int e = eidx[j];
        float4 l = *(const float4*)(elog + (size_t)e * 4);
        mx.x = fmaxf(mx.x, l.x); mx.y = fmaxf(mx.y, l.y);
        mx.z = fmaxf(mx.z, l.z); mx.w = fmaxf(mx.w, l.w);
    }
#pragma unroll
    for (int o = 16; o > 0; o >>= 1) {
        mx.x = fmaxf(mx.x, __shfl_xor_sync(0xFFFFFFFFu, mx.x, o));
        mx.y = fmaxf(mx.y, __shfl_xor_sync(0xFFFFFFFFu, mx.y, o));
        mx.z = fmaxf(mx.z, __shfl_xor_sync(0xFFFFFFFFu, mx.z, o));
        mx.w = fmaxf(mx.w, __shfl_xor_sync(0xFFFFFFFFu, mx.w, o));
    }
    int h = lane >> 3;
    float mh = (h == 0) ? mx.x : (h == 1) ? mx.y : (h == 2) ? mx.z : mx.w;

    float acc[8] = {0.f, 0.f, 0.f, 0.f, 0.f, 0.f, 0.f, 0.f};
    float ssum = 0.f;
    int j = beg;
    for (; j + 1 < end; j += 2) {
        int ea = eidx[j], eb = eidx[j + 1];
        int sa = srcs[ea], sbn = srcs[eb];
        float la = elog[(size_t)ea * 4 + h], lb = elog[(size_t)eb * 4 + h];
        uint4 ra = *((const uint4*)(hsrc + (size_t)sa * 256) + lane);
        uint4 rb = *((const uint4*)(hsrc + (size_t)sbn * 256) + lane);
        float wa = expf(la - mh), wb = expf(lb - mh);
        ssum += wa + wb;
        float2 t;
        t = __half22float2(*(__half2*)&ra.x); acc[0] += wa * t.x; acc[1] += wa * t.y;
        t = __half22float2(*(__half2*)&ra.y); acc[2] += wa * t.x; acc[3] += wa * t.y;
        t = __half22float2(*(__half2*)&ra.z); acc[4] += wa * t.x; acc[5] += wa * t.y;
        t = __half22float2(*(__half2*)&ra.w); acc[6] += wa * t.x; acc[7] += wa * t.y;
        t = __half22float2(*(__half2*)&rb.x); acc[0] += wb * t.x; acc[1] += wb * t.y;
        t = __half22float2(*(__half2*)&rb.y); acc[2] += wb * t.x; acc[3] += wb * t.y;
        t = __half22float2(*(__half2*)&rb.z); acc[4] += wb * t.x; acc[5] += wb * t.y;
        t = __half22float2(*(__half2*)&rb.w); acc[6] += wb * t.x; acc[7] += wb * t.y;
    }
    if (j < end) {
        int e = eidx[j];
        float w = expf(elog[(size_t)e * 4 + h] - mh);
        ssum += w;
        uint4 ra = *((const uint4*)(hsrc + (size_t)srcs[e] * 256) + lane);
        float2 t;
        t = __half22float2(*(__half2*)&ra.x); acc[0] += w * t.x; acc[1] += w * t.y;
        t = __half22float2(*(__half2*)&ra.y); acc[2] += w * t.x; acc[3] += w * t.y;
        t = __half22float2(*(__half2*)&ra.z); acc[4] += w * t.x; acc[5] += w * t.y;
        t = __half22float2(*(__half2*)&ra.w); acc[6] += w * t.x; acc[7] += w * t.y;
    }
    float inv = (end > beg) ? 1.f / ssum : 0.f;
    float* op = outp + (size_t)node * 256 + lane * 8;
    float4 o0, o1;
    o0.x = elu_f(acc[0] * inv); o0.y = elu_f(acc[1] * inv);
    o0.z = elu_f(acc[2] * inv); o0.w = elu_f(acc[3] * inv);
    o1.x = elu_f(acc[4] * inv); o1.y = elu_f(acc[5] * inv);
    o1.z = elu_f(acc[6] * inv); o1.w = elu_f(acc[7] * inv);
    *(float4*)op = o0;
    *(float4*)(op + 4) = o1;
}

// ---------------- host ----------------
extern "C" void kernel_launch(void* const* d_in, const int* in_sizes, int n_in,
                              void* d_out, int out_size) {
    const int*   node_types = (const int*)d_in[0];
    const int*   src        = (const int*)d_in[1];
    const int*   dst        = (const int*)d_in[2];
    const float* efeats     = (const float*)d_in[3];
    const float* embed      = (const float*)d_in[4];
    const float* W_src[2] = {(const float*)d_in[5],  (const float*)d_in[12]};
    const float* b_src[2] = {(const float*)d_in[6],  (const float*)d_in[13]};
    const float* W_ni[2]  = {(const float*)d_in[7],  (const float*)d_in[14]};
    const float* W_nj[2]  = {(const float*)d_in[8],  (const float*)d_in[15]};
    const float* W_fij[2] = {(const float*)d_in[9],  (const float*)d_in[16]};
    const float* attn[2]  = {(const float*)d_in[10], (const float*)d_in[17]};
    const float* bias[2]  = {(const float*)d_in[11], (const float*)d_in[18]};

    float *nf, *node_out, *efbuf, *elog, *bcat;
    __half* hsrc;
    int *deg, *offs, *cursor, *eidx, *bsum;
    __nv_bfloat16 *btnh, *btnl, *bteh, *btel;
    cudaGetSymbolAddress((void**)&nf, g_nf);
    cudaGetSymbolAddress((void**)&node_out, g_node_out);
    cudaGetSymbolAddress((void**)&hsrc, g_hsrc);
    cudaGetSymbolAddress((void**)&efbuf, g_efbuf);
    cudaGetSymbolAddress((void**)&elog, g_elog);
    cudaGetSymbolAddress((void**)&bcat, g_bcat);
    cudaGetSymbolAddress((void**)&btnh, g_btn_hi);
    cudaGetSymbolAddress((void**)&btnl, g_btn_lo);
    cudaGetSymbolAddress((void**)&bteh, g_bte_hi);
    cudaGetSymbolAddress((void**)&btel, g_bte_lo);
    cudaGetSymbolAddress((void**)&deg, g_deg);
    cudaGetSymbolAddress((void**)&offs, g_offs);
    cudaGetSymbolAddress((void**)&cursor, g_cursor);
    cudaGetSymbolAddress((void**)&eidx, g_eidx);
    cudaGetSymbolAddress((void**)&bsum, g_bsum);

    cudaFuncSetAttribute(gemm_node_mma, cudaFuncAttributeMaxDynamicSharedMemorySize, NODE_SMEM);
    cudaFuncSetAttribute(gemm_edge_mma, cudaFuncAttributeMaxDynamicSharedMemorySize, EDGE_SMEM);

    float* out_nf = (float*)d_out;
    float* out_ef = out_nf + (size_t)NN * 256;

    k_embed<<<(NN * 128 + 255) / 256, 256>>>(node_types, embed, nf);

    // CSR by dst (edges identical across layers)
    k_zero_deg<<<NB_SCAN, 256>>>(deg);
    k_hist<<<(EE + 255) / 256, 256>>>(dst, deg);
    k_scanA<<<NB_SCAN, 256>>>(deg, bsum);
    k_scanB<<<1, 256>>>(bsum);
    k_scanC<<<NB_SCAN, 256>>>(deg, bsum, offs, cursor);
    k_scatter<<<(EE + 255) / 256, 256>>>(dst, cursor, eidx);

    const float* ef_in = efeats;
    for (int L = 0; L < 2; L++) {
        int in_n = L ? 256 : 128;
        int in_e = L ? 128 : 64;
        int prep_items = 512 * in_n + 128 * in_e;
        k_prep<<<(prep_items + 255) / 256, 256>>>(W_ni[L], W_nj[L], W_src[L], b_src[L],
                                                  W_fij[L], bcat, btnh, btnl, bteh, btel,
                                                  in_n, in_e);

        dim3 gn((NN + 127) / 128, 4);
        gemm_node_mma<<<gn, 256, NODE_SMEM>>>(nf, btnh, btnl, bcat, node_out, hsrc, NN, in_n);

        float* ef_out = L ? out_ef : efbuf;
        gemm_edge_mma<<<(EE + 127) / 128, 256, EDGE_SMEM>>>(ef_in, bteh, btel, node_out,
                                                            src, dst, bias[L], attn[L],
                                                            ef_out, elog, EE, in_e);

        float* nf_out = L ? out_nf : nf;
        k_aggr<<<(NN * 32 + 255) / 256, 256>>>(src, eidx, offs, elog, hsrc, nf_out);
        ef_in = ef_out;
    }
}

// round 13
// speedup vs baseline: 1.5316x; 1.0110x over previous
#include <cuda_runtime.h>
#include <cuda_bf16.h>
#include <cuda_fp16.h>
#include <math.h>
#include <stdint.h>

#define NN 50000
#define EE 500000
#define NB_SCAN ((NN + 255) / 256)   // 196

// ---------------- scratch ----------------
__device__ float    g_nf[(size_t)NN * 256];
__device__ __half   g_nodeh[(size_t)NN * 256];     // [f_ni(128) | f_nj(128)] fp16
__device__ __half   g_hsrc[(size_t)NN * 256];      // h_src fp16
__device__ __half   g_efh[(size_t)EE * 128];       // layer-0 ef intermediate fp16
__device__ float    g_elog[(size_t)EE * 4];
__device__ float    g_bcat[512];
__device__ __nv_bfloat16 g_btn_hi[512 * 256];
__device__ __nv_bfloat16 g_btn_lo[512 * 256];
__device__ __nv_bfloat16 g_bte_hi[128 * 128];
__device__ __nv_bfloat16 g_bte_lo[128 * 128];
// CSR by dst
__device__ int g_deg[NN];
__device__ int g_offs[NN + 1];
__device__ int g_cursor[NN];
__device__ int g_eidx[EE];
__device__ int g_bsum[256];

// ---------------- helpers ----------------
__device__ __forceinline__ uint32_t smem_u32(const void* p) {
    uint32_t a;
    asm("{ .reg .u64 t; cvta.to.shared.u64 t, %1; cvt.u32.u64 %0, t; }" : "=r"(a) : "l"(p));
    return a;
}
__device__ __forceinline__ void sts128(uint32_t a, uint4 v) {
    asm volatile("st.shared.v4.b32 [%0], {%1, %2, %3, %4};"
                 :: "r"(a), "r"(v.x), "r"(v.y), "r"(v.z), "r"(v.w) : "memory");
}
__device__ __forceinline__ void ldsm_x4(unsigned& r0, unsigned& r1, unsigned& r2,
                                        unsigned& r3, uint32_t addr) {
    asm volatile("ldmatrix.sync.aligned.m8n8.x4.shared.b16 {%0,%1,%2,%3}, [%4];"
                 : "=r"(r0), "=r"(r1), "=r"(r2), "=r"(r3) : "r"(addr));
}
#define CP_ASYNC16(dst, src) \
    asm volatile("cp.async.ca.shared.global [%0], [%1], 16;" :: "r"(dst), "l"(src) : "memory")
#define CP_COMMIT() asm volatile("cp.async.commit_group;" ::: "memory")
#define CP_WAIT0()  asm volatile("cp.async.wait_group 0;" ::: "memory")

__device__ __forceinline__ void mma_bf16(float& d0, float& d1, float& d2, float& d3,
                                         unsigned a0, unsigned a1, unsigned a2, unsigned a3,
                                         unsigned b0, unsigned b1) {
    asm volatile(
        "mma.sync.aligned.m16n8k16.row.col.f32.bf16.bf16.f32 "
        "{%0,%1,%2,%3}, {%4,%5,%6,%7}, {%8,%9}, {%0,%1,%2,%3};"
        : "+f"(d0), "+f"(d1), "+f"(d2), "+f"(d3)
        : "r"(a0), "r"(a1), "r"(a2), "r"(a3), "r"(b0), "r"(b1));
}
__device__ __forceinline__ void split2(float a, float b, unsigned& hi, unsigned& lo) {
    __nv_bfloat16 ah = __float2bfloat16_rn(a), bh = __float2bfloat16_rn(b);
    __nv_bfloat16 al = __float2bfloat16_rn(a - __bfloat162float(ah));
    __nv_bfloat16 bl = __float2bfloat16_rn(b - __bfloat162float(bh));
    hi = (unsigned)__bfloat16_as_ushort(ah) | ((unsigned)__bfloat16_as_ushort(bh) << 16);
    lo = (unsigned)__bfloat16_as_ushort(al) | ((unsigned)__bfloat16_as_ushort(bl) << 16);
}
__device__ __forceinline__ float elu_f(float v)   { return v > 0.f ? v : expm1f(v); }
__device__ __forceinline__ float lrelu_f(float v) { return v > 0.f ? v : 0.01f * v; }

// A-tile fetch: fp32 or fp16 source -> float4[4] (16 values)
__device__ __forceinline__ void a_fetch(const float* p, float4 pa[4], bool v) {
    const float4 z4 = make_float4(0.f, 0.f, 0.f, 0.f);
#pragma unroll
    for (int q = 0; q < 4; q++) pa[q] = v ? *(const float4*)(p + q * 4) : z4;
}
__device__ __forceinline__ void a_fetch(const __half* p, float4 pa[4], bool v) {
    if (v) {
        uint4 u0 = *(const uint4*)p;
        uint4 u1 = *(const uint4*)(p + 8);
        float2 t;
        t = __half22float2(*(__half2*)&u0.x); pa[0].x = t.x; pa[0].y = t.y;
        t = __half22float2(*(__half2*)&u0.y); pa[0].z = t.x; pa[0].w = t.y;
        t = __half22float2(*(__half2*)&u0.z); pa[1].x = t.x; pa[1].y = t.y;
        t = __half22float2(*(__half2*)&u0.w); pa[1].z = t.x; pa[1].w = t.y;
        t = __half22float2(*(__half2*)&u1.x); pa[2].x = t.x; pa[2].y = t.y;
        t = __half22float2(*(__half2*)&u1.y); pa[2].z = t.x; pa[2].w = t.y;
        t = __half22float2(*(__half2*)&u1.z); pa[3].x = t.x; pa[3].y = t.y;
        t = __half22float2(*(__half2*)&u1.w); pa[3].z = t.x; pa[3].w = t.y;
    } else {
        const float4 z4 = make_float4(0.f, 0.f, 0.f, 0.f);
#pragma unroll
        for (int q = 0; q < 4; q++) pa[q] = z4;
    }
}

// ---------------- smem layout (bytes) ----------------
#define AHI    0
#define ALO    10240
#define BHI    20480
#define BLO    30720
#define BUFSZ  40960
#define NODE_BIAS 81920
#define NODE_SMEM (81920 + 2048)
#define ESRC     81920
#define EDST     82432
#define EBIAS    82944
#define EATTN    83456
#define EDGE_SMEM 83968

// ---------------- small kernels ----------------
__global__ void k_embed(const int* __restrict__ node_types,
                        const float* __restrict__ embed, float* __restrict__ nf) {
    int i = blockIdx.x * 256 + threadIdx.x;
    if (i < NN * 128) {
        int n = i >> 7, c = i & 127;
        nf[(size_t)n * 128 + c] = embed[node_types[n] * 128 + c];
    }
}

__global__ void k_prep(const float* __restrict__ Wni, const float* __restrict__ Wnj,
                       const float* __restrict__ Wsrc, const float* __restrict__ bsrc,
                       const float* __restrict__ Wfij,
                       float* __restrict__ bcat,
                       __nv_bfloat16* __restrict__ btn_hi, __nv_bfloat16* __restrict__ btn_lo,
                       __nv_bfloat16* __restrict__ bte_hi, __nv_bfloat16* __restrict__ bte_lo,
                       int in_n, int in_e) {
    int i = blockIdx.x * 256 + threadIdx.x;
    int nn = 512 * in_n;
    if (i < nn) {
        int n = i / in_n, k = i - n * in_n;
        float v;
        if (n < 128)      v = Wni[k * 128 + n];
        else if (n < 256) v = Wnj[k * 128 + (n - 128)];
        else              v = Wsrc[k * 256 + (n - 256)];
        __nv_bfloat16 h = __float2bfloat16_rn(v);
        __nv_bfloat16 l = __float2bfloat16_rn(v - __bfloat162float(h));
        btn_hi[(size_t)n * in_n + k] = h;
        btn_lo[(size_t)n * in_n + k] = l;
    } else if (i < nn + 128 * in_e) {
        int j = i - nn;
        int n = j / in_e, k = j - n * in_e;
        float v = Wfij[k * 128 + n];
        __nv_bfloat16 h = __float2bfloat16_rn(v);
        __nv_bfloat16 l = __float2bfloat16_rn(v - __bfloat162float(h));
        bte_hi[(size_t)n * in_e + k] = h;
        bte_lo[(size_t)n * in_e + k] = l;
    }
    if (i < 512) bcat[i] = (i < 256) ? 0.f : bsrc[i - 256];
}

// ---------------- CSR build ----------------
__global__ void k_zero_deg(int* __restrict__ deg) {
    int i = blockIdx.x * 256 + threadIdx.x;
    if (i < NN) deg[i] = 0;
}
__global__ void k_hist(const int* __restrict__ dst, int* __restrict__ deg) {
    int e = blockIdx.x * 256 + threadIdx.x;
    if (e < EE) atomicAdd(&deg[dst[e]], 1);
}
__global__ void k_scanA(const int* __restrict__ deg, int* __restrict__ bsum) {
    __shared__ int sh[256];
    int i = blockIdx.x * 256 + threadIdx.x;
    sh[threadIdx.x] = (i < NN) ? deg[i] : 0;
    __syncthreads();
    for (int o = 128; o > 0; o >>= 1) {
        if (threadIdx.x < o) sh[threadIdx.x] += sh[threadIdx.x + o];
        __syncthreads();
    }
    if (threadIdx.x == 0) bsum[blockIdx.x] = sh[0];
}
__global__ void k_scanB(int* __restrict__ bsum) {
    __shared__ int sh[256];
    int t = threadIdx.x;
    int v = (t < NB_SCAN) ? bsum[t] : 0;
    sh[t] = v;
    __syncthreads();
    for (int o = 1; o < 256; o <<= 1) {
        int add = (t >= o) ? sh[t - o] : 0;
        __syncthreads();
        sh[t] += add;
        __syncthreads();
    }
    if (t < NB_SCAN) bsum[t] = sh[t] - v;
}
__global__ void k_scanC(const int* __restrict__ deg, const int* __restrict__ bsum,
                        int* __restrict__ offs, int* __restrict__ cursor) {
    __shared__ int sh[256];
    int i = blockIdx.x * 256 + threadIdx.x;
    int t = threadIdx.x;
    int v = (i < NN) ? deg[i] : 0;
    sh[t] = v;
    __syncthreads();
    for (int o = 1; o < 256; o <<= 1) {
        int add = (t >= o) ? sh[t - o] : 0;
        __syncthreads();
        sh[t] += add;
        __syncthreads();
    }
    if (i < NN) {
        int ex = bsum[blockIdx.x] + sh[t] - v;
        offs[i] = ex;
        cursor[i] = ex;
    }
    if (i == 0) offs[NN] = EE;
}
__global__ void k_scatter(const int* __restrict__ dst, int* __restrict__ cursor,
                          int* __restrict__ eidx) {
    int e = blockIdx.x * 256 + threadIdx.x;
    if (e < EE) {
        int pos = atomicAdd(&cursor[dst[e]], 1);
        eidx[pos] = e;
    }
}

// ---------------- pipelined GEMM mainloop (ldmatrix; templated A type) ----------------
__device__ __forceinline__ void b_cpasync(uint32_t sb, int buf,
                                          const __nv_bfloat16* __restrict__ Bth,
                                          const __nv_bfloat16* __restrict__ Btl,
                                          int n0, int K, int k0) {
    int tid = threadIdx.x;
#pragma unroll
    for (int i = 0; i < 2; i++) {
        int c = tid + i * 256;
        int n = c >> 2, k16 = c & 3;
        size_t go = (size_t)(n0 + n) * K + k0 + k16 * 8;
        uint32_t da = sb + buf * BUFSZ + BHI + n * 80 + k16 * 16;
        CP_ASYNC16(da, Bth + go);
        CP_ASYNC16(da + (BLO - BHI), Btl + go);
    }
}

__device__ __forceinline__ void a_convert_sts(uint32_t sb, int buf, int r, int hk,
                                              const float4 pa[4]) {
    uint32_t ah = sb + buf * BUFSZ + AHI + r * 80 + hk * 32;
    uint32_t al = ah + (ALO - AHI);
#pragma unroll
    for (int q = 0; q < 2; q++) {
        unsigned h0, l0, h1, l1, h2, l2, h3, l3;
        split2(pa[2 * q].x,     pa[2 * q].y,     h0, l0);
        split2(pa[2 * q].z,     pa[2 * q].w,     h1, l1);
        split2(pa[2 * q + 1].x, pa[2 * q + 1].y, h2, l2);
        split2(pa[2 * q + 1].z, pa[2 * q + 1].w, h3, l3);
        sts128(ah + q * 16, make_uint4(h0, h1, h2, h3));
        sts128(al + q * 16, make_uint4(l0, l1, l2, l3));
    }
}

__device__ __forceinline__ void mma_compute(uint32_t sb, int buf, float acc[2][8][4]) {
    int tid = threadIdx.x, lane = tid & 31, wid = tid >> 5;
    int wm = wid & 3, wn = wid >> 2;
    uint32_t bo = sb + buf * BUFSZ;
    uint32_t aAddr = bo + AHI + (wm * 32 + (lane & 15)) * 80 + ((lane & 16) ? 16 : 0);
    uint32_t bAddr = bo + BHI + (wn * 64 + ((lane & 16) ? 8 : 0) + (lane & 7)) * 80 +
                     ((lane & 8) ? 16 : 0);
#pragma unroll
    for (int ks = 0; ks < 2; ks++) {
        unsigned ahr[2][4], alr[2][4];
#pragma unroll
        for (int mt = 0; mt < 2; mt++) {
            uint32_t aa = aAddr + mt * 1280 + ks * 32;
            ldsm_x4(ahr[mt][0], ahr[mt][1], ahr[mt][2], ahr[mt][3], aa);
            ldsm_x4(alr[mt][0], alr[mt][1], alr[mt][2], alr[mt][3], aa + (ALO - AHI));
        }
#pragma unroll
        for (int p = 0; p < 4; p++) {
            uint32_t ba = bAddr + p * 1280 + ks * 32;
            unsigned bh[4], bl[4];
            ldsm_x4(bh[0], bh[1], bh[2], bh[3], ba);
            ldsm_x4(bl[0], bl[1], bl[2], bl[3], ba + (BLO - BHI));
#pragma unroll
            for (int sub = 0; sub < 2; sub++) {
                int nt = p * 2 + sub;
                unsigned bh0 = bh[sub * 2], bh1 = bh[sub * 2 + 1];
                unsigned bl0 = bl[sub * 2], bl1 = bl[sub * 2 + 1];
#pragma unroll
                for (int mt = 0; mt < 2; mt++) {
                    float* d = acc[mt][nt];
                    mma_bf16(d[0], d[1], d[2], d[3],
                             ahr[mt][0], ahr[mt][1], ahr[mt][2], ahr[mt][3], bh0, bh1);
                    mma_bf16(d[0], d[1], d[2], d[3],
                             ahr[mt][0], ahr[mt][1], ahr[mt][2], ahr[mt][3], bl0, bl1);
                    mma_bf16(d[0], d[1], d[2], d[3],
                             alr[mt][0], alr[mt][1], alr[mt][2], alr[mt][3], bh0, bh1);
                }
            }
        }
    }
}

template <typename AT>
__device__ __forceinline__ void mma_mainloop(
    uint32_t sb, const AT* __restrict__ A,
    const __nv_bfloat16* __restrict__ Bth, const __nv_bfloat16* __restrict__ Btl,
    int row0, int n0, int M, int K, float acc[2][8][4]) {
    int tid = threadIdx.x;
    int r = tid >> 1, hk = tid & 1;
    int arow = row0 + r;
    bool aval = arow < M;
    const AT* abase = A + (size_t)arow * K + hk * 16;
    int nst = K >> 5;

    float4 pa[4];
    a_fetch(abase, pa, aval);
    b_cpasync(sb, 0, Bth, Btl, n0, K, 0);
    CP_COMMIT();
    a_convert_sts(sb, 0, r, hk, pa);
    CP_WAIT0();
    __syncthreads();

    for (int s = 0; s < nst; s++) {
        int buf = s & 1, nb = buf ^ 1;
        bool more = (s + 1) < nst;
        if (more) {
            b_cpasync(sb, nb, Bth, Btl, n0, K, (s + 1) * 32);
            CP_COMMIT();
            a_fetch(abase + (s + 1) * 32, pa, aval);
        }
        mma_compute(sb, buf, acc);
        if (more) {
            a_convert_sts(sb, nb, r, hk, pa);
            CP_WAIT0();
        }
        __syncthreads();
    }
}

// ---------------- node GEMM: fp16 f_ni/f_nj + fp16 h_src ----------------
__global__ __launch_bounds__(256, 2) void gemm_node_mma(
    const float* __restrict__ A,
    const __nv_bfloat16* __restrict__ Bth, const __nv_bfloat16* __restrict__ Btl,
    const float* __restrict__ bias, __half* __restrict__ nodeh,
    __half* __restrict__ hsrc, int M, int K) {
    extern __shared__ __align__(16) char smem[];
    uint32_t sb = smem_u32(smem);
    float* bsm = (float*)(smem + NODE_BIAS);
    int tid = threadIdx.x;
    ((float2*)bsm)[tid] = ((const float2*)bias)[tid];

    int row0 = blockIdx.x * 128, n0 = blockIdx.y * 128;
    float acc[2][8][4];
#pragma unroll
    for (int mt = 0; mt < 2; mt++)
#pragma unroll
        for (int nt = 0; nt < 8; nt++)
#pragma unroll
            for (int q = 0; q < 4; q++) acc[mt][nt][q] = 0.f;

    mma_mainloop(sb, A, Bth, Btl, row0, n0, M, K, acc);

    int lane = tid & 31, wid = tid >> 5;
    int g = lane >> 2, tig = lane & 3;
    int wm = wid & 3, wn = wid >> 2;
    bool to_hsrc = n0 >= 256;
    __half* outp = to_hsrc ? hsrc : nodeh;
    int cbase = to_hsrc ? 256 : 0;
#pragma unroll
    for (int mt = 0; mt < 2; mt++) {
        int r0 = row0 + wm * 32 + mt * 16 + g;
#pragma unroll
        for (int nt = 0; nt < 8; nt++) {
            int cc = n0 + wn * 64 + nt * 8 + 2 * tig;
            float b0 = bsm[cc], b1 = bsm[cc + 1];
            float* d = acc[mt][nt];
            int hc = cc - cbase;
            if (r0 < M)
                *(__half2*)(outp + (size_t)r0 * 256 + hc) =
                    __floats2half2_rn(d[0] + b0, d[1] + b1);
            if (r0 + 8 < M)
                *(__half2*)(outp + (size_t)(r0 + 8) * 256 + hc) =
                    __floats2half2_rn(d[2] + b0, d[3] + b1);
        }
    }
}

// ---------------- edge GEMM: direct-from-fragment fused epilogue ----------------
// AT: A element type; EFHALF: 1 -> write fp16 intermediate, 0 -> write fp32 final
template <typename AT, int EFHALF>
__global__ __launch_bounds__(256, 2) void gemm_edge_mma(
    const AT* __restrict__ A,
    const __nv_bfloat16* __restrict__ Bth, const __nv_bfloat16* __restrict__ Btl,
    const __half* __restrict__ nodeh,
    const int* __restrict__ src, const int* __restrict__ dst,
    const float* __restrict__ bias, const float* __restrict__ attn,
    float* __restrict__ ef32, __half* __restrict__ efh,
    float* __restrict__ elog, int M, int K) {
    extern __shared__ __align__(16) char smem[];
    uint32_t sb = smem_u32(smem);
    int*   ssh = (int*)(smem + ESRC);
    int*   dsh = (int*)(smem + EDST);
    float* bsh = (float*)(smem + EBIAS);
    float* ash = (float*)(smem + EATTN);

    int tid = threadIdx.x;
    int e0 = blockIdx.x * 128;
    if (tid < 128) {
        int e = e0 + tid;
        ssh[tid] = (e < M) ? src[e] : 0;
        dsh[tid] = (e < M) ? dst[e] : 0;
        bsh[tid] = bias[tid];
        ash[tid] = attn[tid];
    }

    float acc[2][8][4];
#pragma unroll
    for (int mt = 0; mt < 2; mt++)
#pragma unroll
        for (int nt = 0; nt < 8; nt++)
#pragma unroll
            for (int q = 0; q < 4; q++) acc[mt][nt][q] = 0.f;

    mma_mainloop(sb, A, Bth, Btl, e0, 0, M, K, acc);

    int lane = tid & 31, wid = tid >> 5;
    int g = lane >> 2, tig = lane & 3;
    int wm = wid & 3, wn = wid >> 2;

#pragma unroll
    for (int mt = 0; mt < 2; mt++) {
        int r = wm * 32 + mt * 16 + g;
        int rA = r, rB = r + 8;
        int eA = e0 + rA, eB = e0 + rB;
        int siA = ssh[rA], djA = dsh[rA];
        int siB = ssh[rB], djB = dsh[rB];
        const __half* niA = nodeh + (size_t)siA * 256;
        const __half* njA = nodeh + (size_t)djA * 256 + 128;
        const __half* niB = nodeh + (size_t)siB * 256;
        const __half* njB = nodeh + (size_t)djB * 256 + 128;
        float partA[2] = {0.f, 0.f};
        float partB[2] = {0.f, 0.f};
#pragma unroll
        for (int nt = 0; nt < 8; nt++) {
            int cc = wn * 64 + nt * 8 + 2 * tig;
            int hl = nt >> 2;
            float b0 = bsh[cc], b1 = bsh[cc + 1];
            float a0 = ash[cc], a1 = ash[cc + 1];
            float2 nA0 = __half22float2(*(const __half2*)(niA + cc));
            float2 nA1 = __half22float2(*(const __half2*)(njA + cc));
            float2 nB0 = __half22float2(*(const __half2*)(niB + cc));
            float2 nB1 = __half22float2(*(const __half2*)(njB + cc));
            float* d = acc[mt][nt];
            float v0 = lrelu_f(d[0] + nA0.x + nA1.x + b0);
            float v1 = lrelu_f(d[1] + nA0.y + nA1.y + b1);
            partA[hl] += v0 * a0 + v1 * a1;
            float e0v = elu_f(v0), e1v = elu_f(v1);
            if (eA < M) {
                if (EFHALF)
                    *(__half2*)(efh + (size_t)eA * 128 + cc) = __floats2half2_rn(e0v, e1v);
                else
                    *(float2*)(ef32 + (size_t)eA * 128 + cc) = make_float2(e0v, e1v);
            }
            float w0 = lrelu_f(d[2] + nB0.x + nB1.x + b0);
            float w1 = lrelu_f(d[3] + nB0.y + nB1.y + b1);
            partB[hl] += w0 * a0 + w1 * a1;
            float f0v = elu_f(w0), f1v = elu_f(w1);
            if (eB < M) {
                if (EFHALF)
                    *(__half2*)(efh + (size_t)eB * 128 + cc) = __floats2half2_rn(f0v, f1v);
                else
                    *(float2*)(ef32 + (size_t)eB * 128 + cc) = make_float2(f0v, f1v);
            }
        }
#pragma unroll
        for (int o = 1; o <= 2; o <<= 1) {
            partA[0] += __shfl_xor_sync(0xFFFFFFFFu, partA[0], o);
            partA[1] += __shfl_xor_sync(0xFFFFFFFFu, partA[1], o);
            partB[0] += __shfl_xor_sync(0xFFFFFFFFu, partB[0], o);
            partB[1] += __shfl_xor_sync(0xFFFFFFFFu, partB[1], o);
        }
        if (tig == 0) {
            int h0 = wn * 2, h1 = wn * 2 + 1;
            if (eA < M) {
                elog[(size_t)eA * 4 + h0] = partA[0];
                elog[(size_t)eA * 4 + h1] = partA[1];
            }
            if (eB < M) {
                elog[(size_t)eB * 4 + h0] = partB[0];
                elog[(size_t)eB * 4 + h1] = partB[1];
            }
        }
    }
}

// ---------------- CSR aggregation (fp16 h_src gather) ----------------
__global__ __launch_bounds__(256) void k_aggr(
    const int* __restrict__ srcs, const int* __restrict__ eidx,
    const int* __restrict__ offs, const float* __restrict__ elog,
    const __half* __restrict__ hsrc, float* __restrict__ outp) {
    int node = (blockIdx.x * 256 + threadIdx.x) >> 5;
    int lane = threadIdx.x & 31;
    if (node >= NN) return;
    int beg = offs[node], end = offs[node + 1];

    float4 mx = make_float4(-1e30f, -1e30f, -1e30f, -1e30f);
    for (int j = beg + lane; j < end; j += 32) {
        int e = eidx[j];
        float4 l = *(const float4*)(elog + (size_t)e * 4);
        mx.x = fmaxf(mx.x, l.x); mx.y = fmaxf(mx.y, l.y);
        mx.z = fmaxf(mx.z, l.z); mx.w = fmaxf(mx.w, l.w);
    }
#pragma unroll
    for (int o = 16; o > 0; o >>= 1) {
        mx.x = fmaxf(mx.x, __shfl_xor_sync(0xFFFFFFFFu, mx.x, o));
        mx.y = fmaxf(mx.y, __shfl_xor_sync(0xFFFFFFFFu, mx.y, o));
        mx.z = fmaxf(mx.z, __shfl_xor_sync(0xFFFFFFFFu, mx.z, o));
        mx.w = fmaxf(mx.w, __shfl_xor_sync(0xFFFFFFFFu, mx.w, o));
    }
    int h = lane >> 3;
    float mh = (h == 0) ? mx.x : (h == 1) ? mx.y : (h == 2) ? mx.z : mx.w;

    float acc[8] = {0.f, 0.f, 0.f, 0.f, 0.f, 0.f, 0.f, 0.f};
    float ssum = 0.f;
    int j = beg;
    for (; j + 1 < end; j += 2) {
        int ea = eidx[j], eb = eidx[j + 1];
        int sa = srcs[ea], sbn = srcs[eb];
        float la = elog[(size_t)ea * 4 + h], lb = elog[(size_t)eb * 4 + h];
        uint4 ra = *((const uint4*)(hsrc + (size_t)sa * 256) + lane);
        uint4 rb = *((const uint4*)(hsrc + (size_t)sbn * 256) + lane);
        float wa = expf(la - mh), wb = expf(lb - mh);
        ssum += wa + wb;
        float2 t;
        t = __half22float2(*(__half2*)&ra.x); acc[0] += wa * t.x; acc[1] += wa * t.y;
        t = __half22float2(*(__half2*)&ra.y); acc[2] += wa * t.x; acc[3] += wa * t.y;
        t = __half22float2(*(__half2*)&ra.z); acc[4] += wa * t.x; acc[5] += wa * t.y;
        t = __half22float2(*(__half2*)&ra.w); acc[6] += wa * t.x; acc[7] += wa * t.y;
        t = __half22float2(*(__half2*)&rb.x); acc[0] += wb * t.x; acc[1] += wb * t.y;
        t = __half22float2(*(__half2*)&rb.y); acc[2] += wb * t.x; acc[3] += wb * t.y;
        t = __half22float2(*(__half2*)&rb.z); acc[4] += wb * t.x; acc[5] += wb * t.y;
        t = __half22float2(*(__half2*)&rb.w); acc[6] += wb * t.x; acc[7] += wb * t.y;
    }
    if (j < end) {
        int e = eidx[j];
        float w = expf(elog[(size_t)e * 4 + h] - mh);
        ssum += w;
        uint4 ra = *((const uint4*)(hsrc + (size_t)srcs[e] * 256) + lane);
        float2 t;
        t = __half22float2(*(__half2*)&ra.x); acc[0] += w * t.x; acc[1] += w * t.y;
        t = __half22float2(*(__half2*)&ra.y); acc[2] += w * t.x; acc[3] += w * t.y;
        t = __half22float2(*(__half2*)&ra.z); acc[4] += w * t.x; acc[5] += w * t.y;
        t = __half22float2(*(__half2*)&ra.w); acc[6] += w * t.x; acc[7] += w * t.y;
    }
    float inv = (end > beg) ? 1.f / ssum : 0.f;
    float* op = outp + (size_t)node * 256 + lane * 8;
    float4 o0, o1;
    o0.x = elu_f(acc[0] * inv); o0.y = elu_f(acc[1] * inv);
    o0.z = elu_f(acc[2] * inv); o0.w = elu_f(acc[3] * inv);
    o1.x = elu_f(acc[4] * inv); o1.y = elu_f(acc[5] * inv);
    o1.z = elu_f(acc[6] * inv); o1.w = elu_f(acc[7] * inv);
    *(float4*)op = o0;
    *(float4*)(op + 4) = o1;
}

// ---------------- host ----------------
extern "C" void kernel_launch(void* const* d_in, const int* in_sizes, int n_in,
                              void* d_out, int out_size) {
    const int*   node_types = (const int*)d_in[0];
    const int*   src        = (const int*)d_in[1];
    const int*   dst        = (const int*)d_in[2];
    const float* efeats     = (const float*)d_in[3];
    const float* embed      = (const float*)d_in[4];
    const float* W_src[2] = {(const float*)d_in[5],  (const float*)d_in[12]};
    const float* b_src[2] = {(const float*)d_in[6],  (const float*)d_in[13]};
    const float* W_ni[2]  = {(const float*)d_in[7],  (const float*)d_in[14]};
    const float* W_nj[2]  = {(const float*)d_in[8],  (const float*)d_in[15]};
    const float* W_fij[2] = {(const float*)d_in[9],  (const float*)d_in[16]};
    const float* attn[2]  = {(const float*)d_in[10], (const float*)d_in[17]};
    const float* bias[2]  = {(const float*)d_in[11], (const float*)d_in[18]};

    float *nf, *elog, *bcat;
    __half *nodeh, *hsrc, *efh;
    int *deg, *offs, *cursor, *eidx, *bsum;
    __nv_bfloat16 *btnh, *btnl, *bteh, *btel;
    cudaGetSymbolAddress((void**)&nf, g_nf);
    cudaGetSymbolAddress((void**)&nodeh, g_nodeh);
    cudaGetSymbolAddress((void**)&hsrc, g_hsrc);
    cudaGetSymbolAddress((void**)&efh, g_efh);
    cudaGetSymbolAddress((void**)&elog, g_elog);
    cudaGetSymbolAddress((void**)&bcat, g_bcat);
    cudaGetSymbolAddress((void**)&btnh, g_btn_hi);
    cudaGetSymbolAddress((void**)&btnl, g_btn_lo);
    cudaGetSymbolAddress((void**)&bteh, g_bte_hi);
    cudaGetSymbolAddress((void**)&btel, g_bte_lo);
    cudaGetSymbolAddress((void**)&deg, g_deg);
    cudaGetSymbolAddress((void**)&offs, g_offs);
    cudaGetSymbolAddress((void**)&cursor, g_cursor);
    cudaGetSymbolAddress((void**)&eidx, g_eidx);
    cudaGetSymbolAddress((void**)&bsum, g_bsum);

    cudaFuncSetAttribute(gemm_node_mma, cudaFuncAttributeMaxDynamicSharedMemorySize, NODE_SMEM);
    cudaFuncSetAttribute((const void*)gemm_edge_mma<float, 1>,
                         cudaFuncAttributeMaxDynamicSharedMemorySize, EDGE_SMEM);
    cudaFuncSetAttribute((const void*)gemm_edge_mma<__half, 0>,
                         cudaFuncAttributeMaxDynamicSharedMemorySize, EDGE_SMEM);

    float* out_nf = (float*)d_out;
    float* out_ef = out_nf + (size_t)NN * 256;

    k_embed<<<(NN * 128 + 255) / 256, 256>>>(node_types, embed, nf);

    // CSR by dst (edges identical across layers)
    k_zero_deg<<<NB_SCAN, 256>>>(deg);
    k_hist<<<(EE + 255) / 256, 256>>>(dst, deg);
    k_scanA<<<NB_SCAN, 256>>>(deg, bsum);
    k_scanB<<<1, 256>>>(bsum);
    k_scanC<<<NB_SCAN, 256>>>(deg, bsum, offs, cursor);
    k_scatter<<<(EE + 255) / 256, 256>>>(dst, cursor, eidx);

    for (int L = 0; L < 2; L++) {
        int in_n = L ? 256 : 128;
        int in_e = L ? 128 : 64;
        int prep_items = 512 * in_n + 128 * in_e;
        k_prep<<<(prep_items + 255) / 256, 256>>>(W_ni[L], W_nj[L], W_src[L], b_src[L],
                                                  W_fij[L], bcat, btnh, btnl, bteh, btel,
                                                  in_n, in_e);

        dim3 gn((NN + 127) / 128, 4);
        gemm_node_mma<<<gn, 256, NODE_SMEM>>>(nf, btnh, btnl, bcat, nodeh, hsrc, NN, in_n);

        if (L == 0) {
            gemm_edge_mma<float, 1><<<(EE + 127) / 128, 256, EDGE_SMEM>>>(
                efeats, bteh, btel, nodeh, src, dst, bias[L], attn[L],
                nullptr, efh, elog, EE, in_e);
        } else {
            gemm_edge_mma<__half, 0><<<(EE + 127) / 128, 256, EDGE_SMEM>>>(
                efh, bteh, btel, nodeh, src, dst, bias[L], attn[L],
                out_ef, nullptr, elog, EE, in_e);
        }

        float* nf_out = L ? out_nf : nf;
        k_aggr<<<(NN * 32 + 255) / 256, 256>>>(src, eidx, offs, elog, hsrc, nf_out);
    }
}

// round 14
// speedup vs baseline: 1.8407x; 1.2018x over previous
#include <cuda_runtime.h>
#include <cuda_bf16.h>
#include <cuda_fp16.h>
#include <math.h>
#include <stdint.h>

#define NN 50000
#define EE 500000
#define NB_SCAN ((NN + 255) / 256)   // 196

// ---------------- scratch ----------------
__device__ float    g_nf[(size_t)NN * 256];
__device__ __half   g_nodeh[(size_t)NN * 256];     // [f_ni(128) | f_nj(128)] fp16
__device__ __half   g_hsrc[(size_t)NN * 256];      // h_src fp16
__device__ __half   g_efh[(size_t)EE * 128];       // layer-0 ef intermediate fp16
__device__ float    g_elog[(size_t)EE * 4];
__device__ float    g_bcat[512];
__device__ __half   g_btn[512 * 256];              // node weights fp16, [n][k]
__device__ __half   g_bte[128 * 128];              // edge weights fp16, [n][k]
// CSR by dst
__device__ int g_deg[NN];
__device__ int g_offs[NN + 1];
__device__ int g_cursor[NN];
__device__ int g_eidx[EE];
__device__ int g_bsum[256];

// ---------------- helpers ----------------
__device__ __forceinline__ uint32_t smem_u32(const void* p) {
    uint32_t a;
    asm("{ .reg .u64 t; cvta.to.shared.u64 t, %1; cvt.u32.u64 %0, t; }" : "=r"(a) : "l"(p));
    return a;
}
__device__ __forceinline__ void sts128(uint32_t a, uint4 v) {
    asm volatile("st.shared.v4.b32 [%0], {%1, %2, %3, %4};"
                 :: "r"(a), "r"(v.x), "r"(v.y), "r"(v.z), "r"(v.w) : "memory");
}
__device__ __forceinline__ void ldsm_x4(unsigned& r0, unsigned& r1, unsigned& r2,
                                        unsigned& r3, uint32_t addr) {
    asm volatile("ldmatrix.sync.aligned.m8n8.x4.shared.b16 {%0,%1,%2,%3}, [%4];"
                 : "=r"(r0), "=r"(r1), "=r"(r2), "=r"(r3) : "r"(addr));
}
#define CP_ASYNC16(dst, src) \
    asm volatile("cp.async.ca.shared.global [%0], [%1], 16;" :: "r"(dst), "l"(src) : "memory")
#define CP_ASYNC16Z(dst, src, pred) \
    asm volatile("cp.async.ca.shared.global [%0], [%1], 16, %2;" \
                 :: "r"(dst), "l"(src), "r"((pred) ? 16 : 0) : "memory")
#define CP_COMMIT() asm volatile("cp.async.commit_group;" ::: "memory")
#define CP_WAIT0()  asm volatile("cp.async.wait_group 0;" ::: "memory")

__device__ __forceinline__ void mma_f16(float& d0, float& d1, float& d2, float& d3,
                                        unsigned a0, unsigned a1, unsigned a2, unsigned a3,
                                        unsigned b0, unsigned b1) {
    asm volatile(
        "mma.sync.aligned.m16n8k16.row.col.f32.f16.f16.f32 "
        "{%0,%1,%2,%3}, {%4,%5,%6,%7}, {%8,%9}, {%0,%1,%2,%3};"
        : "+f"(d0), "+f"(d1), "+f"(d2), "+f"(d3)
        : "r"(a0), "r"(a1), "r"(a2), "r"(a3), "r"(b0), "r"(b1));
}
// fp16 two-term split of two fp32 values, packed
__device__ __forceinline__ void split2h(float a, float b, unsigned& hi, unsigned& lo) {
    __half ah = __float2half_rn(a), bh = __float2half_rn(b);
    __half al = __float2half_rn(a - __half2float(ah));
    __half bl = __float2half_rn(b - __half2float(bh));
    hi = (unsigned)__half_as_ushort(ah) | ((unsigned)__half_as_ushort(bh) << 16);
    lo = (unsigned)__half_as_ushort(al) | ((unsigned)__half_as_ushort(bl) << 16);
}
__device__ __forceinline__ float elu_f(float v)   { return v > 0.f ? v : expm1f(v); }
__device__ __forceinline__ float lrelu_f(float v) { return v > 0.f ? v : 0.01f * v; }

// ---------------- smem layout (bytes) ----------------
#define AHI    0
#define ALO    10240
#define BSM    20480
#define BUFSZ  30720
#define NODE_BIAS 61440
#define NODE_SMEM (61440 + 2048)
#define ESRC     61440
#define EDST     61952
#define EBIAS    62464
#define EATTN    62976
#define EDGE_SMEM 63488

// ---------------- small kernels ----------------
__global__ void k_embed(const int* __restrict__ node_types,
                        const float* __restrict__ embed, float* __restrict__ nf) {
    int i = blockIdx.x * 256 + threadIdx.x;
    if (i < NN * 128) {
        int n = i >> 7, c = i & 127;
        nf[(size_t)n * 128 + c] = embed[node_types[n] * 128 + c];
    }
}

__global__ void k_prep(const float* __restrict__ Wni, const float* __restrict__ Wnj,
                       const float* __restrict__ Wsrc, const float* __restrict__ bsrc,
                       const float* __restrict__ Wfij,
                       float* __restrict__ bcat,
                       __half* __restrict__ btn, __half* __restrict__ bte,
                       int in_n, int in_e) {
    int i = blockIdx.x * 256 + threadIdx.x;
    int nn = 512 * in_n;
    if (i < nn) {
        int n = i / in_n, k = i - n * in_n;
        float v;
        if (n < 128)      v = Wni[k * 128 + n];
        else if (n < 256) v = Wnj[k * 128 + (n - 128)];
        else              v = Wsrc[k * 256 + (n - 256)];
        btn[(size_t)n * in_n + k] = __float2half_rn(v);
    } else if (i < nn + 128 * in_e) {
        int j = i - nn;
        int n = j / in_e, k = j - n * in_e;
        bte[(size_t)n * in_e + k] = __float2half_rn(Wfij[k * 128 + n]);
    }
    if (i < 512) bcat[i] = (i < 256) ? 0.f : bsrc[i - 256];
}

// ---------------- CSR build ----------------
__global__ void k_zero_deg(int* __restrict__ deg) {
    int i = blockIdx.x * 256 + threadIdx.x;
    if (i < NN) deg[i] = 0;
}
__global__ void k_hist(const int* __restrict__ dst, int* __restrict__ deg) {
    int e = blockIdx.x * 256 + threadIdx.x;
    if (e < EE) atomicAdd(&deg[dst[e]], 1);
}
__global__ void k_scanA(const int* __restrict__ deg, int* __restrict__ bsum) {
    __shared__ int sh[256];
    int i = blockIdx.x * 256 + threadIdx.x;
    sh[threadIdx.x] = (i < NN) ? deg[i] : 0;
    __syncthreads();
    for (int o = 128; o > 0; o >>= 1) {
        if (threadIdx.x < o) sh[threadIdx.x] += sh[threadIdx.x + o];
        __syncthreads();
    }
    if (threadIdx.x == 0) bsum[blockIdx.x] = sh[0];
}
__global__ void k_scanB(int* __restrict__ bsum) {
    __shared__ int sh[256];
    int t = threadIdx.x;
    int v = (t < NB_SCAN) ? bsum[t] : 0;
    sh[t] = v;
    __syncthreads();
    for (int o = 1; o < 256; o <<= 1) {
        int add = (t >= o) ? sh[t - o] : 0;
        __syncthreads();
        sh[t] += add;
        __syncthreads();
    }
    if (t < NB_SCAN) bsum[t] = sh[t] - v;
}
__global__ void k_scanC(const int* __restrict__ deg, const int* __restrict__ bsum,
                        int* __restrict__ offs, int* __restrict__ cursor) {
    __shared__ int sh[256];
    int i = blockIdx.x * 256 + threadIdx.x;
    int t = threadIdx.x;
    int v = (i < NN) ? deg[i] : 0;
    sh[t] = v;
    __syncthreads();
    for (int o = 1; o < 256; o <<= 1) {
        int add = (t >= o) ? sh[t - o] : 0;
        __syncthreads();
        sh[t] += add;
        __syncthreads();
    }
    if (i < NN) {
        int ex = bsum[blockIdx.x] + sh[t] - v;
        offs[i] = ex;
        cursor[i] = ex;
    }
    if (i == 0) offs[NN] = EE;
}
__global__ void k_scatter(const int* __restrict__ dst, int* __restrict__ cursor,
                          int* __restrict__ eidx) {
    int e = blockIdx.x * 256 + threadIdx.x;
    if (e < EE) {
        int pos = atomicAdd(&cursor[dst[e]], 1);
        eidx[pos] = e;
    }
}

// ---------------- GEMM mainloops ----------------
__device__ __forceinline__ void b_cpasync(uint32_t sb, int buf,
                                          const __half* __restrict__ Bt,
                                          int n0, int K, int k0) {
    int tid = threadIdx.x;
#pragma unroll
    for (int i = 0; i < 2; i++) {
        int c = tid + i * 256;
        int n = c >> 2, k16 = c & 3;
        size_t go = (size_t)(n0 + n) * K + k0 + k16 * 8;
        CP_ASYNC16(sb + buf * BUFSZ + BSM + n * 80 + k16 * 16, Bt + go);
    }
}

__device__ __forceinline__ void a_convert_sts(uint32_t sb, int buf, int r, int hk,
                                              const float4 pa[4]) {
    uint32_t ah = sb + buf * BUFSZ + AHI + r * 80 + hk * 32;
    uint32_t al = ah + (ALO - AHI);
#pragma unroll
    for (int q = 0; q < 2; q++) {
        unsigned h0, l0, h1, l1, h2, l2, h3, l3;
        split2h(pa[2 * q].x,     pa[2 * q].y,     h0, l0);
        split2h(pa[2 * q].z,     pa[2 * q].w,     h1, l1);
        split2h(pa[2 * q + 1].x, pa[2 * q + 1].y, h2, l2);
        split2h(pa[2 * q + 1].z, pa[2 * q + 1].w, h3, l3);
        sts128(ah + q * 16, make_uint4(h0, h1, h2, h3));
        sts128(al + q * 16, make_uint4(l0, l1, l2, l3));
    }
}

template <int NPASS>
__device__ __forceinline__ void mma_compute(uint32_t sb, int buf, float acc[2][8][4]) {
    int tid = threadIdx.x, lane = tid & 31, wid = tid >> 5;
    int wm = wid & 3, wn = wid >> 2;
    uint32_t bo = sb + buf * BUFSZ;
    uint32_t aAddr = bo + AHI + (wm * 32 + (lane & 15)) * 80 + ((lane & 16) ? 16 : 0);
    uint32_t bAddr = bo + BSM + (wn * 64 + ((lane & 16) ? 8 : 0) + (lane & 7)) * 80 +
                     ((lane & 8) ? 16 : 0);
#pragma unroll
    for (int ks = 0; ks < 2; ks++) {
        unsigned ahr[2][4], alr[2][4];
#pragma unroll
        for (int mt = 0; mt < 2; mt++) {
            uint32_t aa = aAddr + mt * 1280 + ks * 32;
            ldsm_x4(ahr[mt][0], ahr[mt][1], ahr[mt][2], ahr[mt][3], aa);
            if (NPASS == 2)
                ldsm_x4(alr[mt][0], alr[mt][1], alr[mt][2], alr[mt][3], aa + (ALO - AHI));
        }
#pragma unroll
        for (int p = 0; p < 4; p++) {
            uint32_t ba = bAddr + p * 1280 + ks * 32;
            unsigned bh[4];
            ldsm_x4(bh[0], bh[1], bh[2], bh[3], ba);
#pragma unroll
            for (int sub = 0; sub < 2; sub++) {
                int nt = p * 2 + sub;
                unsigned b0 = bh[sub * 2], b1 = bh[sub * 2 + 1];
#pragma unroll
                for (int mt = 0; mt < 2; mt++) {
                    float* d = acc[mt][nt];
                    mma_f16(d[0], d[1], d[2], d[3],
                            ahr[mt][0], ahr[mt][1], ahr[mt][2], ahr[mt][3], b0, b1);
                    if (NPASS == 2)
                        mma_f16(d[0], d[1], d[2], d[3],
                                alr[mt][0], alr[mt][1], alr[mt][2], alr[mt][3], b0, b1);
                }
            }
        }
    }
}

// 2-pass mainloop: fp32 A, register fetch + fp16 hi/lo split
__device__ __forceinline__ void mma_mainloop(
    uint32_t sb, const float* __restrict__ A, const __half* __restrict__ Bt,
    int row0, int n0, int M, int K, float acc[2][8][4]) {
    int tid = threadIdx.x;
    int r = tid >> 1, hk = tid & 1;
    int arow = row0 + r;
    bool aval = arow < M;
    const float* abase = A + (size_t)arow * K + hk * 16;
    int nst = K >> 5;

    float4 pa[4];
    const float4 z4 = make_float4(0.f, 0.f, 0.f, 0.f);
#pragma unroll
    for (int q = 0; q < 4; q++) pa[q] = aval ? *(const float4*)(abase + q * 4) : z4;
    b_cpasync(sb, 0, Bt, n0, K, 0);
    CP_COMMIT();
    a_convert_sts(sb, 0, r, hk, pa);
    CP_WAIT0();
    __syncthreads();

    for (int s = 0; s < nst; s++) {
        int buf = s & 1, nb = buf ^ 1;
        bool more = (s + 1) < nst;
        if (more) {
            b_cpasync(sb, nb, Bt, n0, K, (s + 1) * 32);
            CP_COMMIT();
            const float* ap = abase + (s + 1) * 32;
#pragma unroll
            for (int q = 0; q < 4; q++) pa[q] = aval ? *(const float4*)(ap + q * 4) : z4;
        }
        mma_compute<2>(sb, buf, acc);
        if (more) {
            a_convert_sts(sb, nb, r, hk, pa);
            CP_WAIT0();
        }
        __syncthreads();
    }
}

// 1-pass mainloop: fp16 A, all-cp.async
__device__ __forceinline__ void tile_load1(uint32_t sb, int buf,
                                           const __half* __restrict__ A, int row0, int M,
                                           const __half* __restrict__ Bt, int n0,
                                           int K, int k0) {
    int tid = threadIdx.x;
    uint32_t bo = sb + buf * BUFSZ;
#pragma unroll
    for (int i = 0; i < 2; i++) {
        int c = tid + i * 256;
        int r = c >> 2, k16 = c & 3;
        int arow = row0 + r;
        CP_ASYNC16Z(bo + AHI + r * 80 + k16 * 16,
                    A + (size_t)arow * K + k0 + k16 * 8, arow < M);
        CP_ASYNC16(bo + BSM + r * 80 + k16 * 16,
                   Bt + (size_t)(n0 + r) * K + k0 + k16 * 8);
    }
}

__device__ __forceinline__ void mma_mainloop(
    uint32_t sb, const __half* __restrict__ A, const __half* __restrict__ Bt,
    int row0, int n0, int M, int K, float acc[2][8][4]) {
    int nst = K >> 5;
    tile_load1(sb, 0, A, row0, M, Bt, n0, K, 0);
    CP_COMMIT();
    CP_WAIT0();
    __syncthreads();
    for (int s = 0; s < nst; s++) {
        int buf = s & 1;
        bool more = (s + 1) < nst;
        if (more) {
            tile_load1(sb, buf ^ 1, A, row0, M, Bt, n0, K, (s + 1) * 32);
            CP_COMMIT();
        }
        mma_compute<1>(sb, buf, acc);
        if (more) CP_WAIT0();
        __syncthreads();
    }
}

// ---------------- node GEMM: fp16 f_ni/f_nj + fp16 h_src ----------------
__global__ __launch_bounds__(256, 2) void gemm_node_mma(
    const float* __restrict__ A, const __half* __restrict__ Bt,
    const float* __restrict__ bias, __half* __restrict__ nodeh,
    __half* __restrict__ hsrc, int M, int K) {
    extern __shared__ __align__(16) char smem[];
    uint32_t sb = smem_u32(smem);
    float* bsm = (float*)(smem + NODE_BIAS);
    int tid = threadIdx.x;
    ((float2*)bsm)[tid] = ((const float2*)bias)[tid];

    int row0 = blockIdx.x * 128, n0 = blockIdx.y * 128;
    float acc[2][8][4];
#pragma unroll
    for (int mt = 0; mt < 2; mt++)
#pragma unroll
        for (int nt = 0; nt < 8; nt++)
#pragma unroll
            for (int q = 0; q < 4; q++) acc[mt][nt][q] = 0.f;

    mma_mainloop(sb, A, Bt, row0, n0, M, K, acc);

    int lane = tid & 31, wid = tid >> 5;
    int g = lane >> 2, tig = lane & 3;
    int wm = wid & 3, wn = wid >> 2;
    bool to_hsrc = n0 >= 256;
    __half* outp = to_hsrc ? hsrc : nodeh;
    int cbase = to_hsrc ? 256 : 0;
#pragma unroll
    for (int mt = 0; mt < 2; mt++) {
        int r0 = row0 + wm * 32 + mt * 16 + g;
#pragma unroll
        for (int nt = 0; nt < 8; nt++) {
            int cc = n0 + wn * 64 + nt * 8 + 2 * tig;
            float b0 = bsm[cc], b1 = bsm[cc + 1];
            float* d = acc[mt][nt];
            int hc = cc - cbase;
            if (r0 < M)
                *(__half2*)(outp + (size_t)r0 * 256 + hc) =
                    __floats2half2_rn(d[0] + b0, d[1] + b1);
            if (r0 + 8 < M)
                *(__half2*)(outp + (size_t)(r0 + 8) * 256 + hc) =
                    __floats2half2_rn(d[2] + b0, d[3] + b1);
        }
    }
}

// ---------------- edge GEMM: direct-from-fragment fused epilogue ----------------
template <typename AT, int EFHALF>
__global__ __launch_bounds__(256, 2) void gemm_edge_mma(
    const AT* __restrict__ A, const __half* __restrict__ Bt,
    const __half* __restrict__ nodeh,
    const int* __restrict__ src, const int* __restrict__ dst,
    const float* __restrict__ bias, const float* __restrict__ attn,
    float* __restrict__ ef32, __half* __restrict__ efh,
    float* __restrict__ elog, int M, int K) {
    extern __shared__ __align__(16) char smem[];
    uint32_t sb = smem_u32(smem);
    int*   ssh = (int*)(smem + ESRC);
    int*   dsh = (int*)(smem + EDST);
    float* bsh = (float*)(smem + EBIAS);
    float* ash = (float*)(smem + EATTN);

    int tid = threadIdx.x;
    int e0 = blockIdx.x * 128;
    if (tid < 128) {
        int e = e0 + tid;
        ssh[tid] = (e < M) ? src[e] : 0;
        dsh[tid] = (e < M) ? dst[e] : 0;
        bsh[tid] = bias[tid];
        ash[tid] = attn[tid];
    }

    float acc[2][8][4];
#pragma unroll
    for (int mt = 0; mt < 2; mt++)
#pragma unroll
        for (int nt = 0; nt < 8; nt++)
#pragma unroll
            for (int q = 0; q < 4; q++) acc[mt][nt][q] = 0.f;

    mma_mainloop(sb, A, Bt, e0, 0, M, K, acc);

    int lane = tid & 31, wid = tid >> 5;
    int g = lane >> 2, tig = lane & 3;
    int wm = wid & 3, wn = wid >> 2;

#pragma unroll
    for (int mt = 0; mt < 2; mt++) {
        int r = wm * 32 + mt * 16 + g;
        int rA = r, rB = r + 8;
        int eA = e0 + rA, eB = e0 + rB;
        int siA = ssh[rA], djA = dsh[rA];
        int siB = ssh[rB], djB = dsh[rB];
        const __half* niA = nodeh + (size_t)siA * 256;
        const __half* njA = nodeh + (size_t)djA * 256 + 128;
        const __half* niB = nodeh + (size_t)siB * 256;
        const __half* njB = nodeh + (size_t)djB * 256 + 128;
        float partA[2] = {0.f, 0.f};
        float partB[2] = {0.f, 0.f};
#pragma unroll
        for (int nt = 0; nt < 8; nt++) {
            int cc = wn * 64 + nt * 8 + 2 * tig;
            int hl = nt >> 2;
            float b0 = bsh[cc], b1 = bsh[cc + 1];
            float a0 = ash[cc], a1 = ash[cc + 1];
            float2 nA0 = __half22float2(*(const __half2*)(niA + cc));
            float2 nA1 = __half22float2(*(const __half2*)(njA + cc));
            float2 nB0 = __half22float2(*(const __half2*)(niB + cc));
            float2 nB1 = __half22float2(*(const __half2*)(njB + cc));
            float* d = acc[mt][nt];
            float v0 = lrelu_f(d[0] + nA0.x + nA1.x + b0);
            float v1 = lrelu_f(d[1] + nA0.y + nA1.y + b1);
            partA[hl] += v0 * a0 + v1 * a1;
            float e0v = elu_f(v0), e1v = elu_f(v1);
            if (eA < M) {
                if (EFHALF)
                    *(__half2*)(efh + (size_t)eA * 128 + cc) = __floats2half2_rn(e0v, e1v);
                else
                    *(float2*)(ef32 + (size_t)eA * 128 + cc) = make_float2(e0v, e1v);
            }
            float w0 = lrelu_f(d[2] + nB0.x + nB1.x + b0);
            float w1 = lrelu_f(d[3] + nB0.y + nB1.y + b1);
            partB[hl] += w0 * a0 + w1 * a1;
            float f0v = elu_f(w0), f1v = elu_f(w1);
            if (eB < M) {
                if (EFHALF)
                    *(__half2*)(efh + (size_t)eB * 128 + cc) = __floats2half2_rn(f0v, f1v);
                else
                    *(float2*)(ef32 + (size_t)eB * 128 + cc) = make_float2(f0v, f1v);
            }
        }
#pragma unroll
        for (int o = 1; o <= 2; o <<= 1) {
            partA[0] += __shfl_xor_sync(0xFFFFFFFFu, partA[0], o);
            partA[1] += __shfl_xor_sync(0xFFFFFFFFu, partA[1], o);
            partB[0] += __shfl_xor_sync(0xFFFFFFFFu, partB[0], o);
            partB[1] += __shfl_xor_sync(0xFFFFFFFFu, partB[1], o);
        }
        if (tig == 0) {
            int h0 = wn * 2, h1 = wn * 2 + 1;
            if (eA < M) {
                elog[(size_t)eA * 4 + h0] = partA[0];
                elog[(size_t)eA * 4 + h1] = partA[1];
            }
            if (eB < M) {
                elog[(size_t)eB * 4 + h0] = partB[0];
                elog[(size_t)eB * 4 + h1] = partB[1];
            }
        }
    }
}

// ---------------- CSR aggregation (fp16 h_src gather) ----------------
__global__ __launch_bounds__(256) void k_aggr(
    const int* __restrict__ srcs, const int* __restrict__ eidx,
    const int* __restrict__ offs, const float* __restrict__ elog,
    const __half* __restrict__ hsrc, float* __restrict__ outp) {
    int node = (blockIdx.x * 256 + threadIdx.x) >> 5;
    int lane = threadIdx.x & 31;
    if (node >= NN) return;
    int beg = offs[node], end = offs[node + 1];

    float4 mx = make_float4(-1e30f, -1e30f, -1e30f, -1e30f);
    for (int j = beg + lane; j < end; j += 32) {
        int e = eidx[j];
        float4 l = *(const float4*)(elog + (size_t)e * 4);
        mx.x = fmaxf(mx.x, l.x); mx.y = fmaxf(mx.y, l.y);
        mx.z = fmaxf(mx.z, l.z); mx.w = fmaxf(mx.w, l.w);
    }
#pragma unroll
    for (int o = 16; o > 0; o >>= 1) {
        mx.x = fmaxf(mx.x, __shfl_xor_sync(0xFFFFFFFFu, mx.x, o));
        mx.y = fmaxf(mx.y, __shfl_xor_sync(0xFFFFFFFFu, mx.y, o));
        mx.z = fmaxf(mx.z, __shfl_xor_sync(0xFFFFFFFFu, mx.z, o));
        mx.w = fmaxf(mx.w, __shfl_xor_sync(0xFFFFFFFFu, mx.w, o));
    }
    int h = lane >> 3;
    float mh = (h == 0) ? mx.x : (h == 1) ? mx.y : (h == 2) ? mx.z : mx.w;

    float acc[8] = {0.f, 0.f, 0.f, 0.f, 0.f, 0.f, 0.f, 0.f};
    float ssum = 0.f;
    int j = beg;
    for (; j + 1 < end; j += 2) {
        int ea = eidx[j], eb = eidx[j + 1];
        int sa = srcs[ea], sbn = srcs[eb];
        float la = elog[(size_t)ea * 4 + h], lb = elog[(size_t)eb * 4 + h];
        uint4 ra = *((const uint4*)(hsrc + (size_t)sa * 256) + lane);
        uint4 rb = *((const uint4*)(hsrc + (size_t)sbn * 256) + lane);
        float wa = expf(la - mh), wb = expf(lb - mh);
        ssum += wa + wb;
        float2 t;
        t = __half22float2(*(__half2*)&ra.x); acc[0] += wa * t.x; acc[1] += wa * t.y;
        t = __half22float2(*(__half2*)&ra.y); acc[2] += wa * t.x; acc[3] += wa * t.y;
        t = __half22float2(*(__half2*)&ra.z); acc[4] += wa * t.x; acc[5] += wa * t.y;
        t = __half22float2(*(__half2*)&ra.w); acc[6] += wa * t.x; acc[7] += wa * t.y;
        t = __half22float2(*(__half2*)&rb.x); acc[0] += wb * t.x; acc[1] += wb * t.y;
        t = __half22float2(*(__half2*)&rb.y); acc[2] += wb * t.x; acc[3] += wb * t.y;
        t = __half22float2(*(__half2*)&rb.z); acc[4] += wb * t.x; acc[5] += wb * t.y;
        t = __half22float2(*(__half2*)&rb.w); acc[6] += wb * t.x; acc[7] += wb * t.y;
    }
    if (j < end) {
        int e = eidx[j];
        float w = expf(elog[(size_t)e * 4 + h] - mh);
        ssum += w;
        uint4 ra = *((const uint4*)(hsrc + (size_t)srcs[e] * 256) + lane);
        float2 t;
        t = __half22float2(*(__half2*)&ra.x); acc[0] += w * t.x; acc[1] += w * t.y;
        t = __half22float2(*(__half2*)&ra.y); acc[2] += w * t.x; acc[3] += w * t.y;
        t = __half22float2(*(__half2*)&ra.z); acc[4] += w * t.x; acc[5] += w * t.y;
        t = __half22float2(*(__half2*)&ra.w); acc[6] += w * t.x; acc[7] += w * t.y;
    }
    float inv = (end > beg) ? 1.f / ssum : 0.f;
    float* op = outp + (size_t)node * 256 + lane * 8;
    float4 o0, o1;
    o0.x = elu_f(acc[0] * inv); o0.y = elu_f(acc[1] * inv);
    o0.z = elu_f(acc[2] * inv); o0.w = elu_f(acc[3] * inv);
    o1.x = elu_f(acc[4] * inv); o1.y = elu_f(acc[5] * inv);
    o1.z = elu_f(acc[6] * inv); o1.w = elu_f(acc[7] * inv);
    *(float4*)op = o0;
    *(float4*)(op + 4) = o1;
}

// ---------------- host ----------------
extern "C" void kernel_launch(void* const* d_in, const int* in_sizes, int n_in,
                              void* d_out, int out_size) {
    const int*   node_types = (const int*)d_in[0];
    const int*   src        = (const int*)d_in[1];
    const int*   dst        = (const int*)d_in[2];
    const float* efeats     = (const float*)d_in[3];
    const float* embed      = (const float*)d_in[4];
    const float* W_src[2] = {(const float*)d_in[5],  (const float*)d_in[12]};
    const float* b_src[2] = {(const float*)d_in[6],  (const float*)d_in[13]};
    const float* W_ni[2]  = {(const float*)d_in[7],  (const float*)d_in[14]};
    const float* W_nj[2]  = {(const float*)d_in[8],  (const float*)d_in[15]};
    const float* W_fij[2] = {(const float*)d_in[9],  (const float*)d_in[16]};
    const float* attn[2]  = {(const float*)d_in[10], (const float*)d_in[17]};
    const float* bias[2]  = {(const float*)d_in[11], (const float*)d_in[18]};

    float *nf, *elog, *bcat;
    __half *nodeh, *hsrc, *efh, *btn, *bte;
    int *deg, *offs, *cursor, *eidx, *bsum;
    cudaGetSymbolAddress((void**)&nf, g_nf);
    cudaGetSymbolAddress((void**)&nodeh, g_nodeh);
    cudaGetSymbolAddress((void**)&hsrc, g_hsrc);
    cudaGetSymbolAddress((void**)&efh, g_efh);
    cudaGetSymbolAddress((void**)&elog, g_elog);
    cudaGetSymbolAddress((void**)&bcat, g_bcat);
    cudaGetSymbolAddress((void**)&btn, g_btn);
    cudaGetSymbolAddress((void**)&bte, g_bte);
    cudaGetSymbolAddress((void**)&deg, g_deg);
    cudaGetSymbolAddress((void**)&offs, g_offs);
    cudaGetSymbolAddress((void**)&cursor, g_cursor);
    cudaGetSymbolAddress((void**)&eidx, g_eidx);
    cudaGetSymbolAddress((void**)&bsum, g_bsum);

    cudaFuncSetAttribute(gemm_node_mma, cudaFuncAttributeMaxDynamicSharedMemorySize, NODE_SMEM);
    cudaFuncSetAttribute((const void*)gemm_edge_mma<float, 1>,
                         cudaFuncAttributeMaxDynamicSharedMemorySize, EDGE_SMEM);
    cudaFuncSetAttribute((const void*)gemm_edge_mma<__half, 0>,
                         cudaFuncAttributeMaxDynamicSharedMemorySize, EDGE_SMEM);

    float* out_nf = (float*)d_out;
    float* out_ef = out_nf + (size_t)NN * 256;

    k_embed<<<(NN * 128 + 255) / 256, 256>>>(node_types, embed, nf);

    // CSR by dst (edges identical across layers)
    k_zero_deg<<<NB_SCAN, 256>>>(deg);
    k_hist<<<(EE + 255) / 256, 256>>>(dst, deg);
    k_scanA<<<NB_SCAN, 256>>>(deg, bsum);
    k_scanB<<<1, 256>>>(bsum);
    k_scanC<<<NB_SCAN, 256>>>(deg, bsum, offs, cursor);
    k_scatter<<<(EE + 255) / 256, 256>>>(dst, cursor, eidx);

    for (int L = 0; L < 2; L++) {
        int in_n = L ? 256 : 128;
        int in_e = L ? 128 : 64;
        int prep_items = 512 * in_n + 128 * in_e;
        k_prep<<<(prep_items + 255) / 256, 256>>>(W_ni[L], W_nj[L], W_src[L], b_src[L],
                                                  W_fij[L], bcat, btn, bte, in_n, in_e);

        dim3 gn((NN + 127) / 128, 4);
        gemm_node_mma<<<gn, 256, NODE_SMEM>>>(nf, btn, bcat, nodeh, hsrc, NN, in_n);

        if (L == 0) {
            gemm_edge_mma<float, 1><<<(EE + 127) / 128, 256, EDGE_SMEM>>>(
                efeats, bte, nodeh, src, dst, bias[L], attn[L],
                nullptr, efh, elog, EE, in_e);
        } else {
            gemm_edge_mma<__half, 0><<<(EE + 127) / 128, 256, EDGE_SMEM>>>(
                efh, bte, nodeh, src, dst, bias[L], attn[L],
                out_ef, nullptr, elog, EE, in_e);
        }

        float* nf_out = L ? out_nf : nf;
        k_aggr<<<(NN * 32 + 255) / 256, 256>>>(src, eidx, offs, elog, hsrc, nf_out);
    }
}

// round 15
// speedup vs baseline: 1.9946x; 1.0837x over previous
#include <cuda_runtime.h>
#include <cuda_fp16.h>
#include <math.h>
#include <stdint.h>

#define NN 50000
#define EE 500000
#define NB_SCAN ((NN + 255) / 256)   // 196

// ---------------- scratch ----------------
__device__ __half   g_nfh[(size_t)NN * 256];       // node features fp16 (stride 128 L0 / 256 L1)
__device__ __half   g_nodeh[(size_t)NN * 256];     // [f_ni(128) | f_nj(128)] fp16
__device__ __half   g_hsrc[(size_t)NN * 256];      // h_src fp16
__device__ __half   g_efa[(size_t)EE * 64];        // efeats fp16
__device__ __half   g_efh[(size_t)EE * 128];       // layer-0 ef intermediate fp16
__device__ float    g_elog[(size_t)EE * 4];
__device__ float    g_bcat[512];
__device__ __half   g_btn[512 * 256];              // node weights fp16, [n][k]
__device__ __half   g_bte[128 * 128];              // edge weights fp16, [n][k]
// CSR by dst
__device__ int g_deg[NN];
__device__ int g_offs[NN + 1];
__device__ int g_cursor[NN];
__device__ int g_eidx[EE];
__device__ int g_bsum[256];

// ---------------- helpers ----------------
__device__ __forceinline__ uint32_t smem_u32(const void* p) {
    uint32_t a;
    asm("{ .reg .u64 t; cvta.to.shared.u64 t, %1; cvt.u32.u64 %0, t; }" : "=r"(a) : "l"(p));
    return a;
}
__device__ __forceinline__ void ldsm_x4(unsigned& r0, unsigned& r1, unsigned& r2,
                                        unsigned& r3, uint32_t addr) {
    asm volatile("ldmatrix.sync.aligned.m8n8.x4.shared.b16 {%0,%1,%2,%3}, [%4];"
                 : "=r"(r0), "=r"(r1), "=r"(r2), "=r"(r3) : "r"(addr));
}
#define CP_ASYNC16(dst, src) \
    asm volatile("cp.async.ca.shared.global [%0], [%1], 16;" :: "r"(dst), "l"(src) : "memory")
#define CP_ASYNC16Z(dst, src, pred) \
    asm volatile("cp.async.ca.shared.global [%0], [%1], 16, %2;" \
                 :: "r"(dst), "l"(src), "r"((pred) ? 16 : 0) : "memory")
#define CP_COMMIT() asm volatile("cp.async.commit_group;" ::: "memory")
#define CP_WAIT0()  asm volatile("cp.async.wait_group 0;" ::: "memory")

__device__ __forceinline__ void mma_f16(float& d0, float& d1, float& d2, float& d3,
                                        unsigned a0, unsigned a1, unsigned a2, unsigned a3,
                                        unsigned b0, unsigned b1) {
    asm volatile(
        "mma.sync.aligned.m16n8k16.row.col.f32.f16.f16.f32 "
        "{%0,%1,%2,%3}, {%4,%5,%6,%7}, {%8,%9}, {%0,%1,%2,%3};"
        : "+f"(d0), "+f"(d1), "+f"(d2), "+f"(d3)
        : "r"(a0), "r"(a1), "r"(a2), "r"(a3), "r"(b0), "r"(b1));
}
__device__ __forceinline__ float elu_f(float v)   { return v > 0.f ? v : expm1f(v); }
__device__ __forceinline__ float lrelu_f(float v) { return v > 0.f ? v : 0.01f * v; }

// ---------------- smem layout (bytes) ----------------
#define ASM    0
#define BSM    10240
#define BUFSZ  20480
#define NODE_BIAS 40960
#define NODE_SMEM (40960 + 2048)
#define ESRC     40960
#define EDST     41472
#define EBIAS    41984
#define EATTN    42496
#define EDGE_SMEM 43008

// ---------------- small kernels ----------------
__global__ void k_embed(const int* __restrict__ node_types,
                        const float* __restrict__ embed, __half* __restrict__ nfh) {
    int i = blockIdx.x * 256 + threadIdx.x;
    if (i < NN * 32) {
        int n = i >> 5, c4 = (i & 31) * 4;
        float4 v = *(const float4*)(embed + node_types[n] * 128 + c4);
        __half2 h0 = __floats2half2_rn(v.x, v.y);
        __half2 h1 = __floats2half2_rn(v.z, v.w);
        *(uint2*)(nfh + (size_t)n * 128 + c4) =
            make_uint2(*(unsigned*)&h0, *(unsigned*)&h1);
    }
}

__global__ void k_half(const float* __restrict__ in, __half* __restrict__ out, int n4) {
    int i = blockIdx.x * 256 + threadIdx.x;
    if (i < n4) {
        float4 v = *(const float4*)(in + (size_t)i * 4);
        __half2 h0 = __floats2half2_rn(v.x, v.y);
        __half2 h1 = __floats2half2_rn(v.z, v.w);
        *(uint2*)(out + (size_t)i * 4) = make_uint2(*(unsigned*)&h0, *(unsigned*)&h1);
    }
}

__global__ void k_prep(const float* __restrict__ Wni, const float* __restrict__ Wnj,
                       const float* __restrict__ Wsrc, const float* __restrict__ bsrc,
                       const float* __restrict__ Wfij,
                       float* __restrict__ bcat,
                       __half* __restrict__ btn, __half* __restrict__ bte,
                       int in_n, int in_e) {
    int i = blockIdx.x * 256 + threadIdx.x;
    int nn = 512 * in_n;
    if (i < nn) {
        int n = i / in_n, k = i - n * in_n;
        float v;
        if (n < 128)      v = Wni[k * 128 + n];
        else if (n < 256) v = Wnj[k * 128 + (n - 128)];
        else              v = Wsrc[k * 256 + (n - 256)];
        btn[(size_t)n * in_n + k] = __float2half_rn(v);
    } else if (i < nn + 128 * in_e) {
        int j = i - nn;
        int n = j / in_e, k = j - n * in_e;
        bte[(size_t)n * in_e + k] = __float2half_rn(Wfij[k * 128 + n]);
    }
    if (i < 512) bcat[i] = (i < 256) ? 0.f : bsrc[i - 256];
}

// ---------------- CSR build ----------------
__global__ void k_zero_deg(int* __restrict__ deg) {
    int i = blockIdx.x * 256 + threadIdx.x;
    if (i < NN) deg[i] = 0;
}
__global__ void k_hist(const int* __restrict__ dst, int* __restrict__ deg) {
    int e = blockIdx.x * 256 + threadIdx.x;
    if (e < EE) atomicAdd(&deg[dst[e]], 1);
}
__global__ void k_scanA(const int* __restrict__ deg, int* __restrict__ bsum) {
    __shared__ int sh[256];
    int i = blockIdx.x * 256 + threadIdx.x;
    sh[threadIdx.x] = (i < NN) ? deg[i] : 0;
    __syncthreads();
    for (int o = 128; o > 0; o >>= 1) {
        if (threadIdx.x < o) sh[threadIdx.x] += sh[threadIdx.x + o];
        __syncthreads();
    }
    if (threadIdx.x == 0) bsum[blockIdx.x] = sh[0];
}
__global__ void k_scanB(int* __restrict__ bsum) {
    __shared__ int sh[256];
    int t = threadIdx.x;
    int v = (t < NB_SCAN) ? bsum[t] : 0;
    sh[t] = v;
    __syncthreads();
    for (int o = 1; o < 256; o <<= 1) {
        int add = (t >= o) ? sh[t - o] : 0;
        __syncthreads();
        sh[t] += add;
        __syncthreads();
    }
    if (t < NB_SCAN) bsum[t] = sh[t] - v;
}
__global__ void k_scanC(const int* __restrict__ deg, const int* __restrict__ bsum,
                        int* __restrict__ offs, int* __restrict__ cursor) {
    __shared__ int sh[256];
    int i = blockIdx.x * 256 + threadIdx.x;
    int t = threadIdx.x;
    int v = (i < NN) ? deg[i] : 0;
    sh[t] = v;
    __syncthreads();
    for (int o = 1; o < 256; o <<= 1) {
        int add = (t >= o) ? sh[t - o] : 0;
        __syncthreads();
        sh[t] += add;
        __syncthreads();
    }
    if (i < NN) {
        int ex = bsum[blockIdx.x] + sh[t] - v;
        offs[i] = ex;
        cursor[i] = ex;
    }
    if (i == 0) offs[NN] = EE;
}
__global__ void k_scatter(const int* __restrict__ dst, int* __restrict__ cursor,
                          int* __restrict__ eidx) {
    int e = blockIdx.x * 256 + threadIdx.x;
    if (e < EE) {
        int pos = atomicAdd(&cursor[dst[e]], 1);
        eidx[pos] = e;
    }
}

// ---------------- 1-pass fp16 GEMM mainloop ----------------
__device__ __forceinline__ void tile_load1(uint32_t sb, int buf,
                                           const __half* __restrict__ A, int row0, int M,
                                           const __half* __restrict__ Bt, int n0,
                                           int K, int k0) {
    int tid = threadIdx.x;
    uint32_t bo = sb + buf * BUFSZ;
#pragma unroll
    for (int i = 0; i < 2; i++) {
        int c = tid + i * 256;
        int r = c >> 2, k16 = c & 3;
        int arow = row0 + r;
        CP_ASYNC16Z(bo + ASM + r * 80 + k16 * 16,
                    A + (size_t)arow * K + k0 + k16 * 8, arow < M);
        CP_ASYNC16(bo + BSM + r * 80 + k16 * 16,
                   Bt + (size_t)(n0 + r) * K + k0 + k16 * 8);
    }
}

__device__ __forceinline__ void mma_compute(uint32_t sb, int buf, float acc[2][8][4]) {
    int tid = threadIdx.x, lane = tid & 31, wid = tid >> 5;
    int wm = wid & 3, wn = wid >> 2;
    uint32_t bo = sb + buf * BUFSZ;
    uint32_t aAddr = bo + ASM + (wm * 32 + (lane & 15)) * 80 + ((lane & 16) ? 16 : 0);
    uint32_t bAddr = bo + BSM + (wn * 64 + ((lane & 16) ? 8 : 0) + (lane & 7)) * 80 +
                     ((lane & 8) ? 16 : 0);
#pragma unroll
    for (int ks = 0; ks < 2; ks++) {
        unsigned ahr[2][4];
#pragma unroll
        for (int mt = 0; mt < 2; mt++) {
            uint32_t aa = aAddr + mt * 1280 + ks * 32;
            ldsm_x4(ahr[mt][0], ahr[mt][1], ahr[mt][2], ahr[mt][3], aa);
        }
#pragma unroll
        for (int p = 0; p < 4; p++) {
            uint32_t ba = bAddr + p * 1280 + ks * 32;
            unsigned bh[4];
            ldsm_x4(bh[0], bh[1], bh[2], bh[3], ba);
#pragma unroll
            for (int sub = 0; sub < 2; sub++) {
                int nt = p * 2 + sub;
                unsigned b0 = bh[sub * 2], b1 = bh[sub * 2 + 1];
#pragma unroll
                for (int mt = 0; mt < 2; mt++) {
                    float* d = acc[mt][nt];
                    mma_f16(d[0], d[1], d[2], d[3],
                            ahr[mt][0], ahr[mt][1], ahr[mt][2], ahr[mt][3], b0, b1);
                }
            }
        }
    }
}

__device__ __forceinline__ void mma_mainloop(
    uint32_t sb, const __half* __restrict__ A, const __half* __restrict__ Bt,
    int row0, int n0, int M, int K, float acc[2][8][4]) {
    int nst = K >> 5;
    tile_load1(sb, 0, A, row0, M, Bt, n0, K, 0);
    CP_COMMIT();
    CP_WAIT0();
    __syncthreads();
    for (int s = 0; s < nst; s++) {
        int buf = s & 1;
        bool more = (s + 1) < nst;
        if (more) {
            tile_load1(sb, buf ^ 1, A, row0, M, Bt, n0, K, (s + 1) * 32);
            CP_COMMIT();
        }
        mma_compute(sb, buf, acc);
        if (more) CP_WAIT0();
        __syncthreads();
    }
}

// ---------------- node GEMM: fp16 A, fp16 outputs ----------------
__global__ __launch_bounds__(256, 2) void gemm_node_mma(
    const __half* __restrict__ A, const __half* __restrict__ Bt,
    const float* __restrict__ bias, __half* __restrict__ nodeh,
    __half* __restrict__ hsrc, int M, int K) {
    extern __shared__ __align__(16) char smem[];
    uint32_t sb = smem_u32(smem);
    float* bsm = (float*)(smem + NODE_BIAS);
    int tid = threadIdx.x;
    ((float2*)bsm)[tid] = ((const float2*)bias)[tid];

    int row0 = blockIdx.x * 128, n0 = blockIdx.y * 128;
    float acc[2][8][4];
#pragma unroll
    for (int mt = 0; mt < 2; mt++)
#pragma unroll
        for (int nt = 0; nt < 8; nt++)
#pragma unroll
            for (int q = 0; q < 4; q++) acc[mt][nt][q] = 0.f;

    mma_mainloop(sb, A, Bt, row0, n0, M, K, acc);

    int lane = tid & 31, wid = tid >> 5;
    int g = lane >> 2, tig = lane & 3;
    int wm = wid & 3, wn = wid >> 2;
    bool to_hsrc = n0 >= 256;
    __half* outp = to_hsrc ? hsrc : nodeh;
    int cbase = to_hsrc ? 256 : 0;
#pragma unroll
    for (int mt = 0; mt < 2; mt++) {
        int r0 = row0 + wm * 32 + mt * 16 + g;
#pragma unroll
        for (int nt = 0; nt < 8; nt++) {
            int cc = n0 + wn * 64 + nt * 8 + 2 * tig;
            float b0 = bsm[cc], b1 = bsm[cc + 1];
            float* d = acc[mt][nt];
            int hc = cc - cbase;
            if (r0 < M)
                *(__half2*)(outp + (size_t)r0 * 256 + hc) =
                    __floats2half2_rn(d[0] + b0, d[1] + b1);
            if (r0 + 8 < M)
                *(__half2*)(outp + (size_t)(r0 + 8) * 256 + hc) =
                    __floats2half2_rn(d[2] + b0, d[3] + b1);
        }
    }
}

// ---------------- edge GEMM: direct-from-fragment fused epilogue ----------------
template <int EFHALF>
__global__ __launch_bounds__(256, 2) void gemm_edge_mma(
    const __half* __restrict__ A, const __half* __restrict__ Bt,
    const __half* __restrict__ nodeh,
    const int* __restrict__ src, const int* __restrict__ dst,
    const float* __restrict__ bias, const float* __restrict__ attn,
    float* __restrict__ ef32, __half* __restrict__ efh,
    float* __restrict__ elog, int M, int K) {
    extern __shared__ __align__(16) char smem[];
    uint32_t sb = smem_u32(smem);
    int*   ssh = (int*)(smem + ESRC);
    int*   dsh = (int*)(smem + EDST);
    float* bsh = (float*)(smem + EBIAS);
    float* ash = (float*)(smem + EATTN);

    int tid = threadIdx.x;
    int e0 = blockIdx.x * 128;
    if (tid < 128) {
        int e = e0 + tid;
        ssh[tid] = (e < M) ? src[e] : 0;
        dsh[tid] = (e < M) ? dst[e] : 0;
        bsh[tid] = bias[tid];
        ash[tid] = attn[tid];
    }

    float acc[2][8][4];
#pragma unroll
    for (int mt = 0; mt < 2; mt++)
#pragma unroll
        for (int nt = 0; nt < 8; nt++)
#pragma unroll
            for (int q = 0; q < 4; q++) acc[mt][nt][q] = 0.f;

    mma_mainloop(sb, A, Bt, e0, 0, M, K, acc);

    int lane = tid & 31, wid = tid >> 5;
    int g = lane >> 2, tig = lane & 3;
    int wm = wid & 3, wn = wid >> 2;

#pragma unroll
    for (int mt = 0; mt < 2; mt++) {
        int r = wm * 32 + mt * 16 + g;
        int rA = r, rB = r + 8;
        int eA = e0 + rA, eB = e0 + rB;
        int siA = ssh[rA], djA = dsh[rA];
        int siB = ssh[rB], djB = dsh[rB];
        const __half* niA = nodeh + (size_t)siA * 256;
        const __half* njA = nodeh + (size_t)djA * 256 + 128;
        const __half* niB = nodeh + (size_t)siB * 256;
        const __half* njB = nodeh + (size_t)djB * 256 + 128;
        float partA[2] = {0.f, 0.f};
        float partB[2] = {0.f, 0.f};
#pragma unroll
        for (int nt = 0; nt < 8; nt++) {
            int cc = wn * 64 + nt * 8 + 2 * tig;
            int hl = nt >> 2;
            float b0 = bsh[cc], b1 = bsh[cc + 1];
            float a0 = ash[cc], a1 = ash[cc + 1];
            float2 nA0 = __half22float2(*(const __half2*)(niA + cc));
            float2 nA1 = __half22float2(*(const __half2*)(njA + cc));
            float2 nB0 = __half22float2(*(const __half2*)(niB + cc));
            float2 nB1 = __half22float2(*(const __half2*)(njB + cc));
            float* d = acc[mt][nt];
            float v0 = lrelu_f(d[0] + nA0.x + nA1.x + b0);
            float v1 = lrelu_f(d[1] + nA0.y + nA1.y + b1);
            partA[hl] += v0 * a0 + v1 * a1;
            float e0v = elu_f(v0), e1v = elu_f(v1);
            if (eA < M) {
                if (EFHALF)
                    *(__half2*)(efh + (size_t)eA * 128 + cc) = __floats2half2_rn(e0v, e1v);
                else
                    *(float2*)(ef32 + (size_t)eA * 128 + cc) = make_float2(e0v, e1v);
            }
            float w0 = lrelu_f(d[2] + nB0.x + nB1.x + b0);
            float w1 = lrelu_f(d[3] + nB0.y + nB1.y + b1);
            partB[hl] += w0 * a0 + w1 * a1;
            float f0v = elu_f(w0), f1v = elu_f(w1);
            if (eB < M) {
                if (EFHALF)
                    *(__half2*)(efh + (size_t)eB * 128 + cc) = __floats2half2_rn(f0v, f1v);
                else
                    *(float2*)(ef32 + (size_t)eB * 128 + cc) = make_float2(f0v, f1v);
            }
        }
#pragma unroll
        for (int o = 1; o <= 2; o <<= 1) {
            partA[0] += __shfl_xor_sync(0xFFFFFFFFu, partA[0], o);
            partA[1] += __shfl_xor_sync(0xFFFFFFFFu, partA[1], o);
            partB[0] += __shfl_xor_sync(0xFFFFFFFFu, partB[0], o);
            partB[1] += __shfl_xor_sync(0xFFFFFFFFu, partB[1], o);
        }
        if (tig == 0) {
            int h0 = wn * 2, h1 = wn * 2 + 1;
            if (eA < M) {
                elog[(size_t)eA * 4 + h0] = partA[0];
                elog[(size_t)eA * 4 + h1] = partA[1];
            }
            if (eB < M) {
                elog[(size_t)eB * 4 + h0] = partB[0];
                elog[(size_t)eB * 4 + h1] = partB[1];
            }
        }
    }
}

// ---------------- CSR aggregation (fp16 h_src gather; fp16 or fp32 output) ----------------
__global__ __launch_bounds__(256) void k_aggr(
    const int* __restrict__ srcs, const int* __restrict__ eidx,
    const int* __restrict__ offs, const float* __restrict__ elog,
    const __half* __restrict__ hsrc,
    float* __restrict__ out32, __half* __restrict__ outh, int mode) {
    int node = (blockIdx.x * 256 + threadIdx.x) >> 5;
    int lane = threadIdx.x & 31;
    if (node >= NN) return;
    int beg = offs[node], end = offs[node + 1];

    float4 mx = make_float4(-1e30f, -1e30f, -1e30f, -1e30f);
    for (int j = beg + lane; j < end; j += 32) {
        int e = eidx[j];
        float4 l = *(const float4*)(elog + (size_t)e * 4);
        mx.x = fmaxf(mx.x, l.x); mx.y = fmaxf(mx.y, l.y);
        mx.z = fmaxf(mx.z, l.z); mx.w = fmaxf(mx.w, l.w);
    }
#pragma unroll
    for (int o = 16; o > 0; o >>= 1) {
        mx.x = fmaxf(mx.x, __shfl_xor_sync(0xFFFFFFFFu, mx.x, o));
        mx.y = fmaxf(mx.y, __shfl_xor_sync(0xFFFFFFFFu, mx.y, o));
        mx.z = fmaxf(mx.z, __shfl_xor_sync(0xFFFFFFFFu, mx.z, o));
        mx.w = fmaxf(mx.w, __shfl_xor_sync(0xFFFFFFFFu, mx.w, o));
    }
    int h = lane >> 3;
    float mh = (h == 0) ? mx.x : (h == 1) ? mx.y : (h == 2) ? mx.z : mx.w;

    float acc[8] = {0.f, 0.f, 0.f, 0.f, 0.f, 0.f, 0.f, 0.f};
    float ssum = 0.f;
    int j = beg;
    for (; j + 1 < end; j += 2) {
        int ea = eidx[j], eb = eidx[j + 1];
        int sa = srcs[ea], sbn = srcs[eb];
        float la = elog[(size_t)ea * 4 + h], lb = elog[(size_t)eb * 4 + h];
        uint4 ra = *((const uint4*)(hsrc + (size_t)sa * 256) + lane);
        uint4 rb = *((const uint4*)(hsrc + (size_t)sbn * 256) + lane);
        float wa = expf(la - mh), wb = expf(lb - mh);
        ssum += wa + wb;
        float2 t;
        t = __half22float2(*(__half2*)&ra.x); acc[0] += wa * t.x; acc[1] += wa * t.y;
        t = __half22float2(*(__half2*)&ra.y); acc[2] += wa * t.x; acc[3] += wa * t.y;
        t = __half22float2(*(__half2*)&ra.z); acc[4] += wa * t.x; acc[5] += wa * t.y;
        t = __half22float2(*(__half2*)&ra.w); acc[6] += wa * t.x; acc[7] += wa * t.y;
        t = __half22float2(*(__half2*)&rb.x); acc[0] += wb * t.x; acc[1] += wb * t.y;
        t = __half22float2(*(__half2*)&rb.y); acc[2] += wb * t.x; acc[3] += wb * t.y;
        t = __half22float2(*(__half2*)&rb.z); acc[4] += wb * t.x; acc[5] += wb * t.y;
        t = __half22float2(*(__half2*)&rb.w); acc[6] += wb * t.x; acc[7] += wb * t.y;
    }
    if (j < end) {
        int e = eidx[j];
        float w = expf(elog[(size_t)e * 4 + h] - mh);
        ssum += w;
        uint4 ra = *((const uint4*)(hsrc + (size_t)srcs[e] * 256) + lane);
        float2 t;
        t = __half22float2(*(__half2*)&ra.x); acc[0] += w * t.x; acc[1] += w * t.y;
        t = __half22float2(*(__half2*)&ra.y); acc[2] += w * t.x; acc[3] += w * t.y;
        t = __half22float2(*(__half2*)&ra.z); acc[4] += w * t.x; acc[5] += w * t.y;
        t = __half22float2(*(__half2*)&ra.w); acc[6] += w * t.x; acc[7] += w * t.y;
    }
    float inv = (end > beg) ? 1.f / ssum : 0.f;
    float o[8];
#pragma unroll
    for (int q = 0; q < 8; q++) o[q] = elu_f(acc[q] * inv);
    if (mode == 0) {
        __half2 h0 = __floats2half2_rn(o[0], o[1]);
        __half2 h1 = __floats2half2_rn(o[2], o[3]);
        __half2 h2 = __floats2half2_rn(o[4], o[5]);
        __half2 h3 = __floats2half2_rn(o[6], o[7]);
        *(uint4*)(outh + (size_t)node * 256 + lane * 8) =
            make_uint4(*(unsigned*)&h0, *(unsigned*)&h1, *(unsigned*)&h2, *(unsigned*)&h3);
    } else {
        float* op = out32 + (size_t)node * 256 + lane * 8;
        *(float4*)op = make_float4(o[0], o[1], o[2], o[3]);
        *(float4*)(op + 4) = make_float4(o[4], o[5], o[6], o[7]);
    }
}

// ---------------- host ----------------
extern "C" void kernel_launch(void* const* d_in, const int* in_sizes, int n_in,
                              void* d_out, int out_size) {
    const int*   node_types = (const int*)d_in[0];
    const int*   src        = (const int*)d_in[1];
    const int*   dst        = (const int*)d_in[2];
    const float* efeats     = (const float*)d_in[3];
    const float* embed      = (const float*)d_in[4];
    const float* W_src[2] = {(const float*)d_in[5],  (const float*)d_in[12]};
    const float* b_src[2] = {(const float*)d_in[6],  (const float*)d_in[13]};
    const float* W_ni[2]  = {(const float*)d_in[7],  (const float*)d_in[14]};
    const float* W_nj[2]  = {(const float*)d_in[8],  (const float*)d_in[15]};
    const float* W_fij[2] = {(const float*)d_in[9],  (const float*)d_in[16]};
    const float* attn[2]  = {(const float*)d_in[10], (const float*)d_in[17]};
    const float* bias[2]  = {(const float*)d_in[11], (const float*)d_in[18]};

    float *elog, *bcat;
    __half *nfh, *nodeh, *hsrc, *efa, *efh, *btn, *bte;
    int *deg, *offs, *cursor, *eidx, *bsum;
    cudaGetSymbolAddress((void**)&nfh, g_nfh);
    cudaGetSymbolAddress((void**)&nodeh, g_nodeh);
    cudaGetSymbolAddress((void**)&hsrc, g_hsrc);
    cudaGetSymbolAddress((void**)&efa, g_efa);
    cudaGetSymbolAddress((void**)&efh, g_efh);
    cudaGetSymbolAddress((void**)&elog, g_elog);
    cudaGetSymbolAddress((void**)&bcat, g_bcat);
    cudaGetSymbolAddress((void**)&btn, g_btn);
    cudaGetSymbolAddress((void**)&bte, g_bte);
    cudaGetSymbolAddress((void**)&deg, g_deg);
    cudaGetSymbolAddress((void**)&offs, g_offs);
    cudaGetSymbolAddress((void**)&cursor, g_cursor);
    cudaGetSymbolAddress((void**)&eidx, g_eidx);
    cudaGetSymbolAddress((void**)&bsum, g_bsum);

    cudaFuncSetAttribute(gemm_node_mma, cudaFuncAttributeMaxDynamicSharedMemorySize, NODE_SMEM);
    cudaFuncSetAttribute((const void*)gemm_edge_mma<1>,
                         cudaFuncAttributeMaxDynamicSharedMemorySize, EDGE_SMEM);
    cudaFuncSetAttribute((const void*)gemm_edge_mma<0>,
                         cudaFuncAttributeMaxDynamicSharedMemorySize, EDGE_SMEM);

    float* out_nf = (float*)d_out;
    float* out_ef = out_nf + (size_t)NN * 256;

    k_embed<<<(NN * 32 + 255) / 256, 256>>>(node_types, embed, nfh);
    k_half<<<(EE * 16 + 255) / 256, 256>>>(efeats, efa, EE * 16);

    // CSR by dst (edges identical across layers)
    k_zero_deg<<<NB_SCAN, 256>>>(deg);
    k_hist<<<(EE + 255) / 256, 256>>>(dst, deg);
    k_scanA<<<NB_SCAN, 256>>>(deg, bsum);
    k_scanB<<<1, 256>>>(bsum);
    k_scanC<<<NB_SCAN, 256>>>(deg, bsum, offs, cursor);
    k_scatter<<<(EE + 255) / 256, 256>>>(dst, cursor, eidx);

    for (int L = 0; L < 2; L++) {
        int in_n = L ? 256 : 128;
        int in_e = L ? 128 : 64;
        int prep_items = 512 * in_n + 128 * in_e;
        k_prep<<<(prep_items + 255) / 256, 256>>>(W_ni[L], W_nj[L], W_src[L], b_src[L],
                                                  W_fij[L], bcat, btn, bte, in_n, in_e);

        dim3 gn((NN + 127) / 128, 4);
        gemm_node_mma<<<gn, 256, NODE_SMEM>>>(nfh, btn, bcat, nodeh, hsrc, NN, in_n);

        if (L == 0) {
            gemm_edge_mma<1><<<(EE + 127) / 128, 256, EDGE_SMEM>>>(
                efa, bte, nodeh, src, dst, bias[L], attn[L],
                nullptr, efh, elog, EE, in_e);
        } else {
            gemm_edge_mma<0><<<(EE + 127) / 128, 256, EDGE_SMEM>>>(
                efh, bte, nodeh, src, dst, bias[L], attn[L],
                out_ef, nullptr, elog, EE, in_e);
        }

        k_aggr<<<(NN * 32 + 255) / 256, 256>>>(src, eidx, offs, elog, hsrc,
                                               out_nf, nfh, L);
    }
}

// round 16
// speedup vs baseline: 2.0415x; 1.0235x over previous
#include <cuda_runtime.h>
#include <cuda_fp16.h>
#include <math.h>
#include <stdint.h>

#define NN 50000
#define EE 500000
#define NB_SCAN ((NN + 255) / 256)   // 196

// ---------------- scratch ----------------
__device__ __half   g_nfh[(size_t)NN * 256];       // node features fp16 (stride 128 L0 / 256 L1)
__device__ __half   g_nodeh[(size_t)NN * 256];     // [f_ni(128) | f_nj(128)] fp16
__device__ __half   g_hsrc[(size_t)NN * 256];      // h_src fp16
__device__ __half   g_efa[(size_t)EE * 64];        // efeats fp16
__device__ __half   g_efh[(size_t)EE * 128];       // layer-0 ef intermediate fp16
__device__ float    g_elog[(size_t)EE * 4];
__device__ float    g_bcat[512];
__device__ __half   g_btn[512 * 256];              // node weights fp16, [n][k]
__device__ __half   g_bte[128 * 128];              // edge weights fp16, [n][k]
// CSR by dst
__device__ int g_deg[NN];
__device__ int g_offs[NN + 1];
__device__ int g_cursor[NN];
__device__ int g_eidx[EE];
__device__ int g_bsum[256];

// ---------------- helpers ----------------
__device__ __forceinline__ uint32_t smem_u32(const void* p) {
    uint32_t a;
    asm("{ .reg .u64 t; cvta.to.shared.u64 t, %1; cvt.u32.u64 %0, t; }" : "=r"(a) : "l"(p));
    return a;
}
__device__ __forceinline__ void ldsm_x4(unsigned& r0, unsigned& r1, unsigned& r2,
                                        unsigned& r3, uint32_t addr) {
    asm volatile("ldmatrix.sync.aligned.m8n8.x4.shared.b16 {%0,%1,%2,%3}, [%4];"
                 : "=r"(r0), "=r"(r1), "=r"(r2), "=r"(r3) : "r"(addr));
}
#define CP_ASYNC16(dst, src) \
    asm volatile("cp.async.ca.shared.global [%0], [%1], 16;" :: "r"(dst), "l"(src) : "memory")
#define CP_ASYNC16Z(dst, src, pred) \
    asm volatile("cp.async.ca.shared.global [%0], [%1], 16, %2;" \
                 :: "r"(dst), "l"(src), "r"((pred) ? 16 : 0) : "memory")
#define CP_COMMIT() asm volatile("cp.async.commit_group;" ::: "memory")
#define CP_WAIT0()  asm volatile("cp.async.wait_group 0;" ::: "memory")

__device__ __forceinline__ void mma_f16(float& d0, float& d1, float& d2, float& d3,
                                        unsigned a0, unsigned a1, unsigned a2, unsigned a3,
                                        unsigned b0, unsigned b1) {
    asm volatile(
        "mma.sync.aligned.m16n8k16.row.col.f32.f16.f16.f32 "
        "{%0,%1,%2,%3}, {%4,%5,%6,%7}, {%8,%9}, {%0,%1,%2,%3};"
        : "+f"(d0), "+f"(d1), "+f"(d2), "+f"(d3)
        : "r"(a0), "r"(a1), "r"(a2), "r"(a3), "r"(b0), "r"(b1));
}
__device__ __forceinline__ float elu_f(float v)   { return v > 0.f ? v : expm1f(v); }
__device__ __forceinline__ float lrelu_f(float v) { return v > 0.f ? v : 0.01f * v; }

// ---------------- smem layout (bytes) ----------------
#define ASM    0
#define BSM    10240
#define BUFSZ  20480
#define NODE_BIAS 40960
#define NODE_SMEM (40960 + 2048)
#define ESRC     40960
#define EDST     41472
#define EBIAS    41984
#define EATTN    42496
#define EDGE_SMEM 43008

// ---------------- small kernels ----------------
__global__ void k_embed(const int* __restrict__ node_types,
                        const float* __restrict__ embed, __half* __restrict__ nfh) {
    int i = blockIdx.x * 256 + threadIdx.x;
    if (i < NN * 32) {
        int n = i >> 5, c4 = (i & 31) * 4;
        float4 v = *(const float4*)(embed + node_types[n] * 128 + c4);
        __half2 h0 = __floats2half2_rn(v.x, v.y);
        __half2 h1 = __floats2half2_rn(v.z, v.w);
        *(uint2*)(nfh + (size_t)n * 128 + c4) =
            make_uint2(*(unsigned*)&h0, *(unsigned*)&h1);
    }
}

__global__ void k_half(const float* __restrict__ in, __half* __restrict__ out, int n4) {
    int i = blockIdx.x * 256 + threadIdx.x;
    if (i < n4) {
        float4 v = *(const float4*)(in + (size_t)i * 4);
        __half2 h0 = __floats2half2_rn(v.x, v.y);
        __half2 h1 = __floats2half2_rn(v.z, v.w);
        *(uint2*)(out + (size_t)i * 4) = make_uint2(*(unsigned*)&h0, *(unsigned*)&h1);
    }
}

__global__ void k_prep(const float* __restrict__ Wni, const float* __restrict__ Wnj,
                       const float* __restrict__ Wsrc, const float* __restrict__ bsrc,
                       const float* __restrict__ Wfij,
                       float* __restrict__ bcat,
                       __half* __restrict__ btn, __half* __restrict__ bte,
                       int in_n, int in_e) {
    int i = blockIdx.x * 256 + threadIdx.x;
    int nn = 512 * in_n;
    if (i < nn) {
        int n = i / in_n, k = i - n * in_n;
        float v;
        if (n < 128)      v = Wni[k * 128 + n];
        else if (n < 256) v = Wnj[k * 128 + (n - 128)];
        else              v = Wsrc[k * 256 + (n - 256)];
        btn[(size_t)n * in_n + k] = __float2half_rn(v);
    } else if (i < nn + 128 * in_e) {
        int j = i - nn;
        int n = j / in_e, k = j - n * in_e;
        bte[(size_t)n * in_e + k] = __float2half_rn(Wfij[k * 128 + n]);
    }
    if (i < 512) bcat[i] = (i < 256) ? 0.f : bsrc[i - 256];
}

// ---------------- CSR build ----------------
__global__ void k_zero_deg(int* __restrict__ deg) {
    int i = blockIdx.x * 256 + threadIdx.x;
    if (i < NN) deg[i] = 0;
}
__global__ void k_hist(const int* __restrict__ dst, int* __restrict__ deg) {
    int e = blockIdx.x * 256 + threadIdx.x;
    if (e < EE) atomicAdd(&deg[dst[e]], 1);
}
__global__ void k_scanA(const int* __restrict__ deg, int* __restrict__ bsum) {
    __shared__ int sh[256];
    int i = blockIdx.x * 256 + threadIdx.x;
    sh[threadIdx.x] = (i < NN) ? deg[i] : 0;
    __syncthreads();
    for (int o = 128; o > 0; o >>= 1) {
        if (threadIdx.x < o) sh[threadIdx.x] += sh[threadIdx.x + o];
        __syncthreads();
    }
    if (threadIdx.x == 0) bsum[blockIdx.x] = sh[0];
}
__global__ void k_scanB(int* __restrict__ bsum) {
    __shared__ int sh[256];
    int t = threadIdx.x;
    int v = (t < NB_SCAN) ? bsum[t] : 0;
    sh[t] = v;
    __syncthreads();
    for (int o = 1; o < 256; o <<= 1) {
        int add = (t >= o) ? sh[t - o] : 0;
        __syncthreads();
        sh[t] += add;
        __syncthreads();
    }
    if (t < NB_SCAN) bsum[t] = sh[t] - v;
}
__global__ void k_scanC(const int* __restrict__ deg, const int* __restrict__ bsum,
                        int* __restrict__ offs, int* __restrict__ cursor) {
    __shared__ int sh[256];
    int i = blockIdx.x * 256 + threadIdx.x;
    int t = threadIdx.x;
    int v = (i < NN) ? deg[i] : 0;
    sh[t] = v;
    __syncthreads();
    for (int o = 1; o < 256; o <<= 1) {
        int add = (t >= o) ? sh[t - o] : 0;
        __syncthreads();
        sh[t] += add;
        __syncthreads();
    }
    if (i < NN) {
        int ex = bsum[blockIdx.x] + sh[t] - v;
        offs[i] = ex;
        cursor[i] = ex;
    }
    if (i == 0) offs[NN] = EE;
}
__global__ void k_scatter(const int* __restrict__ dst, int* __restrict__ cursor,
                          int* __restrict__ eidx) {
    int e = blockIdx.x * 256 + threadIdx.x;
    if (e < EE) {
        int pos = atomicAdd(&cursor[dst[e]], 1);
        eidx[pos] = e;
    }
}

// ---------------- 1-pass fp16 GEMM mainloop ----------------
__device__ __forceinline__ void tile_load1(uint32_t sb, int buf,
                                           const __half* __restrict__ A, int row0, int M,
                                           const __half* __restrict__ Bt, int n0,
                                           int K, int k0) {
    int tid = threadIdx.x;
    uint32_t bo = sb + buf * BUFSZ;
#pragma unroll
    for (int i = 0; i < 2; i++) {
        int c = tid + i * 256;
        int r = c >> 2, k16 = c & 3;
        int arow = row0 + r;
        CP_ASYNC16Z(bo + ASM + r * 80 + k16 * 16,
                    A + (size_t)arow * K + k0 + k16 * 8, arow < M);
        CP_ASYNC16(bo + BSM + r * 80 + k16 * 16,
                   Bt + (size_t)(n0 + r) * K + k0 + k16 * 8);
    }
}

__device__ __forceinline__ void mma_compute(uint32_t sb, int buf, float acc[2][8][4]) {
    int tid = threadIdx.x, lane = tid & 31, wid = tid >> 5;
    int wm = wid & 3, wn = wid >> 2;
    uint32_t bo = sb + buf * BUFSZ;
    uint32_t aAddr = bo + ASM + (wm * 32 + (lane & 15)) * 80 + ((lane & 16) ? 16 : 0);
    uint32_t bAddr = bo + BSM + (wn * 64 + ((lane & 16) ? 8 : 0) + (lane & 7)) * 80 +
                     ((lane & 8) ? 16 : 0);
#pragma unroll
    for (int ks = 0; ks < 2; ks++) {
        unsigned ahr[2][4];
#pragma unroll
        for (int mt = 0; mt < 2; mt++) {
            uint32_t aa = aAddr + mt * 1280 + ks * 32;
            ldsm_x4(ahr[mt][0], ahr[mt][1], ahr[mt][2], ahr[mt][3], aa);
        }
#pragma unroll
        for (int p = 0; p < 4; p++) {
            uint32_t ba = bAddr + p * 1280 + ks * 32;
            unsigned bh[4];
            ldsm_x4(bh[0], bh[1], bh[2], bh[3], ba);
#pragma unroll
            for (int sub = 0; sub < 2; sub++) {
                int nt = p * 2 + sub;
                unsigned b0 = bh[sub * 2], b1 = bh[sub * 2 + 1];
#pragma unroll
                for (int mt = 0; mt < 2; mt++) {
                    float* d = acc[mt][nt];
                    mma_f16(d[0], d[1], d[2], d[3],
                            ahr[mt][0], ahr[mt][1], ahr[mt][2], ahr[mt][3], b0, b1);
                }
            }
        }
    }
}

__device__ __forceinline__ void mma_mainloop(
    uint32_t sb, const __half* __restrict__ A, const __half* __restrict__ Bt,
    int row0, int n0, int M, int K, float acc[2][8][4]) {
    int nst = K >> 5;
    tile_load1(sb, 0, A, row0, M, Bt, n0, K, 0);
    CP_COMMIT();
    CP_WAIT0();
    __syncthreads();
    for (int s = 0; s < nst; s++) {
        int buf = s & 1;
        bool more = (s + 1) < nst;
        if (more) {
            tile_load1(sb, buf ^ 1, A, row0, M, Bt, n0, K, (s + 1) * 32);
            CP_COMMIT();
        }
        mma_compute(sb, buf, acc);
        if (more) CP_WAIT0();
        __syncthreads();
    }
}

// ---------------- node GEMM: fp16 A, fp16 outputs ----------------
__global__ __launch_bounds__(256, 2) void gemm_node_mma(
    const __half* __restrict__ A, const __half* __restrict__ Bt,
    const float* __restrict__ bias, __half* __restrict__ nodeh,
    __half* __restrict__ hsrc, int M, int K) {
    extern __shared__ __align__(16) char smem[];
    uint32_t sb = smem_u32(smem);
    float* bsm = (float*)(smem + NODE_BIAS);
    int tid = threadIdx.x;
    ((float2*)bsm)[tid] = ((const float2*)bias)[tid];

    int row0 = blockIdx.x * 128, n0 = blockIdx.y * 128;
    float acc[2][8][4];
#pragma unroll
    for (int mt = 0; mt < 2; mt++)
#pragma unroll
        for (int nt = 0; nt < 8; nt++)
#pragma unroll
            for (int q = 0; q < 4; q++) acc[mt][nt][q] = 0.f;

    mma_mainloop(sb, A, Bt, row0, n0, M, K, acc);

    int lane = tid & 31, wid = tid >> 5;
    int g = lane >> 2, tig = lane & 3;
    int wm = wid & 3, wn = wid >> 2;
    bool to_hsrc = n0 >= 256;
    __half* outp = to_hsrc ? hsrc : nodeh;
    int cbase = to_hsrc ? 256 : 0;
#pragma unroll
    for (int mt = 0; mt < 2; mt++) {
        int r0 = row0 + wm * 32 + mt * 16 + g;
#pragma unroll
        for (int nt = 0; nt < 8; nt++) {
            int cc = n0 + wn * 64 + nt * 8 + 2 * tig;
            float b0 = bsm[cc], b1 = bsm[cc + 1];
            float* d = acc[mt][nt];
            int hc = cc - cbase;
            if (r0 < M)
                *(__half2*)(outp + (size_t)r0 * 256 + hc) =
                    __floats2half2_rn(d[0] + b0, d[1] + b1);
            if (r0 + 8 < M)
                *(__half2*)(outp + (size_t)(r0 + 8) * 256 + hc) =
                    __floats2half2_rn(d[2] + b0, d[3] + b1);
        }
    }
}

// ---------------- edge GEMM: direct-from-fragment fused epilogue ----------------
template <int EFHALF>
__global__ __launch_bounds__(256, 2) void gemm_edge_mma(
    const __half* __restrict__ A, const __half* __restrict__ Bt,
    const __half* __restrict__ nodeh,
    const int* __restrict__ src, const int* __restrict__ dst,
    const float* __restrict__ bias, const float* __restrict__ attn,
    float* __restrict__ ef32, __half* __restrict__ efh,
    float* __restrict__ elog, int M, int K) {
    extern __shared__ __align__(16) char smem[];
    uint32_t sb = smem_u32(smem);
    int*   ssh = (int*)(smem + ESRC);
    int*   dsh = (int*)(smem + EDST);
    float* bsh = (float*)(smem + EBIAS);
    float* ash = (float*)(smem + EATTN);

    int tid = threadIdx.x;
    int e0 = blockIdx.x * 128;
    if (tid < 128) {
        int e = e0 + tid;
        ssh[tid] = (e < M) ? src[e] : 0;
        dsh[tid] = (e < M) ? dst[e] : 0;
        bsh[tid] = bias[tid];
        ash[tid] = attn[tid];
    }

    float acc[2][8][4];
#pragma unroll
    for (int mt = 0; mt < 2; mt++)
#pragma unroll
        for (int nt = 0; nt < 8; nt++)
#pragma unroll
            for (int q = 0; q < 4; q++) acc[mt][nt][q] = 0.f;

    mma_mainloop(sb, A, Bt, e0, 0, M, K, acc);

    int lane = tid & 31, wid = tid >> 5;
    int g = lane >> 2, tig = lane & 3;
    int wm = wid & 3, wn = wid >> 2;

#pragma unroll
    for (int mt = 0; mt < 2; mt++) {
        int r = wm * 32 + mt * 16 + g;
        int rA = r, rB = r + 8;
        int eA = e0 + rA, eB = e0 + rB;
        int siA = ssh[rA], djA = dsh[rA];
        int siB = ssh[rB], djB = dsh[rB];
        const __half* niA = nodeh + (size_t)siA * 256;
        const __half* njA = nodeh + (size_t)djA * 256 + 128;
        const __half* niB = nodeh + (size_t)siB * 256;
        const __half* njB = nodeh + (size_t)djB * 256 + 128;
        float partA[2] = {0.f, 0.f};
        float partB[2] = {0.f, 0.f};
#pragma unroll
        for (int nt = 0; nt < 8; nt++) {
            int cc = wn * 64 + nt * 8 + 2 * tig;
            int hl = nt >> 2;
            float b0 = bsh[cc], b1 = bsh[cc + 1];
            float a0 = ash[cc], a1 = ash[cc + 1];
            float2 nA0 = __half22float2(*(const __half2*)(niA + cc));
            float2 nA1 = __half22float2(*(const __half2*)(njA + cc));
            float2 nB0 = __half22float2(*(const __half2*)(niB + cc));
            float2 nB1 = __half22float2(*(const __half2*)(njB + cc));
            float* d = acc[mt][nt];
            float v0 = lrelu_f(d[0] + nA0.x + nA1.x + b0);
            float v1 = lrelu_f(d[1] + nA0.y + nA1.y + b1);
            partA[hl] += v0 * a0 + v1 * a1;
            float e0v = elu_f(v0), e1v = elu_f(v1);
            if (eA < M) {
                if (EFHALF)
                    *(__half2*)(efh + (size_t)eA * 128 + cc) = __floats2half2_rn(e0v, e1v);
                else
                    *(float2*)(ef32 + (size_t)eA * 128 + cc) = make_float2(e0v, e1v);
            }
            float w0 = lrelu_f(d[2] + nB0.x + nB1.x + b0);
            float w1 = lrelu_f(d[3] + nB0.y + nB1.y + b1);
            partB[hl] += w0 * a0 + w1 * a1;
            float f0v = elu_f(w0), f1v = elu_f(w1);
            if (eB < M) {
                if (EFHALF)
                    *(__half2*)(efh + (size_t)eB * 128 + cc) = __floats2half2_rn(f0v, f1v);
                else
                    *(float2*)(ef32 + (size_t)eB * 128 + cc) = make_float2(f0v, f1v);
            }
        }
#pragma unroll
        for (int o = 1; o <= 2; o <<= 1) {
            partA[0] += __shfl_xor_sync(0xFFFFFFFFu, partA[0], o);
            partA[1] += __shfl_xor_sync(0xFFFFFFFFu, partA[1], o);
            partB[0] += __shfl_xor_sync(0xFFFFFFFFu, partB[0], o);
            partB[1] += __shfl_xor_sync(0xFFFFFFFFu, partB[1], o);
        }
        if (tig == 0) {
            int h0 = wn * 2, h1 = wn * 2 + 1;
            if (eA < M) {
                elog[(size_t)eA * 4 + h0] = partA[0];
                elog[(size_t)eA * 4 + h1] = partA[1];
            }
            if (eB < M) {
                elog[(size_t)eB * 4 + h0] = partB[0];
                elog[(size_t)eB * 4 + h1] = partB[1];
            }
        }
    }
}

// ---------------- CSR aggregation: single-pass softmax (no max subtraction) ----------------
// exp(e)/sum(exp(e)) == exp(e-m)/sum(exp(e-m)); logits are O(+-40) so fp32 exp is safe.
__global__ __launch_bounds__(256) void k_aggr(
    const int* __restrict__ srcs, const int* __restrict__ eidx,
    const int* __restrict__ offs, const float* __restrict__ elog,
    const __half* __restrict__ hsrc,
    float* __restrict__ out32, __half* __restrict__ outh, int mode) {
    int node = (blockIdx.x * 256 + threadIdx.x) >> 5;
    int lane = threadIdx.x & 31;
    if (node >= NN) return;
    int beg = offs[node], end = offs[node + 1];
    int h = lane >> 3;

    float acc[8] = {0.f, 0.f, 0.f, 0.f, 0.f, 0.f, 0.f, 0.f};
    float ssum = 0.f;
    int j = beg;
    for (; j + 1 < end; j += 2) {
        int ea = eidx[j], eb = eidx[j + 1];
        int sa = srcs[ea], sbn = srcs[eb];
        float la = elog[(size_t)ea * 4 + h], lb = elog[(size_t)eb * 4 + h];
        uint4 ra = *((const uint4*)(hsrc + (size_t)sa * 256) + lane);
        uint4 rb = *((const uint4*)(hsrc + (size_t)sbn * 256) + lane);
        float wa = expf(la), wb = expf(lb);
        ssum += wa + wb;
        float2 t;
        t = __half22float2(*(__half2*)&ra.x); acc[0] += wa * t.x; acc[1] += wa * t.y;
        t = __half22float2(*(__half2*)&ra.y); acc[2] += wa * t.x; acc[3] += wa * t.y;
        t = __half22float2(*(__half2*)&ra.z); acc[4] += wa * t.x; acc[5] += wa * t.y;
        t = __half22float2(*(__half2*)&ra.w); acc[6] += wa * t.x; acc[7] += wa * t.y;
        t = __half22float2(*(__half2*)&rb.x); acc[0] += wb * t.x; acc[1] += wb * t.y;
        t = __half22float2(*(__half2*)&rb.y); acc[2] += wb * t.x; acc[3] += wb * t.y;
        t = __half22float2(*(__half2*)&rb.z); acc[4] += wb * t.x; acc[5] += wb * t.y;
        t = __half22float2(*(__half2*)&rb.w); acc[6] += wb * t.x; acc[7] += wb * t.y;
    }
    if (j < end) {
        int e = eidx[j];
        float w = expf(elog[(size_t)e * 4 + h]);
        ssum += w;
        uint4 ra = *((const uint4*)(hsrc + (size_t)srcs[e] * 256) + lane);
        float2 t;
        t = __half22float2(*(__half2*)&ra.x); acc[0] += w * t.x; acc[1] += w * t.y;
        t = __half22float2(*(__half2*)&ra.y); acc[2] += w * t.x; acc[3] += w * t.y;
        t = __half22float2(*(__half2*)&ra.z); acc[4] += w * t.x; acc[5] += w * t.y;
        t = __half22float2(*(__half2*)&ra.w); acc[6] += w * t.x; acc[7] += w * t.y;
    }
    float inv = (end > beg) ? 1.f / ssum : 0.f;
    float o[8];
#pragma unroll
    for (int q = 0; q < 8; q++) o[q] = elu_f(acc[q] * inv);
    if (mode == 0) {
        __half2 h0 = __floats2half2_rn(o[0], o[1]);
        __half2 h1 = __floats2half2_rn(o[2], o[3]);
        __half2 h2 = __floats2half2_rn(o[4], o[5]);
        __half2 h3 = __floats2half2_rn(o[6], o[7]);
        *(uint4*)(outh + (size_t)node * 256 + lane * 8) =
            make_uint4(*(unsigned*)&h0, *(unsigned*)&h1, *(unsigned*)&h2, *(unsigned*)&h3);
    } else {
        float* op = out32 + (size_t)node * 256 + lane * 8;
        *(float4*)op = make_float4(o[0], o[1], o[2], o[3]);
        *(float4*)(op + 4) = make_float4(o[4], o[5], o[6], o[7]);
    }
}

// ---------------- host ----------------
extern "C" void kernel_launch(void* const* d_in, const int* in_sizes, int n_in,
                              void* d_out, int out_size) {
    const int*   node_types = (const int*)d_in[0];
    const int*   src        = (const int*)d_in[1];
    const int*   dst        = (const int*)d_in[2];
    const float* efeats     = (const float*)d_in[3];
    const float* embed      = (const float*)d_in[4];
    const float* W_src[2] = {(const float*)d_in[5],  (const float*)d_in[12]};
    const float* b_src[2] = {(const float*)d_in[6],  (const float*)d_in[13]};
    const float* W_ni[2]  = {(const float*)d_in[7],  (const float*)d_in[14]};
    const float* W_nj[2]  = {(const float*)d_in[8],  (const float*)d_in[15]};
    const float* W_fij[2] = {(const float*)d_in[9],  (const float*)d_in[16]};
    const float* attn[2]  = {(const float*)d_in[10], (const float*)d_in[17]};
    const float* bias[2]  = {(const float*)d_in[11], (const float*)d_in[18]};

    float *elog, *bcat;
    __half *nfh, *nodeh, *hsrc, *efa, *efh, *btn, *bte;
    int *deg, *offs, *cursor, *eidx, *bsum;
    cudaGetSymbolAddress((void**)&nfh, g_nfh);
    cudaGetSymbolAddress((void**)&nodeh, g_nodeh);
    cudaGetSymbolAddress((void**)&hsrc, g_hsrc);
    cudaGetSymbolAddress((void**)&efa, g_efa);
    cudaGetSymbolAddress((void**)&efh, g_efh);
    cudaGetSymbolAddress((void**)&elog, g_elog);
    cudaGetSymbolAddress((void**)&bcat, g_bcat);
    cudaGetSymbolAddress((void**)&btn, g_btn);
    cudaGetSymbolAddress((void**)&bte, g_bte);
    cudaGetSymbolAddress((void**)&deg, g_deg);
    cudaGetSymbolAddress((void**)&offs, g_offs);
    cudaGetSymbolAddress((void**)&cursor, g_cursor);
    cudaGetSymbolAddress((void**)&eidx, g_eidx);
    cudaGetSymbolAddress((void**)&bsum, g_bsum);

    cudaFuncSetAttribute(gemm_node_mma, cudaFuncAttributeMaxDynamicSharedMemorySize, NODE_SMEM);
    cudaFuncSetAttribute((const void*)gemm_edge_mma<1>,
                         cudaFuncAttributeMaxDynamicSharedMemorySize, EDGE_SMEM);
    cudaFuncSetAttribute((const void*)gemm_edge_mma<0>,
                         cudaFuncAttributeMaxDynamicSharedMemorySize, EDGE_SMEM);

    float* out_nf = (float*)d_out;
    float* out_ef = out_nf + (size_t)NN * 256;

    k_embed<<<(NN * 32 + 255) / 256, 256>>>(node_types, embed, nfh);
    k_half<<<(EE * 16 + 255) / 256, 256>>>(efeats, efa, EE * 16);

    // CSR by dst (edges identical across layers)
    k_zero_deg<<<NB_SCAN, 256>>>(deg);
    k_hist<<<(EE + 255) / 256, 256>>>(dst, deg);
    k_scanA<<<NB_SCAN, 256>>>(deg, bsum);
    k_scanB<<<1, 256>>>(bsum);
    k_scanC<<<NB_SCAN, 256>>>(deg, bsum, offs, cursor);
    k_scatter<<<(EE + 255) / 256, 256>>>(dst, cursor, eidx);

    for (int L = 0; L < 2; L++) {
        int in_n = L ? 256 : 128;
        int in_e = L ? 128 : 64;
        int prep_items = 512 * in_n + 128 * in_e;
        k_prep<<<(prep_items + 255) / 256, 256>>>(W_ni[L], W_nj[L], W_src[L], b_src[L],
                                                  W_fij[L], bcat, btn, bte, in_n, in_e);

        dim3 gn((NN + 127) / 128, 4);
        gemm_node_mma<<<gn, 256, NODE_SMEM>>>(nfh, btn, bcat, nodeh, hsrc, NN, in_n);

        if (L == 0) {
            gemm_edge_mma<1><<<(EE + 127) / 128, 256, EDGE_SMEM>>>(
                efa, bte, nodeh, src, dst, bias[L], attn[L],
                nullptr, efh, elog, EE, in_e);
        } else {
            gemm_edge_mma<0><<<(EE + 127) / 128, 256, EDGE_SMEM>>>(
                efh, bte, nodeh, src, dst, bias[L], attn[L],
                out_ef, nullptr, elog, EE, in_e);
        }

        k_aggr<<<(NN * 32 + 255) / 256, 256>>>(src, eidx, offs, elog, hsrc,
                                               out_nf, nfh, L);
    }
}

// round 17
// speedup vs baseline: 2.0992x; 1.0283x over previous
#include <cuda_runtime.h>
#include <cuda_fp16.h>
#include <math.h>
#include <stdint.h>

#define NN 50000
#define EE 500000
#define NB_SCAN ((NN + 255) / 256)   // 196

// ---------------- scratch ----------------
__device__ __half   g_nfh[(size_t)NN * 256];       // node features fp16
__device__ __half   g_nodeh[(size_t)NN * 256];     // [f_ni(128) | f_nj(128)] fp16
__device__ __half   g_hsrc[(size_t)NN * 256];      // h_src fp16
__device__ __half   g_efa[(size_t)EE * 64];        // efeats fp16, PERMUTED (CSR order)
__device__ __half   g_efh[(size_t)EE * 128];       // layer-0 ef intermediate fp16, PERMUTED
__device__ float    g_wlog[(size_t)EE * 4];        // exp(logit), PERMUTED
__device__ float    g_bcat[512];
__device__ __half   g_btn[512 * 256];
__device__ __half   g_bte[128 * 128];
// CSR by dst + permuted edge arrays
__device__ int g_deg[NN];
__device__ int g_offs[NN + 1];
__device__ int g_cursor[NN];
__device__ int g_eidx[EE];     // CSR position j -> original edge id
__device__ int g_srcp[EE];     // src in CSR order
__device__ int g_dstp[EE];     // dst in CSR order
__device__ int g_bsum[256];

// ---------------- helpers ----------------
__device__ __forceinline__ uint32_t smem_u32(const void* p) {
    uint32_t a;
    asm("{ .reg .u64 t; cvta.to.shared.u64 t, %1; cvt.u32.u64 %0, t; }" : "=r"(a) : "l"(p));
    return a;
}
__device__ __forceinline__ void ldsm_x4(unsigned& r0, unsigned& r1, unsigned& r2,
                                        unsigned& r3, uint32_t addr) {
    asm volatile("ldmatrix.sync.aligned.m8n8.x4.shared.b16 {%0,%1,%2,%3}, [%4];"
                 : "=r"(r0), "=r"(r1), "=r"(r2), "=r"(r3) : "r"(addr));
}
#define CP_ASYNC16(dst, src) \
    asm volatile("cp.async.ca.shared.global [%0], [%1], 16;" :: "r"(dst), "l"(src) : "memory")
#define CP_ASYNC16Z(dst, src, pred) \
    asm volatile("cp.async.ca.shared.global [%0], [%1], 16, %2;" \
                 :: "r"(dst), "l"(src), "r"((pred) ? 16 : 0) : "memory")
#define CP_COMMIT() asm volatile("cp.async.commit_group;" ::: "memory")
#define CP_WAIT0()  asm volatile("cp.async.wait_group 0;" ::: "memory")

__device__ __forceinline__ void mma_f16(float& d0, float& d1, float& d2, float& d3,
                                        unsigned a0, unsigned a1, unsigned a2, unsigned a3,
                                        unsigned b0, unsigned b1) {
    asm volatile(
        "mma.sync.aligned.m16n8k16.row.col.f32.f16.f16.f32 "
        "{%0,%1,%2,%3}, {%4,%5,%6,%7}, {%8,%9}, {%0,%1,%2,%3};"
        : "+f"(d0), "+f"(d1), "+f"(d2), "+f"(d3)
        : "r"(a0), "r"(a1), "r"(a2), "r"(a3), "r"(b0), "r"(b1));
}
__device__ __forceinline__ float elu_f(float v)   { return v > 0.f ? v : expm1f(v); }
__device__ __forceinline__ float lrelu_f(float v) { return v > 0.f ? v : 0.01f * v; }

// ---------------- smem layout (bytes) ----------------
#define ASM    0
#define BSM    10240
#define BUFSZ  20480
#define NODE_BIAS 40960
#define NODE_SMEM (40960 + 2048)
#define ESRC     40960
#define EDST     41472
#define EORG     41984
#define EBIAS    42496
#define EATTN    43008
#define EDGE_SMEM 43520

// ---------------- small kernels ----------------
__global__ void k_embed(const int* __restrict__ node_types,
                        const float* __restrict__ embed, __half* __restrict__ nfh) {
    int i = blockIdx.x * 256 + threadIdx.x;
    if (i < NN * 32) {
        int n = i >> 5, c4 = (i & 31) * 4;
        float4 v = *(const float4*)(embed + node_types[n] * 128 + c4);
        __half2 h0 = __floats2half2_rn(v.x, v.y);
        __half2 h1 = __floats2half2_rn(v.z, v.w);
        *(uint2*)(nfh + (size_t)n * 128 + c4) =
            make_uint2(*(unsigned*)&h0, *(unsigned*)&h1);
    }
}

// permute edge ids: src/dst into CSR order
__global__ void k_permids(const int* __restrict__ eidx,
                          const int* __restrict__ src, const int* __restrict__ dst,
                          int* __restrict__ srcp, int* __restrict__ dstp) {
    int j = blockIdx.x * 256 + threadIdx.x;
    if (j < EE) {
        int e = eidx[j];
        srcp[j] = src[e];
        dstp[j] = dst[e];
    }
}

// permute + fp16-convert efeats into CSR order
__global__ void k_permef(const int* __restrict__ eidx, const float* __restrict__ ef,
                         __half* __restrict__ efa) {
    int i = blockIdx.x * 256 + threadIdx.x;
    if (i < EE * 8) {
        int j = i >> 3, c = (i & 7) * 8;
        int e = eidx[j];
        const float* p = ef + (size_t)e * 64 + c;
        float4 v0 = *(const float4*)p;
        float4 v1 = *(const float4*)(p + 4);
        __half2 h0 = __floats2half2_rn(v0.x, v0.y);
        __half2 h1 = __floats2half2_rn(v0.z, v0.w);
        __half2 h2 = __floats2half2_rn(v1.x, v1.y);
        __half2 h3 = __floats2half2_rn(v1.z, v1.w);
        *(uint4*)(efa + (size_t)j * 64 + c) =
            make_uint4(*(unsigned*)&h0, *(unsigned*)&h1, *(unsigned*)&h2, *(unsigned*)&h3);
    }
}

__global__ void k_prep(const float* __restrict__ Wni, const float* __restrict__ Wnj,
                       const float* __restrict__ Wsrc, const float* __restrict__ bsrc,
                       const float* __restrict__ Wfij,
                       float* __restrict__ bcat,
                       __half* __restrict__ btn, __half* __restrict__ bte,
                       int in_n, int in_e) {
    int i = blockIdx.x * 256 + threadIdx.x;
    int nn = 512 * in_n;
    if (i < nn) {
        int n = i / in_n, k = i - n * in_n;
        float v;
        if (n < 128)      v = Wni[k * 128 + n];
        else if (n < 256) v = Wnj[k * 128 + (n - 128)];
        else              v = Wsrc[k * 256 + (n - 256)];
        btn[(size_t)n * in_n + k] = __float2half_rn(v);
    } else if (i < nn + 128 * in_e) {
        int j = i - nn;
        int n = j / in_e, k = j - n * in_e;
        bte[(size_t)n * in_e + k] = __float2half_rn(Wfij[k * 128 + n]);
    }
    if (i < 512) bcat[i] = (i < 256) ? 0.f : bsrc[i - 256];
}

// ---------------- CSR build ----------------
__global__ void k_zero_deg(int* __restrict__ deg) {
    int i = blockIdx.x * 256 + threadIdx.x;
    if (i < NN) deg[i] = 0;
}
__global__ void k_hist(const int* __restrict__ dst, int* __restrict__ deg) {
    int e = blockIdx.x * 256 + threadIdx.x;
    if (e < EE) atomicAdd(&deg[dst[e]], 1);
}
__global__ void k_scanA(const int* __restrict__ deg, int* __restrict__ bsum) {
    __shared__ int sh[256];
    int i = blockIdx.x * 256 + threadIdx.x;
    sh[threadIdx.x] = (i < NN) ? deg[i] : 0;
    __syncthreads();
    for (int o = 128; o > 0; o >>= 1) {
        if (threadIdx.x < o) sh[threadIdx.x] += sh[threadIdx.x + o];
        __syncthreads();
    }
    if (threadIdx.x == 0) bsum[blockIdx.x] = sh[0];
}
__global__ void k_scanB(int* __restrict__ bsum) {
    __shared__ int sh[256];
    int t = threadIdx.x;
    int v = (t < NB_SCAN) ? bsum[t] : 0;
    sh[t] = v;
    __syncthreads();
    for (int o = 1; o < 256; o <<= 1) {
        int add = (t >= o) ? sh[t - o] : 0;
        __syncthreads();
        sh[t] += add;
        __syncthreads();
    }
    if (t < NB_SCAN) bsum[t] = sh[t] - v;
}
__global__ void k_scanC(const int* __restrict__ deg, const int* __restrict__ bsum,
                        int* __restrict__ offs, int* __restrict__ cursor) {
    __shared__ int sh[256];
    int i = blockIdx.x * 256 + threadIdx.x;
    int t = threadIdx.x;
    int v = (i < NN) ? deg[i] : 0;
    sh[t] = v;
    __syncthreads();
    for (int o = 1; o < 256; o <<= 1) {
        int add = (t >= o) ? sh[t - o] : 0;
        __syncthreads();
        sh[t] += add;
        __syncthreads();
    }
    if (i < NN) {
        int ex = bsum[blockIdx.x] + sh[t] - v;
        offs[i] = ex;
        cursor[i] = ex;
    }
    if (i == 0) offs[NN] = EE;
}
__global__ void k_scatter(const int* __restrict__ dst, int* __restrict__ cursor,
                          int* __restrict__ eidx) {
    int e = blockIdx.x * 256 + threadIdx.x;
    if (e < EE) {
        int pos = atomicAdd(&cursor[dst[e]], 1);
        eidx[pos] = e;
    }
}

// ---------------- 1-pass fp16 GEMM mainloop ----------------
__device__ __forceinline__ void tile_load1(uint32_t sb, int buf,
                                           const __half* __restrict__ A, int row0, int M,
                                           const __half* __restrict__ Bt, int n0,
                                           int K, int k0) {
    int tid = threadIdx.x;
    uint32_t bo = sb + buf * BUFSZ;
#pragma unroll
    for (int i = 0; i < 2; i++) {
        int c = tid + i * 256;
        int r = c >> 2, k16 = c & 3;
        int arow = row0 + r;
        CP_ASYNC16Z(bo + ASM + r * 80 + k16 * 16,
                    A + (size_t)arow * K + k0 + k16 * 8, arow < M);
        CP_ASYNC16(bo + BSM + r * 80 + k16 * 16,
                   Bt + (size_t)(n0 + r) * K + k0 + k16 * 8);
    }
}

__device__ __forceinline__ void mma_compute(uint32_t sb, int buf, float acc[2][8][4]) {
    int tid = threadIdx.x, lane = tid & 31, wid = tid >> 5;
    int wm = wid & 3, wn = wid >> 2;
    uint32_t bo = sb + buf * BUFSZ;
    uint32_t aAddr = bo + ASM + (wm * 32 + (lane & 15)) * 80 + ((lane & 16) ? 16 : 0);
    uint32_t bAddr = bo + BSM + (wn * 64 + ((lane & 16) ? 8 : 0) + (lane & 7)) * 80 +
                     ((lane & 8) ? 16 : 0);
#pragma unroll
    for (int ks = 0; ks < 2; ks++) {
        unsigned ahr[2][4];
#pragma unroll
        for (int mt = 0; mt < 2; mt++) {
            uint32_t aa = aAddr + mt * 1280 + ks * 32;
            ldsm_x4(ahr[mt][0], ahr[mt][1], ahr[mt][2], ahr[mt][3], aa);
        }
#pragma unroll
        for (int p = 0; p < 4; p++) {
            uint32_t ba = bAddr + p * 1280 + ks * 32;
            unsigned bh[4];
            ldsm_x4(bh[0], bh[1], bh[2], bh[3], ba);
#pragma unroll
            for (int sub = 0; sub < 2; sub++) {
                int nt = p * 2 + sub;
                unsigned b0 = bh[sub * 2], b1 = bh[sub * 2 + 1];
#pragma unroll
                for (int mt = 0; mt < 2; mt++) {
                    float* d = acc[mt][nt];
                    mma_f16(d[0], d[1], d[2], d[3],
                            ahr[mt][0], ahr[mt][1], ahr[mt][2], ahr[mt][3], b0, b1);
                }
            }
        }
    }
}

__device__ __forceinline__ void mma_mainloop(
    uint32_t sb, const __half* __restrict__ A, const __half* __restrict__ Bt,
    int row0, int n0, int M, int K, float acc[2][8][4]) {
    int nst = K >> 5;
    tile_load1(sb, 0, A, row0, M, Bt, n0, K, 0);
    CP_COMMIT();
    CP_WAIT0();
    __syncthreads();
    for (int s = 0; s < nst; s++) {
        int buf = s & 1;
        bool more = (s + 1) < nst;
        if (more) {
            tile_load1(sb, buf ^ 1, A, row0, M, Bt, n0, K, (s + 1) * 32);
            CP_COMMIT();
        }
        mma_compute(sb, buf, acc);
        if (more) CP_WAIT0();
        __syncthreads();
    }
}

// ---------------- node GEMM: fp16 A, fp16 outputs ----------------
__global__ __launch_bounds__(256, 2) void gemm_node_mma(
    const __half* __restrict__ A, const __half* __restrict__ Bt,
    const float* __restrict__ bias, __half* __restrict__ nodeh,
    __half* __restrict__ hsrc, int M, int K) {
    extern __shared__ __align__(16) char smem[];
    uint32_t sb = smem_u32(smem);
    float* bsm = (float*)(smem + NODE_BIAS);
    int tid = threadIdx.x;
    ((float2*)bsm)[tid] = ((const float2*)bias)[tid];

    int row0 = blockIdx.x * 128, n0 = blockIdx.y * 128;
    float acc[2][8][4];
#pragma unroll
    for (int mt = 0; mt < 2; mt++)
#pragma unroll
        for (int nt = 0; nt < 8; nt++)
#pragma unroll
            for (int q = 0; q < 4; q++) acc[mt][nt][q] = 0.f;

    mma_mainloop(sb, A, Bt, row0, n0, M, K, acc);

    int lane = tid & 31, wid = tid >> 5;
    int g = lane >> 2, tig = lane & 3;
    int wm = wid & 3, wn = wid >> 2;
    bool to_hsrc = n0 >= 256;
    __half* outp = to_hsrc ? hsrc : nodeh;
    int cbase = to_hsrc ? 256 : 0;
#pragma unroll
    for (int mt = 0; mt < 2; mt++) {
        int r0 = row0 + wm * 32 + mt * 16 + g;
#pragma unroll
        for (int nt = 0; nt < 8; nt++) {
            int cc = n0 + wn * 64 + nt * 8 + 2 * tig;
            float b0 = bsm[cc], b1 = bsm[cc + 1];
            float* d = acc[mt][nt];
            int hc = cc - cbase;
            if (r0 < M)
                *(__half2*)(outp + (size_t)r0 * 256 + hc) =
                    __floats2half2_rn(d[0] + b0, d[1] + b1);
            if (r0 + 8 < M)
                *(__half2*)(outp + (size_t)(r0 + 8) * 256 + hc) =
                    __floats2half2_rn(d[2] + b0, d[3] + b1);
        }
    }
}

// ---------------- edge GEMM (permuted order): fused epilogue, exp'ed logits ----------------
template <int EFHALF>
__global__ __launch_bounds__(256, 2) void gemm_edge_mma(
    const __half* __restrict__ A, const __half* __restrict__ Bt,
    const __half* __restrict__ nodeh,
    const int* __restrict__ srcp, const int* __restrict__ dstp,
    const int* __restrict__ eidx,
    const float* __restrict__ bias, const float* __restrict__ attn,
    float* __restrict__ ef32, __half* __restrict__ efh,
    float* __restrict__ wlog, int M, int K) {
    extern __shared__ __align__(16) char smem[];
    uint32_t sb = smem_u32(smem);
    int*   ssh = (int*)(smem + ESRC);
    int*   dsh = (int*)(smem + EDST);
    int*   osh = (int*)(smem + EORG);
    float* bsh = (float*)(smem + EBIAS);
    float* ash = (float*)(smem + EATTN);

    int tid = threadIdx.x;
    int e0 = blockIdx.x * 128;
    if (tid < 128) {
        int e = e0 + tid;
        ssh[tid] = (e < M) ? srcp[e] : 0;
        dsh[tid] = (e < M) ? dstp[e] : 0;
        osh[tid] = (!EFHALF && e < M) ? eidx[e] : 0;
        bsh[tid] = bias[tid];
        ash[tid] = attn[tid];
    }

    float acc[2][8][4];
#pragma unroll
    for (int mt = 0; mt < 2; mt++)
#pragma unroll
        for (int nt = 0; nt < 8; nt++)
#pragma unroll
            for (int q = 0; q < 4; q++) acc[mt][nt][q] = 0.f;

    mma_mainloop(sb, A, Bt, e0, 0, M, K, acc);

    int lane = tid & 31, wid = tid >> 5;
    int g = lane >> 2, tig = lane & 3;
    int wm = wid & 3, wn = wid >> 2;

#pragma unroll
    for (int mt = 0; mt < 2; mt++) {
        int r = wm * 32 + mt * 16 + g;
        int rA = r, rB = r + 8;
        int eA = e0 + rA, eB = e0 + rB;
        int siA = ssh[rA], djA = dsh[rA];
        int siB = ssh[rB], djB = dsh[rB];
        const __half* niA = nodeh + (size_t)siA * 256;
        const __half* njA = nodeh + (size_t)djA * 256 + 128;
        const __half* niB = nodeh + (size_t)siB * 256;
        const __half* njB = nodeh + (size_t)djB * 256 + 128;
        // output row: permuted index for intermediate, original id for final
        size_t orA = EFHALF ? (size_t)eA : (size_t)osh[rA];
        size_t orB = EFHALF ? (size_t)eB : (size_t)osh[rB];
        float partA[2] = {0.f, 0.f};
        float partB[2] = {0.f, 0.f};
#pragma unroll
        for (int nt = 0; nt < 8; nt++) {
            int cc = wn * 64 + nt * 8 + 2 * tig;
            int hl = nt >> 2;
            float b0 = bsh[cc], b1 = bsh[cc + 1];
            float a0 = ash[cc], a1 = ash[cc + 1];
            float2 nA0 = __half22float2(*(const __half2*)(niA + cc));
            float2 nA1 = __half22float2(*(const __half2*)(njA + cc));
            float2 nB0 = __half22float2(*(const __half2*)(niB + cc));
            float2 nB1 = __half22float2(*(const __half2*)(njB + cc));
            float* d = acc[mt][nt];
            float v0 = lrelu_f(d[0] + nA0.x + nA1.x + b0);
            float v1 = lrelu_f(d[1] + nA0.y + nA1.y + b1);
            partA[hl] += v0 * a0 + v1 * a1;
            float e0v = elu_f(v0), e1v = elu_f(v1);
            if (eA < M) {
                if (EFHALF)
                    *(__half2*)(efh + orA * 128 + cc) = __floats2half2_rn(e0v, e1v);
                else
                    *(float2*)(ef32 + orA * 128 + cc) = make_float2(e0v, e1v);
            }
            float w0 = lrelu_f(d[2] + nB0.x + nB1.x + b0);
            float w1 = lrelu_f(d[3] + nB0.y + nB1.y + b1);
            partB[hl] += w0 * a0 + w1 * a1;
            float f0v = elu_f(w0), f1v = elu_f(w1);
            if (eB < M) {
                if (EFHALF)
                    *(__half2*)(efh + orB * 128 + cc) = __floats2half2_rn(f0v, f1v);
                else
                    *(float2*)(ef32 + orB * 128 + cc) = make_float2(f0v, f1v);
            }
        }
#pragma unroll
        for (int o = 1; o <= 2; o <<= 1) {
            partA[0] += __shfl_xor_sync(0xFFFFFFFFu, partA[0], o);
            partA[1] += __shfl_xor_sync(0xFFFFFFFFu, partA[1], o);
            partB[0] += __shfl_xor_sync(0xFFFFFFFFu, partB[0], o);
            partB[1] += __shfl_xor_sync(0xFFFFFFFFu, partB[1], o);
        }
        if (tig == 0) {
            int h0 = wn * 2, h1 = wn * 2 + 1;
            if (eA < M) {
                wlog[(size_t)eA * 4 + h0] = expf(partA[0]);
                wlog[(size_t)eA * 4 + h1] = expf(partA[1]);
            }
            if (eB < M) {
                wlog[(size_t)eB * 4 + h0] = expf(partB[0]);
                wlog[(size_t)eB * 4 + h1] = expf(partB[1]);
            }
        }
    }
}

// ---------------- CSR aggregation: contiguous, pre-exp'ed weights ----------------
__global__ __launch_bounds__(256) void k_aggr(
    const int* __restrict__ srcp, const int* __restrict__ offs,
    const float* __restrict__ wlog, const __half* __restrict__ hsrc,
    float* __restrict__ out32, __half* __restrict__ outh, int mode) {
    int node = (blockIdx.x * 256 + threadIdx.x) >> 5;
    int lane = threadIdx.x & 31;
    if (node >= NN) return;
    int beg = offs[node], end = offs[node + 1];
    int h = lane >> 3;

    float acc[8] = {0.f, 0.f, 0.f, 0.f, 0.f, 0.f, 0.f, 0.f};
    float ssum = 0.f;
    int j = beg;
    for (; j + 1 < end; j += 2) {
        int sa = srcp[j], sbn = srcp[j + 1];
        float wa = wlog[(size_t)j * 4 + h], wb = wlog[(size_t)(j + 1) * 4 + h];
        uint4 ra = *((const uint4*)(hsrc + (size_t)sa * 256) + lane);
        uint4 rb = *((const uint4*)(hsrc + (size_t)sbn * 256) + lane);
        ssum += wa + wb;
        float2 t;
        t = __half22float2(*(__half2*)&ra.x); acc[0] += wa * t.x; acc[1] += wa * t.y;
        t = __half22float2(*(__half2*)&ra.y); acc[2] += wa * t.x; acc[3] += wa * t.y;
        t = __half22float2(*(__half2*)&ra.z); acc[4] += wa * t.x; acc[5] += wa * t.y;
        t = __half22float2(*(__half2*)&ra.w); acc[6] += wa * t.x; acc[7] += wa * t.y;
        t = __half22float2(*(__half2*)&rb.x); acc[0] += wb * t.x; acc[1] += wb * t.y;
        t = __half22float2(*(__half2*)&rb.y); acc[2] += wb * t.x; acc[3] += wb * t.y;
        t = __half22float2(*(__half2*)&rb.z); acc[4] += wb * t.x; acc[5] += wb * t.y;
        t = __half22float2(*(__half2*)&rb.w); acc[6] += wb * t.x; acc[7] += wb * t.y;
    }
    if (j < end) {
        int sa = srcp[j];
        float w = wlog[(size_t)j * 4 + h];
        ssum += w;
        uint4 ra = *((const uint4*)(hsrc + (size_t)sa * 256) + lane);
        float2 t;
        t = __half22float2(*(__half2*)&ra.x); acc[0] += w * t.x; acc[1] += w * t.y;
        t = __half22float2(*(__half2*)&ra.y); acc[2] += w * t.x; acc[3] += w * t.y;
        t = __half22float2(*(__half2*)&ra.z); acc[4] += w * t.x; acc[5] += w * t.y;
        t = __half22float2(*(__half2*)&ra.w); acc[6] += w * t.x; acc[7] += w * t.y;
    }
    float inv = (end > beg) ? 1.f / ssum : 0.f;
    float o[8];
#pragma unroll
    for (int q = 0; q < 8; q++) o[q] = elu_f(acc[q] * inv);
    if (mode == 0) {
        __half2 h0 = __floats2half2_rn(o[0], o[1]);
        __half2 h1 = __floats2half2_rn(o[2], o[3]);
        __half2 h2 = __floats2half2_rn(o[4], o[5]);
        __half2 h3 = __floats2half2_rn(o[6], o[7]);
        *(uint4*)(outh + (size_t)node * 256 + lane * 8) =
            make_uint4(*(unsigned*)&h0, *(unsigned*)&h1, *(unsigned*)&h2, *(unsigned*)&h3);
    } else {
        float* op = out32 + (size_t)node * 256 + lane * 8;
        *(float4*)op = make_float4(o[0], o[1], o[2], o[3]);
        *(float4*)(op + 4) = make_float4(o[4], o[5], o[6], o[7]);
    }
}

// ---------------- host ----------------
extern "C" void kernel_launch(void* const* d_in, const int* in_sizes, int n_in,
                              void* d_out, int out_size) {
    const int*   node_types = (const int*)d_in[0];
    const int*   src        = (const int*)d_in[1];
    const int*   dst        = (const int*)d_in[2];
    const float* efeats     = (const float*)d_in[3];
    const float* embed      = (const float*)d_in[4];
    const float* W_src[2] = {(const float*)d_in[5],  (const float*)d_in[12]};
    const float* b_src[2] = {(const float*)d_in[6],  (const float*)d_in[13]};
    const float* W_ni[2]  = {(const float*)d_in[7],  (const float*)d_in[14]};
    const float* W_nj[2]  = {(const float*)d_in[8],  (const float*)d_in[15]};
    const float* W_fij[2] = {(const float*)d_in[9],  (const float*)d_in[16]};
    const float* attn[2]  = {(const float*)d_in[10], (const float*)d_in[17]};
    const float* bias[2]  = {(const float*)d_in[11], (const float*)d_in[18]};

    float *wlog, *bcat;
    __half *nfh, *nodeh, *hsrc, *efa, *efh, *btn, *bte;
    int *deg, *offs, *cursor, *eidx, *srcp, *dstp, *bsum;
    cudaGetSymbolAddress((void**)&nfh, g_nfh);
    cudaGetSymbolAddress((void**)&nodeh, g_nodeh);
    cudaGetSymbolAddress((void**)&hsrc, g_hsrc);
    cudaGetSymbolAddress((void**)&efa, g_efa);
    cudaGetSymbolAddress((void**)&efh, g_efh);
    cudaGetSymbolAddress((void**)&wlog, g_wlog);
    cudaGetSymbolAddress((void**)&bcat, g_bcat);
    cudaGetSymbolAddress((void**)&btn, g_btn);
    cudaGetSymbolAddress((void**)&bte, g_bte);
    cudaGetSymbolAddress((void**)&deg, g_deg);
    cudaGetSymbolAddress((void**)&offs, g_offs);
    cudaGetSymbolAddress((void**)&cursor, g_cursor);
    cudaGetSymbolAddress((void**)&eidx, g_eidx);
    cudaGetSymbolAddress((void**)&srcp, g_srcp);
    cudaGetSymbolAddress((void**)&dstp, g_dstp);
    cudaGetSymbolAddress((void**)&bsum, g_bsum);

    cudaFuncSetAttribute(gemm_node_mma, cudaFuncAttributeMaxDynamicSharedMemorySize, NODE_SMEM);
    cudaFuncSetAttribute((const void*)gemm_edge_mma<1>,
                         cudaFuncAttributeMaxDynamicSharedMemorySize, EDGE_SMEM);
    cudaFuncSetAttribute((const void*)gemm_edge_mma<0>,
                         cudaFuncAttributeMaxDynamicSharedMemorySize, EDGE_SMEM);

    float* out_nf = (float*)d_out;
    float* out_ef = out_nf + (size_t)NN * 256;

    k_embed<<<(NN * 32 + 255) / 256, 256>>>(node_types, embed, nfh);

    // CSR by dst + edge permutation (identical across layers)
    k_zero_deg<<<NB_SCAN, 256>>>(deg);
    k_hist<<<(EE + 255) / 256, 256>>>(dst, deg);
    k_scanA<<<NB_SCAN, 256>>>(deg, bsum);
    k_scanB<<<1, 256>>>(bsum);
    k_scanC<<<NB_SCAN, 256>>>(deg, bsum, offs, cursor);
    k_scatter<<<(EE + 255) / 256, 256>>>(dst, cursor, eidx);
    k_permids<<<(EE + 255) / 256, 256>>>(eidx, src, dst, srcp, dstp);
    k_permef<<<(EE * 8 + 255) / 256, 256>>>(eidx, efeats, efa);

    for (int L = 0; L < 2; L++) {
        int in_n = L ? 256 : 128;
        int in_e = L ? 128 : 64;
        int prep_items = 512 * in_n + 128 * in_e;
        k_prep<<<(prep_items + 255) / 256, 256>>>(W_ni[L], W_nj[L], W_src[L], b_src[L],
                                                  W_fij[L], bcat, btn, bte, in_n, in_e);

        dim3 gn((NN + 127) / 128, 4);
        gemm_node_mma<<<gn, 256, NODE_SMEM>>>(nfh, btn, bcat, nodeh, hsrc, NN, in_n);

        if (L == 0) {
            gemm_edge_mma<1><<<(EE + 127) / 128, 256, EDGE_SMEM>>>(
                efa, bte, nodeh, srcp, dstp, eidx, bias[L], attn[L],
                nullptr, efh, wlog, EE, in_e);
        } else {
            gemm_edge_mma<0><<<(EE + 127) / 128, 256, EDGE_SMEM>>>(
                efh, bte, nodeh, srcp, dstp, eidx, bias[L], attn[L],
                out_ef, nullptr, wlog, EE, in_e);
        }

        k_aggr<<<(NN * 32 + 255) / 256, 256>>>(srcp, offs, wlog, hsrc,
                                               out_nf, nfh, L);
    }
}